// round 1
// baseline (speedup 1.0000x reference)
#include <cuda_runtime.h>
#include <math.h>

#define BATCH   2
#define SEQ     2048
#define DMODEL  1024
#define NHEADS  16
#define DKH     64
#define M_TOT   (BATCH*SEQ)   // 4096

// ---------------- scratch (static device globals; no allocs) ----------------
__device__ float g_q[BATCH*NHEADS*SEQ*DKH];   // [b,h,s,dk] post-RoPE
__device__ float g_k[BATCH*NHEADS*SEQ*DKH];
__device__ float g_v[BATCH*NHEADS*SEQ*DKH];
__device__ float g_ao[M_TOT*DMODEL];          // attention out, [b*s, h*dk]

// ---------------- packed f32x2 helpers (Blackwell) ----------------
__device__ __forceinline__ unsigned long long f2pack(float lo, float hi) {
    unsigned long long r;
    asm("mov.b64 %0, {%1, %2};" : "=l"(r) : "f"(lo), "f"(hi));
    return r;
}
__device__ __forceinline__ void f2unpack(unsigned long long v, float& lo, float& hi) {
    asm("mov.b64 {%0, %1}, %2;" : "=f"(lo), "=f"(hi) : "l"(v));
}
__device__ __forceinline__ unsigned long long f2fma(unsigned long long a,
                                                    unsigned long long b,
                                                    unsigned long long c) {
    unsigned long long d;
    asm("fma.rn.f32x2 %0, %1, %2, %3;" : "=l"(d) : "l"(a), "l"(b), "l"(c));
    return d;
}

// ---------------- GEMM: C = A[M,K] * W[N,K]^T ----------------
// MODE 0: plain row-major C[m*N+n]  (final output projection)
// MODE 1: scatter to [b,h,s,dk]     (V projection)
// MODE 2: scatter to [b,h,s,dk] with fused RoPE (Q/K projections)
template<int MODE>
__global__ __launch_bounds__(256)
void gemm_kernel(const float* __restrict__ A, const float* __restrict__ W,
                 float* __restrict__ C, const int* __restrict__ pos)
{
    const int K = DMODEL, N = DMODEL;
    __shared__ float As[16][132];   // transposed tiles, +4 pad
    __shared__ float Ws[16][132];

    const int tid = threadIdx.x;
    const int tx  = tid & 15;       // n-dir
    const int ty  = tid >> 4;       // m-dir
    const int bm  = blockIdx.y, bn = blockIdx.x;

    unsigned long long acc[8][4];
    const unsigned long long z2 = f2pack(0.f, 0.f);
    #pragma unroll
    for (int i = 0; i < 8; i++)
        #pragma unroll
        for (int j = 0; j < 4; j++) acc[i][j] = z2;

    const float* Aptr = A + (size_t)(bm*128) * K;
    const float* Wptr = W + (size_t)(bn*128) * K;

    for (int k0 = 0; k0 < K; k0 += 16) {
        #pragma unroll
        for (int l = 0; l < 2; l++) {
            int item = tid + l*256;
            int r  = item >> 2;          // 0..127
            int cg = (item & 3) << 2;    // 0,4,8,12
            float4 va = *(const float4*)(Aptr + (size_t)r*K + k0 + cg);
            As[cg+0][r] = va.x; As[cg+1][r] = va.y;
            As[cg+2][r] = va.z; As[cg+3][r] = va.w;
            float4 vw = *(const float4*)(Wptr + (size_t)r*K + k0 + cg);
            Ws[cg+0][r] = vw.x; Ws[cg+1][r] = vw.y;
            Ws[cg+2][r] = vw.z; Ws[cg+3][r] = vw.w;
        }
        __syncthreads();
        #pragma unroll
        for (int kk = 0; kk < 16; kk++) {
            float4 a0 = *(const float4*)&As[kk][ty*8];
            float4 a1 = *(const float4*)&As[kk][ty*8+4];
            float4 b0 = *(const float4*)&Ws[kk][tx*8];
            float4 b1 = *(const float4*)&Ws[kk][tx*8+4];
            unsigned long long bb0 = f2pack(b0.x, b0.y);
            unsigned long long bb1 = f2pack(b0.z, b0.w);
            unsigned long long bb2 = f2pack(b1.x, b1.y);
            unsigned long long bb3 = f2pack(b1.z, b1.w);
            float av[8] = {a0.x,a0.y,a0.z,a0.w,a1.x,a1.y,a1.z,a1.w};
            #pragma unroll
            for (int i = 0; i < 8; i++) {
                unsigned long long ai = f2pack(av[i], av[i]);
                acc[i][0] = f2fma(ai, bb0, acc[i][0]);
                acc[i][1] = f2fma(ai, bb1, acc[i][1]);
                acc[i][2] = f2fma(ai, bb2, acc[i][2]);
                acc[i][3] = f2fma(ai, bb3, acc[i][3]);
            }
        }
        __syncthreads();
    }

    const int row0 = bm*128 + ty*8;
    const int col0 = bn*128 + tx*8;

    if (MODE == 0) {
        #pragma unroll
        for (int i = 0; i < 8; i++) {
            float o[8];
            f2unpack(acc[i][0], o[0], o[1]);
            f2unpack(acc[i][1], o[2], o[3]);
            f2unpack(acc[i][2], o[4], o[5]);
            f2unpack(acc[i][3], o[6], o[7]);
            float* dst = C + (size_t)(row0+i)*N + col0;
            *(float4*)dst     = make_float4(o[0],o[1],o[2],o[3]);
            *(float4*)(dst+4) = make_float4(o[4],o[5],o[6],o[7]);
        }
    } else {
        const int h   = col0 >> 6;
        const int dk0 = col0 & 63;
        float invf[4];
        if (MODE == 2) {
            #pragma unroll
            for (int j = 0; j < 4; j++) {
                int ip = (dk0 + 2*j) >> 1;                 // pair index 0..31
                // theta^(-ip/32) = exp2(-ip * log2(10000)/32)
                invf[j] = (float)exp2(-(double)ip * 0.41524101186090720);
            }
        }
        #pragma unroll
        for (int i = 0; i < 8; i++) {
            int m = row0 + i;
            int b = m >> 11;       // /SEQ
            int s = m & 2047;      // %SEQ
            float o[8];
            f2unpack(acc[i][0], o[0], o[1]);
            f2unpack(acc[i][1], o[2], o[3]);
            f2unpack(acc[i][2], o[4], o[5]);
            f2unpack(acc[i][3], o[6], o[7]);
            if (MODE == 2) {
                float p = (float)pos[s];
                #pragma unroll
                for (int j = 0; j < 4; j++) {
                    float sn, cs;
                    sincosf(p * invf[j], &sn, &cs);
                    float e  = o[2*j], od = o[2*j+1];
                    o[2*j]   = e*cs - od*sn;
                    o[2*j+1] = e*sn + od*cs;
                }
            }
            float* dst = C + ((size_t)(b*NHEADS + h)*SEQ + s)*DKH + dk0;
            *(float4*)dst     = make_float4(o[0],o[1],o[2],o[3]);
            *(float4*)(dst+4) = make_float4(o[4],o[5],o[6],o[7]);
        }
    }
}

// ---------------- Flash attention (causal), fp32 ----------------
// Block: one (bh, 64-query tile). 256 threads.
// thread: qg = tid>>4 (4 queries), kg = tid&15 (2 keys via rows kg,kg+16; 4 out dims)
__global__ __launch_bounds__(256)
void attn_kernel(const float* __restrict__ Q, const float* __restrict__ K,
                 const float* __restrict__ V, float* __restrict__ Out)
{
    __shared__ float  Qs[64][68];
    __shared__ float4 Ks4[32][16];   // XOR-swizzled chunks
    __shared__ float4 Vs4[32][16];
    __shared__ float  Ps[32][68];

    const int tid = threadIdx.x;
    const int qg  = tid >> 4;        // 0..15
    const int kg  = tid & 15;        // 0..15
    const int bh  = blockIdx.y;      // 0..31
    const int qt  = gridDim.x - 1 - blockIdx.x;   // big tiles first
    const int q0  = qt * 64;

    const float* Qb = Q + (size_t)bh*SEQ*DKH;
    const float* Kb = K + (size_t)bh*SEQ*DKH;
    const float* Vb = V + (size_t)bh*SEQ*DKH;

    #pragma unroll
    for (int l = 0; l < 4; l++) {
        int item = tid + l*256;
        int r = item >> 4;
        int c = (item & 15) << 2;
        *(float4*)&Qs[r][c] = *(const float4*)(Qb + (size_t)(q0+r)*DKH + c);
    }

    float mrow[4], lrow[4], Oacc[4][4];
    #pragma unroll
    for (int i = 0; i < 4; i++) {
        mrow[i] = -INFINITY; lrow[i] = 0.f;
        #pragma unroll
        for (int j = 0; j < 4; j++) Oacc[i][j] = 0.f;
    }

    const int nkt = (q0 >> 5) + 2;   // key tiles covering [0, q0+64)
    __syncthreads();

    for (int t = 0; t < nkt; t++) {
        const int k0 = t * 32;
        #pragma unroll
        for (int l = 0; l < 2; l++) {
            int item = tid + l*256;
            int r  = item >> 4;
            int c4 = item & 15;
            Ks4[r][c4 ^ (r & 15)] = *(const float4*)(Kb + (size_t)(k0+r)*DKH + c4*4);
            Vs4[r][c4]            = *(const float4*)(Vb + (size_t)(k0+r)*DKH + c4*4);
        }
        __syncthreads();

        // scores
        float sc[4][2] = {{0.f,0.f},{0.f,0.f},{0.f,0.f},{0.f,0.f}};
        #pragma unroll
        for (int d4 = 0; d4 < 16; d4++) {
            float4 kv0 = Ks4[kg   ][d4 ^ kg];
            float4 kv1 = Ks4[kg+16][d4 ^ kg];
            #pragma unroll
            for (int qi = 0; qi < 4; qi++) {
                float4 qv = *(const float4*)&Qs[qg*4+qi][d4*4];
                sc[qi][0] += qv.x*kv0.x + qv.y*kv0.y + qv.z*kv0.z + qv.w*kv0.w;
                sc[qi][1] += qv.x*kv1.x + qv.y*kv1.y + qv.z*kv1.z + qv.w*kv1.w;
            }
        }
        // scale + causal mask
        #pragma unroll
        for (int qi = 0; qi < 4; qi++) {
            int qglob = q0 + qg*4 + qi;
            #pragma unroll
            for (int kj = 0; kj < 2; kj++) {
                int kglob = k0 + kg + 16*kj;
                sc[qi][kj] = (kglob <= qglob) ? sc[qi][kj]*0.125f : -1e30f;
            }
        }
        // online softmax update
        float fct[4];
        #pragma unroll
        for (int qi = 0; qi < 4; qi++) {
            float v = fmaxf(sc[qi][0], sc[qi][1]);
            v = fmaxf(v, __shfl_xor_sync(0xffffffffu, v, 1));
            v = fmaxf(v, __shfl_xor_sync(0xffffffffu, v, 2));
            v = fmaxf(v, __shfl_xor_sync(0xffffffffu, v, 4));
            v = fmaxf(v, __shfl_xor_sync(0xffffffffu, v, 8));
            float mn = fmaxf(mrow[qi], v);
            fct[qi]  = __expf(mrow[qi] - mn);
            float p0 = __expf(sc[qi][0] - mn);
            float p1 = __expf(sc[qi][1] - mn);
            Ps[kg   ][qg*4+qi] = p0;
            Ps[kg+16][qg*4+qi] = p1;
            float s2 = p0 + p1;
            s2 += __shfl_xor_sync(0xffffffffu, s2, 1);
            s2 += __shfl_xor_sync(0xffffffffu, s2, 2);
            s2 += __shfl_xor_sync(0xffffffffu, s2, 4);
            s2 += __shfl_xor_sync(0xffffffffu, s2, 8);
            lrow[qi] = lrow[qi]*fct[qi] + s2;
            mrow[qi] = mn;
        }
        #pragma unroll
        for (int qi = 0; qi < 4; qi++)
            #pragma unroll
            for (int dj = 0; dj < 4; dj++) Oacc[qi][dj] *= fct[qi];
        __syncthreads();

        // PV accumulate: thread owns dims [kg*4, kg*4+4)
        #pragma unroll
        for (int kk = 0; kk < 32; kk++) {
            float4 pv = *(const float4*)&Ps[kk][qg*4];
            float4 vv = Vs4[kk][kg];
            Oacc[0][0] += pv.x*vv.x; Oacc[0][1] += pv.x*vv.y; Oacc[0][2] += pv.x*vv.z; Oacc[0][3] += pv.x*vv.w;
            Oacc[1][0] += pv.y*vv.x; Oacc[1][1] += pv.y*vv.y; Oacc[1][2] += pv.y*vv.z; Oacc[1][3] += pv.y*vv.w;
            Oacc[2][0] += pv.z*vv.x; Oacc[2][1] += pv.z*vv.y; Oacc[2][2] += pv.z*vv.z; Oacc[2][3] += pv.z*vv.w;
            Oacc[3][0] += pv.w*vv.x; Oacc[3][1] += pv.w*vv.y; Oacc[3][2] += pv.w*vv.z; Oacc[3][3] += pv.w*vv.w;
        }
        __syncthreads();
    }

    const int b = bh >> 4, h = bh & 15;
    #pragma unroll
    for (int qi = 0; qi < 4; qi++) {
        int s = q0 + qg*4 + qi;
        float inv = 1.0f / lrow[qi];
        float4 o4 = make_float4(Oacc[qi][0]*inv, Oacc[qi][1]*inv,
                                Oacc[qi][2]*inv, Oacc[qi][3]*inv);
        *(float4*)(Out + ((size_t)(b*SEQ + s))*DMODEL + h*64 + kg*4) = o4;
    }
}

// ---------------- launch ----------------
extern "C" void kernel_launch(void* const* d_in, const int* in_sizes, int n_in,
                              void* d_out, int out_size)
{
    const float* x  = (const float*)d_in[0];
    const float* wq = (const float*)d_in[1];
    const float* wk = (const float*)d_in[2];
    const float* wv = (const float*)d_in[3];
    const float* wo = (const float*)d_in[4];
    const int*  pos = (const int*)d_in[5];
    float* out = (float*)d_out;

    float *qp, *kp, *vp, *aop;
    cudaGetSymbolAddress((void**)&qp,  g_q);
    cudaGetSymbolAddress((void**)&kp,  g_k);
    cudaGetSymbolAddress((void**)&vp,  g_v);
    cudaGetSymbolAddress((void**)&aop, g_ao);

    dim3 gg(DMODEL/128, M_TOT/128);   // (8, 32)
    gemm_kernel<2><<<gg, 256>>>(x, wq, qp, pos);   // Q proj + RoPE
    gemm_kernel<2><<<gg, 256>>>(x, wk, kp, pos);   // K proj + RoPE
    gemm_kernel<1><<<gg, 256>>>(x, wv, vp, nullptr); // V proj

    dim3 ga(SEQ/64, BATCH*NHEADS);    // (32, 32)
    attn_kernel<<<ga, 256>>>(qp, kp, vp, aop);

    gemm_kernel<0><<<gg, 256>>>(aop, wo, out, nullptr); // output proj
}

// round 2
// speedup vs baseline: 1.0735x; 1.0735x over previous
#include <cuda_runtime.h>
#include <math.h>

#define BATCH   2
#define SEQ     2048
#define DMODEL  1024
#define NHEADS  16
#define DKH     64
#define M_TOT   (BATCH*SEQ)   // 4096

// ---------------- scratch (static device globals; no allocs) ----------------
__device__ float g_q[BATCH*NHEADS*SEQ*DKH];   // [b,h,s,dk] post-RoPE
__device__ float g_k[BATCH*NHEADS*SEQ*DKH];
__device__ float g_v[BATCH*NHEADS*SEQ*DKH];
__device__ float g_ao[M_TOT*DMODEL];          // attention out, [b*s, h*dk]

// ---------------- packed f32x2 helpers (Blackwell) ----------------
__device__ __forceinline__ unsigned long long f2pack(float lo, float hi) {
    unsigned long long r;
    asm("mov.b64 %0, {%1, %2};" : "=l"(r) : "f"(lo), "f"(hi));
    return r;
}
__device__ __forceinline__ void f2unpack(unsigned long long v, float& lo, float& hi) {
    asm("mov.b64 {%0, %1}, %2;" : "=f"(lo), "=f"(hi) : "l"(v));
}
__device__ __forceinline__ unsigned long long f2fma(unsigned long long a,
                                                    unsigned long long b,
                                                    unsigned long long c) {
    unsigned long long d;
    asm("fma.rn.f32x2 %0, %1, %2, %3;" : "=l"(d) : "l"(a), "l"(b), "l"(c));
    return d;
}
__device__ __forceinline__ unsigned long long f2mul(unsigned long long a,
                                                    unsigned long long b) {
    unsigned long long d;
    asm("mul.rn.f32x2 %0, %1, %2;" : "=l"(d) : "l"(a), "l"(b));
    return d;
}

// ---------------- GEMM: C = A[M,K] * W[N,K]^T ----------------
// MODE 0: plain row-major C[m*N+n]  (final output projection)
// MODE 1: scatter to [b,h,s,dk]     (V projection)
// MODE 2: scatter to [b,h,s,dk] with fused RoPE (Q/K projections)
template<int MODE>
__global__ __launch_bounds__(256)
void gemm_kernel(const float* __restrict__ A, const float* __restrict__ W,
                 float* __restrict__ C, const int* __restrict__ pos)
{
    const int K = DMODEL, N = DMODEL;
    __shared__ float As[16][132];   // transposed tiles, +4 pad
    __shared__ float Ws[16][132];

    const int tid = threadIdx.x;
    const int tx  = tid & 15;       // n-dir
    const int ty  = tid >> 4;       // m-dir
    const int bm  = blockIdx.y, bn = blockIdx.x;

    unsigned long long acc[8][4];
    const unsigned long long z2 = f2pack(0.f, 0.f);
    #pragma unroll
    for (int i = 0; i < 8; i++)
        #pragma unroll
        for (int j = 0; j < 4; j++) acc[i][j] = z2;

    const float* Aptr = A + (size_t)(bm*128) * K;
    const float* Wptr = W + (size_t)(bn*128) * K;

    // register prefetch buffers (double buffering vs global)
    float4 pa[2], pw[2];
    #pragma unroll
    for (int l = 0; l < 2; l++) {
        int item = tid + l*256;
        int r  = item >> 2;
        int cg = (item & 3) << 2;
        pa[l] = *(const float4*)(Aptr + (size_t)r*K + cg);
        pw[l] = *(const float4*)(Wptr + (size_t)r*K + cg);
    }

    for (int k0 = 0; k0 < K; k0 += 16) {
        // store prefetched tile to smem (transposed)
        #pragma unroll
        for (int l = 0; l < 2; l++) {
            int item = tid + l*256;
            int r  = item >> 2;
            int cg = (item & 3) << 2;
            As[cg+0][r] = pa[l].x; As[cg+1][r] = pa[l].y;
            As[cg+2][r] = pa[l].z; As[cg+3][r] = pa[l].w;
            Ws[cg+0][r] = pw[l].x; Ws[cg+1][r] = pw[l].y;
            Ws[cg+2][r] = pw[l].z; Ws[cg+3][r] = pw[l].w;
        }
        __syncthreads();
        // prefetch next tile while computing this one
        if (k0 + 16 < K) {
            #pragma unroll
            for (int l = 0; l < 2; l++) {
                int item = tid + l*256;
                int r  = item >> 2;
                int cg = (item & 3) << 2;
                pa[l] = *(const float4*)(Aptr + (size_t)r*K + k0 + 16 + cg);
                pw[l] = *(const float4*)(Wptr + (size_t)r*K + k0 + 16 + cg);
            }
        }
        #pragma unroll
        for (int kk = 0; kk < 16; kk++) {
            float4 a0 = *(const float4*)&As[kk][ty*8];
            float4 a1 = *(const float4*)&As[kk][ty*8+4];
            float4 b0 = *(const float4*)&Ws[kk][tx*8];
            float4 b1 = *(const float4*)&Ws[kk][tx*8+4];
            unsigned long long bb0 = f2pack(b0.x, b0.y);
            unsigned long long bb1 = f2pack(b0.z, b0.w);
            unsigned long long bb2 = f2pack(b1.x, b1.y);
            unsigned long long bb3 = f2pack(b1.z, b1.w);
            float av[8] = {a0.x,a0.y,a0.z,a0.w,a1.x,a1.y,a1.z,a1.w};
            #pragma unroll
            for (int i = 0; i < 8; i++) {
                unsigned long long ai = f2pack(av[i], av[i]);
                acc[i][0] = f2fma(ai, bb0, acc[i][0]);
                acc[i][1] = f2fma(ai, bb1, acc[i][1]);
                acc[i][2] = f2fma(ai, bb2, acc[i][2]);
                acc[i][3] = f2fma(ai, bb3, acc[i][3]);
            }
        }
        __syncthreads();
    }

    const int row0 = bm*128 + ty*8;
    const int col0 = bn*128 + tx*8;

    if (MODE == 0) {
        #pragma unroll
        for (int i = 0; i < 8; i++) {
            float o[8];
            f2unpack(acc[i][0], o[0], o[1]);
            f2unpack(acc[i][1], o[2], o[3]);
            f2unpack(acc[i][2], o[4], o[5]);
            f2unpack(acc[i][3], o[6], o[7]);
            float* dst = C + (size_t)(row0+i)*N + col0;
            *(float4*)dst     = make_float4(o[0],o[1],o[2],o[3]);
            *(float4*)(dst+4) = make_float4(o[4],o[5],o[6],o[7]);
        }
    } else {
        const int h   = col0 >> 6;
        const int dk0 = col0 & 63;
        float invf[4];
        if (MODE == 2) {
            #pragma unroll
            for (int j = 0; j < 4; j++) {
                int ip = (dk0 + 2*j) >> 1;                 // pair index 0..31
                invf[j] = (float)exp2(-(double)ip * 0.41524101186090720);
            }
        }
        #pragma unroll
        for (int i = 0; i < 8; i++) {
            int m = row0 + i;
            int b = m >> 11;
            int s = m & 2047;
            float o[8];
            f2unpack(acc[i][0], o[0], o[1]);
            f2unpack(acc[i][1], o[2], o[3]);
            f2unpack(acc[i][2], o[4], o[5]);
            f2unpack(acc[i][3], o[6], o[7]);
            if (MODE == 2) {
                float p = (float)pos[s];
                #pragma unroll
                for (int j = 0; j < 4; j++) {
                    float sn, cs;
                    sincosf(p * invf[j], &sn, &cs);
                    float e  = o[2*j], od = o[2*j+1];
                    o[2*j]   = e*cs - od*sn;
                    o[2*j+1] = e*sn + od*cs;
                }
            }
            float* dst = C + ((size_t)(b*NHEADS + h)*SEQ + s)*DKH + dk0;
            *(float4*)dst     = make_float4(o[0],o[1],o[2],o[3]);
            *(float4*)(dst+4) = make_float4(o[4],o[5],o[6],o[7]);
        }
    }
}

// ---------------- Flash attention v2 (causal), fp32 + f32x2 ----------------
// Block: (bh, 128-query tile). 256 threads.
// ty = tid>>4 (0..15): q rows ty*8..+8
// tx = tid&15: scores -> k cols tx*4..+4 ; PV -> d cols tx*4..+4
// Smem (dynamic, floats):
//   Qs[64][132]   d-major Q^T
//   Ks[64][68]    d-major K^T, granule-swizzled: phys_g = g ^ (d>>2)
//   Vs[64][68]    k-major V, granule-swizzled:   phys_g = g ^ (k&15)
//   Ps[64][132]   k-major P (k rows, q cols)
#define QS_OFF 0
#define KS_OFF 8448
#define VS_OFF 12800
#define PS_OFF 17152
#define ATTN_SMEM_FLOATS 25600
#define ATTN_SMEM_BYTES  (ATTN_SMEM_FLOATS*4)

__global__ __launch_bounds__(256, 2)
void attn_kernel(const float* __restrict__ Q, const float* __restrict__ K,
                 const float* __restrict__ V, float* __restrict__ Out)
{
    extern __shared__ float sm[];
    float* Qs = sm + QS_OFF;
    float* Ks = sm + KS_OFF;
    float* Vs = sm + VS_OFF;
    float* Ps = sm + PS_OFF;

    const int tid = threadIdx.x;
    const int ty  = tid >> 4;      // 0..15
    const int tx  = tid & 15;      // 0..15
    const int bh  = blockIdx.y;    // 0..31
    const int qt  = gridDim.x - 1 - blockIdx.x;   // big tiles first
    const int q0  = qt * 128;

    const float* Qb = Q + (size_t)bh*SEQ*DKH;
    const float* Kb = K + (size_t)bh*SEQ*DKH;
    const float* Vb = V + (size_t)bh*SEQ*DKH;

    // ---- load Q tile (128x64) transposed into Qs[d][q] ----
    {
        int row  = tid >> 1;          // 0..127
        int half = (tid & 1) * 32;    // d offset
        const float* src = Qb + (size_t)(q0+row)*DKH + half;
        #pragma unroll
        for (int c = 0; c < 8; c++) {
            float4 v = *(const float4*)(src + c*4);
            int d = half + c*4;
            Qs[(d+0)*132 + row] = v.x;
            Qs[(d+1)*132 + row] = v.y;
            Qs[(d+2)*132 + row] = v.z;
            Qs[(d+3)*132 + row] = v.w;
        }
    }

    float mrow[8], lrow[8];
    unsigned long long Oacc[8][2];
    const unsigned long long z2 = f2pack(0.f, 0.f);
    #pragma unroll
    for (int i = 0; i < 8; i++) {
        mrow[i] = -INFINITY; lrow[i] = 0.f;
        Oacc[i][0] = z2; Oacc[i][1] = z2;
    }

    const int nkt = (q0 >> 6) + 2;   // 64-key tiles covering [0, q0+128)
    __syncthreads();

    for (int t = 0; t < nkt; t++) {
        const int k0 = t * 64;
        // ---- load K (transposed+swizzled) and V (swizzled) tiles ----
        #pragma unroll
        for (int l = 0; l < 4; l++) {
            int i  = l*256 + tid;     // float4 index 0..1023
            int kr = i >> 4;          // row 0..63
            int c  = i & 15;          // d-granule
            float4 kv = *(const float4*)(Kb + (size_t)(k0+kr)*DKH + c*4);
            int d = c*4;
            int g = (kr >> 2) ^ c;
            float* kd = Ks + 4*g + (kr & 3);
            kd[(d+0)*68] = kv.x;
            kd[(d+1)*68] = kv.y;
            kd[(d+2)*68] = kv.z;
            kd[(d+3)*68] = kv.w;
            float4 vv = *(const float4*)(Vb + (size_t)(k0+kr)*DKH + c*4);
            int gv = c ^ (kr & 15);
            *(float4*)(Vs + kr*68 + gv*4) = vv;
        }
        __syncthreads();

        // ---- scores: sc[8q][4k] via f32x2 over k-pairs ----
        unsigned long long sc2[8][2];
        #pragma unroll
        for (int i = 0; i < 8; i++) { sc2[i][0] = z2; sc2[i][1] = z2; }

        #pragma unroll 16
        for (int d = 0; d < 64; d++) {
            int s = d >> 2;
            float4 kv = *(const float4*)(Ks + d*68 + ((tx ^ s) << 2));
            unsigned long long k2a = f2pack(kv.x, kv.y);
            unsigned long long k2b = f2pack(kv.z, kv.w);
            float4 qa = *(const float4*)(Qs + d*132 + ty*8);
            float4 qb = *(const float4*)(Qs + d*132 + ty*8 + 4);
            float qv[8] = {qa.x,qa.y,qa.z,qa.w,qb.x,qb.y,qb.z,qb.w};
            #pragma unroll
            for (int qi = 0; qi < 8; qi++) {
                unsigned long long qq = f2pack(qv[qi], qv[qi]);
                sc2[qi][0] = f2fma(qq, k2a, sc2[qi][0]);
                sc2[qi][1] = f2fma(qq, k2b, sc2[qi][1]);
            }
        }

        // ---- softmax (online) ----
        const bool full = (k0 + 64 <= q0);   // tile entirely causal-valid
        float p[8][4];
        float fct[8];
        #pragma unroll
        for (int qi = 0; qi < 8; qi++) {
            float s0, s1, s2, s3;
            f2unpack(sc2[qi][0], s0, s1);
            f2unpack(sc2[qi][1], s2, s3);
            s0 *= 0.125f; s1 *= 0.125f; s2 *= 0.125f; s3 *= 0.125f;
            if (!full) {
                int q = q0 + ty*8 + qi;
                int k = k0 + tx*4;
                if (k+0 > q) s0 = -1e30f;
                if (k+1 > q) s1 = -1e30f;
                if (k+2 > q) s2 = -1e30f;
                if (k+3 > q) s3 = -1e30f;
            }
            float v = fmaxf(fmaxf(s0, s1), fmaxf(s2, s3));
            v = fmaxf(v, __shfl_xor_sync(0xffffffffu, v, 1));
            v = fmaxf(v, __shfl_xor_sync(0xffffffffu, v, 2));
            v = fmaxf(v, __shfl_xor_sync(0xffffffffu, v, 4));
            v = fmaxf(v, __shfl_xor_sync(0xffffffffu, v, 8));
            float mn = fmaxf(mrow[qi], v);
            fct[qi]  = __expf(mrow[qi] - mn);
            mrow[qi] = mn;
            float p0 = __expf(s0 - mn);
            float p1 = __expf(s1 - mn);
            float p2 = __expf(s2 - mn);
            float p3 = __expf(s3 - mn);
            p[qi][0] = p0; p[qi][1] = p1; p[qi][2] = p2; p[qi][3] = p3;
            float sm2 = (p0 + p1) + (p2 + p3);
            sm2 += __shfl_xor_sync(0xffffffffu, sm2, 1);
            sm2 += __shfl_xor_sync(0xffffffffu, sm2, 2);
            sm2 += __shfl_xor_sync(0xffffffffu, sm2, 4);
            sm2 += __shfl_xor_sync(0xffffffffu, sm2, 8);
            lrow[qi] = lrow[qi]*fct[qi] + sm2;
        }
        // rescale O accumulators
        #pragma unroll
        for (int qi = 0; qi < 8; qi++) {
            unsigned long long f2 = f2pack(fct[qi], fct[qi]);
            Oacc[qi][0] = f2mul(Oacc[qi][0], f2);
            Oacc[qi][1] = f2mul(Oacc[qi][1], f2);
        }
        // store P to Ps[k][q] (float4 along q)
        #pragma unroll
        for (int kj = 0; kj < 4; kj++) {
            float* dst = Ps + (tx*4 + kj)*132 + ty*8;
            *(float4*)dst     = make_float4(p[0][kj], p[1][kj], p[2][kj], p[3][kj]);
            *(float4*)(dst+4) = make_float4(p[4][kj], p[5][kj], p[6][kj], p[7][kj]);
        }
        __syncthreads();

        // ---- PV: Oacc[8q][4d] via f32x2 over d-pairs ----
        #pragma unroll 16
        for (int k = 0; k < 64; k++) {
            float4 vv = *(const float4*)(Vs + k*68 + ((tx ^ (k & 15)) << 2));
            unsigned long long v2a = f2pack(vv.x, vv.y);
            unsigned long long v2b = f2pack(vv.z, vv.w);
            float4 pa = *(const float4*)(Ps + k*132 + ty*8);
            float4 pb = *(const float4*)(Ps + k*132 + ty*8 + 4);
            float pv[8] = {pa.x,pa.y,pa.z,pa.w,pb.x,pb.y,pb.z,pb.w};
            #pragma unroll
            for (int qi = 0; qi < 8; qi++) {
                unsigned long long pp = f2pack(pv[qi], pv[qi]);
                Oacc[qi][0] = f2fma(pp, v2a, Oacc[qi][0]);
                Oacc[qi][1] = f2fma(pp, v2b, Oacc[qi][1]);
            }
        }
        __syncthreads();   // before next tile overwrites Ks/Vs
    }

    // ---- epilogue: normalize and store ----
    const int b = bh >> 4, h = bh & 15;
    #pragma unroll
    for (int qi = 0; qi < 8; qi++) {
        int s = q0 + ty*8 + qi;
        float inv = 1.0f / lrow[qi];
        float o0, o1, o2, o3;
        f2unpack(Oacc[qi][0], o0, o1);
        f2unpack(Oacc[qi][1], o2, o3);
        float4 o4 = make_float4(o0*inv, o1*inv, o2*inv, o3*inv);
        *(float4*)(Out + ((size_t)(b*SEQ + s))*DMODEL + h*64 + tx*4) = o4;
    }
}

// ---------------- launch ----------------
extern "C" void kernel_launch(void* const* d_in, const int* in_sizes, int n_in,
                              void* d_out, int out_size)
{
    const float* x  = (const float*)d_in[0];
    const float* wq = (const float*)d_in[1];
    const float* wk = (const float*)d_in[2];
    const float* wv = (const float*)d_in[3];
    const float* wo = (const float*)d_in[4];
    const int*  pos = (const int*)d_in[5];
    float* out = (float*)d_out;

    float *qp, *kp, *vp, *aop;
    cudaGetSymbolAddress((void**)&qp,  g_q);
    cudaGetSymbolAddress((void**)&kp,  g_k);
    cudaGetSymbolAddress((void**)&vp,  g_v);
    cudaGetSymbolAddress((void**)&aop, g_ao);

    cudaFuncSetAttribute(attn_kernel,
                         cudaFuncAttributeMaxDynamicSharedMemorySize,
                         ATTN_SMEM_BYTES);

    dim3 gg(DMODEL/128, M_TOT/128);   // (8, 32)
    gemm_kernel<2><<<gg, 256>>>(x, wq, qp, pos);     // Q proj + RoPE
    gemm_kernel<2><<<gg, 256>>>(x, wk, kp, pos);     // K proj + RoPE
    gemm_kernel<1><<<gg, 256>>>(x, wv, vp, nullptr); // V proj

    dim3 ga(SEQ/128, BATCH*NHEADS);   // (16, 32)
    attn_kernel<<<ga, 256, ATTN_SMEM_BYTES>>>(qp, kp, vp, aop);

    gemm_kernel<0><<<gg, 256>>>(aop, wo, out, nullptr); // output proj
}

// round 5
// speedup vs baseline: 1.4656x; 1.3652x over previous
#include <cuda_runtime.h>
#include <cuda_bf16.h>
#include <math.h>
#include <cstdint>

#define BATCH   2
#define SEQ     2048
#define DMODEL  1024
#define NHEADS  16
#define DKH     64
#define M_TOT   (BATCH*SEQ)   // 4096

// ---------------- scratch (static device globals; no allocs) ----------------
__device__ float g_q[BATCH*NHEADS*SEQ*DKH];
__device__ float g_k[BATCH*NHEADS*SEQ*DKH];
__device__ float g_v[BATCH*NHEADS*SEQ*DKH];
__device__ float g_ao[M_TOT*DMODEL];

__device__ __align__(256) __nv_bfloat16 g_xhi[M_TOT*DMODEL];
__device__ __align__(256) __nv_bfloat16 g_xlo[M_TOT*DMODEL];
__device__ __align__(256) __nv_bfloat16 g_whi[4*DMODEL*DMODEL];
__device__ __align__(256) __nv_bfloat16 g_wlo[4*DMODEL*DMODEL];
__device__ __align__(256) __nv_bfloat16 g_aohi[M_TOT*DMODEL];
__device__ __align__(256) __nv_bfloat16 g_aolo[M_TOT*DMODEL];
__device__ float g_ropec[SEQ*32];   // [s][ip]
__device__ float g_ropes[SEQ*32];

// ---------------- PTX helpers ----------------
__device__ __forceinline__ uint32_t smem_u32(const void* p) {
    uint32_t a;
    asm("{ .reg .u64 t; cvta.to.shared.u64 t, %1; cvt.u32.u64 %0, t; }" : "=r"(a) : "l"(p));
    return a;
}
__device__ __forceinline__ void cp16(uint32_t dst, const void* src) {
    asm volatile("cp.async.cg.shared.global [%0], [%1], 16;" :: "r"(dst), "l"(src) : "memory");
}
#define CP_COMMIT() asm volatile("cp.async.commit_group;" ::: "memory")
template<int N>
__device__ __forceinline__ void cp_wait() {
    asm volatile("cp.async.wait_group %0;" :: "n"(N) : "memory");
}
__device__ __forceinline__ void ldsm_x4(uint32_t& r0, uint32_t& r1, uint32_t& r2,
                                        uint32_t& r3, uint32_t addr) {
    asm volatile("ldmatrix.sync.aligned.m8n8.x4.shared.b16 {%0,%1,%2,%3}, [%4];"
                 : "=r"(r0), "=r"(r1), "=r"(r2), "=r"(r3) : "r"(addr));
}
__device__ __forceinline__ void ldsm_x2(uint32_t& r0, uint32_t& r1, uint32_t addr) {
    asm volatile("ldmatrix.sync.aligned.m8n8.x2.shared.b16 {%0,%1}, [%2];"
                 : "=r"(r0), "=r"(r1) : "r"(addr));
}
__device__ __forceinline__ void mma_bf16(float* c, const uint32_t* a, const uint32_t* b) {
    asm volatile("mma.sync.aligned.m16n8k16.row.col.f32.bf16.bf16.f32 "
                 "{%0,%1,%2,%3}, {%4,%5,%6,%7}, {%8,%9}, {%0,%1,%2,%3};"
                 : "+f"(c[0]), "+f"(c[1]), "+f"(c[2]), "+f"(c[3])
                 : "r"(a[0]), "r"(a[1]), "r"(a[2]), "r"(a[3]), "r"(b[0]), "r"(b[1]));
}

// ---------------- small prep kernels ----------------
__global__ void conv_kernel(const float* __restrict__ src,
                            __nv_bfloat16* __restrict__ hi,
                            __nv_bfloat16* __restrict__ lo, int n4)
{
    int i = blockIdx.x * blockDim.x + threadIdx.x;
    if (i >= n4) return;
    float4 v = *(const float4*)(src + i*4);
    __nv_bfloat16 h0 = __float2bfloat16(v.x), h1 = __float2bfloat16(v.y);
    __nv_bfloat16 h2 = __float2bfloat16(v.z), h3 = __float2bfloat16(v.w);
    __nv_bfloat16 l0 = __float2bfloat16(v.x - __bfloat162float(h0));
    __nv_bfloat16 l1 = __float2bfloat16(v.y - __bfloat162float(h1));
    __nv_bfloat16 l2 = __float2bfloat16(v.z - __bfloat162float(h2));
    __nv_bfloat16 l3 = __float2bfloat16(v.w - __bfloat162float(h3));
    __nv_bfloat162 hp0(h0, h1), hp1(h2, h3), lp0(l0, l1), lp1(l2, l3);
    *(__nv_bfloat162*)(hi + i*4)     = hp0;
    *(__nv_bfloat162*)(hi + i*4 + 2) = hp1;
    *(__nv_bfloat162*)(lo + i*4)     = lp0;
    *(__nv_bfloat162*)(lo + i*4 + 2) = lp1;
}

__global__ void rope_table_kernel(const int* __restrict__ pos,
                                  float* __restrict__ cosT, float* __restrict__ sinT)
{
    int idx = blockIdx.x * blockDim.x + threadIdx.x;   // 0..SEQ*32-1
    int s  = idx >> 5;
    int ip = idx & 31;
    double invf = exp2(-(double)ip * 0.41524101186092028);  // log2(10000)/32
    float ang = (float)pos[s] * (float)invf;
    float sn, cs;
    sincosf(ang, &sn, &cs);
    cosT[idx] = cs;
    sinT[idx] = sn;
}

// ---------------- mma.sync GEMM: C = A[M,K] * W[N,K]^T, bf16x3 split ----------------
// CTA tile 128x128, 256 threads (8 warps as 4m x 2n; warp tile 32m x 64n).
// K chunks of 32, cp.async double buffered. ldmatrix-fed m16n8k16 bf16 MMAs,
// 3 passes (AhBh, AlBh, AhBl) into one fp32 accumulator.
// MODE 0: row-major C; MODE 1: scatter [b,h,s,dk]; MODE 2: scatter + fused RoPE
#define KC 32
#define NKCH (DMODEL/KC)          // 32
#define LDSTR 40                  // b16 stride (80B): conflict-free ldmatrix
#define TILE_B16 (128*LDSTR)      // 5120
#define OFF_AHI 0
#define OFF_ALO (1*TILE_B16)
#define OFF_BHI (2*TILE_B16)
#define OFF_BLO (3*TILE_B16)
#define STAGE_B16 (4*TILE_B16)    // 20480
#define GEMM_SMEM (2*STAGE_B16*2) // 81920 bytes

template<int MODE>
__global__ __launch_bounds__(256, 1)
void gemm_mma(const __nv_bfloat16* __restrict__ Ahi, const __nv_bfloat16* __restrict__ Alo,
              const __nv_bfloat16* __restrict__ Bhi, const __nv_bfloat16* __restrict__ Blo,
              float* __restrict__ C,
              const float* __restrict__ ropec, const float* __restrict__ ropes)
{
    extern __shared__ __nv_bfloat16 smb[];
    const uint32_t sbase = smem_u32(smb);
    const int tid  = threadIdx.x;
    const int wid  = tid >> 5;
    const int lane = tid & 31;
    const int bm = blockIdx.y, bn = blockIdx.x;
    const int wm = wid & 3;       // 0..3  (32 rows each)
    const int wn = wid >> 2;      // 0..1  (64 cols each)

    float acc[2][8][4];
    #pragma unroll
    for (int mt = 0; mt < 2; mt++)
        #pragma unroll
        for (int nt = 0; nt < 8; nt++)
            #pragma unroll
            for (int j = 0; j < 4; j++) acc[mt][nt][j] = 0.f;

    const __nv_bfloat16* Ah = Ahi + (size_t)(bm*128)*DMODEL;
    const __nv_bfloat16* Al = Alo + (size_t)(bm*128)*DMODEL;
    const __nv_bfloat16* Bh = Bhi + (size_t)(bn*128)*DMODEL;
    const __nv_bfloat16* Bl = Blo + (size_t)(bn*128)*DMODEL;

    auto load_stage = [&](int st, int kc) {
        const int koff = kc*KC;
        const uint32_t sb = sbase + st*(STAGE_B16*2);
        #pragma unroll
        for (int i = 0; i < 2; i++) {
            int item = tid + i*256;      // 0..511
            int r = item >> 2;           // row 0..127
            int c = item & 3;            // 16B unit (8 bf16)
            uint32_t d = sb + (uint32_t)(r*LDSTR + c*8)*2;
            const __nv_bfloat16* sa = Ah + (size_t)r*DMODEL + koff + c*8;
            cp16(d + OFF_AHI*2, sa);
            cp16(d + OFF_ALO*2, Al + (sa - Ah));
            const __nv_bfloat16* sbp = Bh + (size_t)r*DMODEL + koff + c*8;
            cp16(d + OFF_BHI*2, sbp);
            cp16(d + OFF_BLO*2, Bl + (sbp - Bh));
        }
    };

    load_stage(0, 0); CP_COMMIT();
    load_stage(1, 1); CP_COMMIT();

    // ldmatrix lane addressing (b16 offsets within a tile)
    const int a_row = wm*32 + (lane & 15);
    const int a_co  = (lane >> 4) * 8;
    const int b_row = wn*64 + (lane & 7);
    const int b_co  = ((lane >> 3) & 1) * 8;

    for (int kc = 0; kc < NKCH; kc++) {
        if (kc + 1 < NKCH) cp_wait<1>(); else cp_wait<0>();
        __syncthreads();
        const uint32_t sb = sbase + (kc & 1)*(STAGE_B16*2);

        #pragma unroll
        for (int ks = 0; ks < 2; ks++) {
            const int kof = ks*16;
            uint32_t ah[2][4], al[2][4];
            #pragma unroll
            for (int mt = 0; mt < 2; mt++) {
                uint32_t aaddr = sb + (uint32_t)((a_row + mt*16)*LDSTR + kof + a_co)*2;
                ldsm_x4(ah[mt][0], ah[mt][1], ah[mt][2], ah[mt][3], aaddr + OFF_AHI*2);
                ldsm_x4(al[mt][0], al[mt][1], al[mt][2], al[mt][3], aaddr + OFF_ALO*2);
            }
            #pragma unroll
            for (int nt = 0; nt < 8; nt++) {
                uint32_t baddr = sb + (uint32_t)((b_row + nt*8)*LDSTR + kof + b_co)*2;
                uint32_t bh[2], bl[2];
                ldsm_x2(bh[0], bh[1], baddr + OFF_BHI*2);
                ldsm_x2(bl[0], bl[1], baddr + OFF_BLO*2);
                #pragma unroll
                for (int mt = 0; mt < 2; mt++) {
                    mma_bf16(acc[mt][nt], ah[mt], bh);
                    mma_bf16(acc[mt][nt], al[mt], bh);
                    mma_bf16(acc[mt][nt], ah[mt], bl);
                }
            }
        }
        __syncthreads();
        if (kc + 2 < NKCH) { load_stage(kc & 1, kc + 2); CP_COMMIT(); }
    }

    // ---- epilogue: RoPE in registers (c0,c1 is an even/odd pair), scatter ----
    const int row_base = bm*128 + wm*32;
    const int col_base = bn*128 + wn*64;
    #pragma unroll
    for (int mt = 0; mt < 2; mt++) {
        #pragma unroll
        for (int rg = 0; rg < 2; rg++) {
            int row = row_base + mt*16 + rg*8 + (lane >> 2);
            int s = row & (SEQ-1);
            int b = row >> 11;
            #pragma unroll
            for (int nt = 0; nt < 8; nt++) {
                int col = col_base + nt*8 + 2*(lane & 3);
                float e = acc[mt][nt][rg*2];
                float o = acc[mt][nt][rg*2+1];
                if (MODE == 2) {
                    int ip = (col & 63) >> 1;
                    float cs = ropec[s*32 + ip];
                    float sn = ropes[s*32 + ip];
                    float ne = e*cs - o*sn;
                    float no = e*sn + o*cs;
                    e = ne; o = no;
                }
                if (MODE == 0) {
                    *(float2*)(C + (size_t)row*DMODEL + col) = make_float2(e, o);
                } else {
                    int h = col >> 6, dk = col & 63;
                    *(float2*)(C + ((size_t)(b*NHEADS + h)*SEQ + s)*DKH + dk) = make_float2(e, o);
                }
            }
        }
    }
}

// ---------------- packed f32x2 helpers (attention) ----------------
__device__ __forceinline__ unsigned long long f2pack(float lo, float hi) {
    unsigned long long r;
    asm("mov.b64 %0, {%1, %2};" : "=l"(r) : "f"(lo), "f"(hi));
    return r;
}
__device__ __forceinline__ void f2unpack(unsigned long long v, float& lo, float& hi) {
    asm("mov.b64 {%0, %1}, %2;" : "=f"(lo), "=f"(hi) : "l"(v));
}
__device__ __forceinline__ unsigned long long f2fma(unsigned long long a,
                                                    unsigned long long b,
                                                    unsigned long long c) {
    unsigned long long d;
    asm("fma.rn.f32x2 %0, %1, %2, %3;" : "=l"(d) : "l"(a), "l"(b), "l"(c));
    return d;
}
__device__ __forceinline__ unsigned long long f2mul(unsigned long long a,
                                                    unsigned long long b) {
    unsigned long long d;
    asm("mul.rn.f32x2 %0, %1, %2;" : "=l"(d) : "l"(a), "l"(b));
    return d;
}

// ---------------- Flash attention (causal), fp32 + f32x2 (unchanged) ----------------
#define QS_OFF 0
#define KS_OFF 8448
#define VS_OFF 12800
#define PS_OFF 17152
#define ATTN_SMEM_FLOATS 25600
#define ATTN_SMEM_BYTES  (ATTN_SMEM_FLOATS*4)

__global__ __launch_bounds__(256, 2)
void attn_kernel(const float* __restrict__ Q, const float* __restrict__ K,
                 const float* __restrict__ V, float* __restrict__ Out)
{
    extern __shared__ float smf[];
    float* Qs = smf + QS_OFF;
    float* Ks = smf + KS_OFF;
    float* Vs = smf + VS_OFF;
    float* Ps = smf + PS_OFF;

    const int tid = threadIdx.x;
    const int ty  = tid >> 4;
    const int tx  = tid & 15;
    const int bh  = blockIdx.y;
    const int qt  = gridDim.x - 1 - blockIdx.x;
    const int q0  = qt * 128;

    const float* Qb = Q + (size_t)bh*SEQ*DKH;
    const float* Kb = K + (size_t)bh*SEQ*DKH;
    const float* Vb = V + (size_t)bh*SEQ*DKH;

    {
        int row  = tid >> 1;
        int half = (tid & 1) * 32;
        const float* src = Qb + (size_t)(q0+row)*DKH + half;
        #pragma unroll
        for (int c = 0; c < 8; c++) {
            float4 v = *(const float4*)(src + c*4);
            int d = half + c*4;
            Qs[(d+0)*132 + row] = v.x;
            Qs[(d+1)*132 + row] = v.y;
            Qs[(d+2)*132 + row] = v.z;
            Qs[(d+3)*132 + row] = v.w;
        }
    }

    float mrow[8], lrow[8];
    unsigned long long Oacc[8][2];
    const unsigned long long z2 = f2pack(0.f, 0.f);
    #pragma unroll
    for (int i = 0; i < 8; i++) {
        mrow[i] = -INFINITY; lrow[i] = 0.f;
        Oacc[i][0] = z2; Oacc[i][1] = z2;
    }

    const int nkt = (q0 >> 6) + 2;
    __syncthreads();

    for (int t = 0; t < nkt; t++) {
        const int k0 = t * 64;
        #pragma unroll
        for (int l = 0; l < 4; l++) {
            int i  = l*256 + tid;
            int kr = i >> 4;
            int c  = i & 15;
            float4 kv = *(const float4*)(Kb + (size_t)(k0+kr)*DKH + c*4);
            int d = c*4;
            int g = (kr >> 2) ^ c;
            float* kd = Ks + 4*g + (kr & 3);
            kd[(d+0)*68] = kv.x;
            kd[(d+1)*68] = kv.y;
            kd[(d+2)*68] = kv.z;
            kd[(d+3)*68] = kv.w;
            float4 vv = *(const float4*)(Vb + (size_t)(k0+kr)*DKH + c*4);
            int gv = c ^ (kr & 15);
            *(float4*)(Vs + kr*68 + gv*4) = vv;
        }
        __syncthreads();

        unsigned long long sc2[8][2];
        #pragma unroll
        for (int i = 0; i < 8; i++) { sc2[i][0] = z2; sc2[i][1] = z2; }

        #pragma unroll 16
        for (int d = 0; d < 64; d++) {
            int sdx = d >> 2;
            float4 kv = *(const float4*)(Ks + d*68 + ((tx ^ sdx) << 2));
            unsigned long long k2a = f2pack(kv.x, kv.y);
            unsigned long long k2b = f2pack(kv.z, kv.w);
            float4 qa = *(const float4*)(Qs + d*132 + ty*8);
            float4 qb = *(const float4*)(Qs + d*132 + ty*8 + 4);
            float qv[8] = {qa.x,qa.y,qa.z,qa.w,qb.x,qb.y,qb.z,qb.w};
            #pragma unroll
            for (int qi = 0; qi < 8; qi++) {
                unsigned long long qq = f2pack(qv[qi], qv[qi]);
                sc2[qi][0] = f2fma(qq, k2a, sc2[qi][0]);
                sc2[qi][1] = f2fma(qq, k2b, sc2[qi][1]);
            }
        }

        const bool full = (k0 + 64 <= q0);
        float p[8][4];
        float fct[8];
        #pragma unroll
        for (int qi = 0; qi < 8; qi++) {
            float s0, s1, s2, s3;
            f2unpack(sc2[qi][0], s0, s1);
            f2unpack(sc2[qi][1], s2, s3);
            s0 *= 0.125f; s1 *= 0.125f; s2 *= 0.125f; s3 *= 0.125f;
            if (!full) {
                int q = q0 + ty*8 + qi;
                int k = k0 + tx*4;
                if (k+0 > q) s0 = -1e30f;
                if (k+1 > q) s1 = -1e30f;
                if (k+2 > q) s2 = -1e30f;
                if (k+3 > q) s3 = -1e30f;
            }
            float v = fmaxf(fmaxf(s0, s1), fmaxf(s2, s3));
            v = fmaxf(v, __shfl_xor_sync(0xffffffffu, v, 1));
            v = fmaxf(v, __shfl_xor_sync(0xffffffffu, v, 2));
            v = fmaxf(v, __shfl_xor_sync(0xffffffffu, v, 4));
            v = fmaxf(v, __shfl_xor_sync(0xffffffffu, v, 8));
            float mn = fmaxf(mrow[qi], v);
            fct[qi]  = __expf(mrow[qi] - mn);
            mrow[qi] = mn;
            float p0 = __expf(s0 - mn);
            float p1 = __expf(s1 - mn);
            float p2 = __expf(s2 - mn);
            float p3 = __expf(s3 - mn);
            p[qi][0] = p0; p[qi][1] = p1; p[qi][2] = p2; p[qi][3] = p3;
            float sm2 = (p0 + p1) + (p2 + p3);
            sm2 += __shfl_xor_sync(0xffffffffu, sm2, 1);
            sm2 += __shfl_xor_sync(0xffffffffu, sm2, 2);
            sm2 += __shfl_xor_sync(0xffffffffu, sm2, 4);
            sm2 += __shfl_xor_sync(0xffffffffu, sm2, 8);
            lrow[qi] = lrow[qi]*fct[qi] + sm2;
        }
        #pragma unroll
        for (int qi = 0; qi < 8; qi++) {
            unsigned long long f2 = f2pack(fct[qi], fct[qi]);
            Oacc[qi][0] = f2mul(Oacc[qi][0], f2);
            Oacc[qi][1] = f2mul(Oacc[qi][1], f2);
        }
        #pragma unroll
        for (int kj = 0; kj < 4; kj++) {
            float* dst = Ps + (tx*4 + kj)*132 + ty*8;
            *(float4*)dst     = make_float4(p[0][kj], p[1][kj], p[2][kj], p[3][kj]);
            *(float4*)(dst+4) = make_float4(p[4][kj], p[5][kj], p[6][kj], p[7][kj]);
        }
        __syncthreads();

        #pragma unroll 16
        for (int k = 0; k < 64; k++) {
            float4 vv = *(const float4*)(Vs + k*68 + ((tx ^ (k & 15)) << 2));
            unsigned long long v2a = f2pack(vv.x, vv.y);
            unsigned long long v2b = f2pack(vv.z, vv.w);
            float4 pa = *(const float4*)(Ps + k*132 + ty*8);
            float4 pb = *(const float4*)(Ps + k*132 + ty*8 + 4);
            float pv[8] = {pa.x,pa.y,pa.z,pa.w,pb.x,pb.y,pb.z,pb.w};
            #pragma unroll
            for (int qi = 0; qi < 8; qi++) {
                unsigned long long pp = f2pack(pv[qi], pv[qi]);
                Oacc[qi][0] = f2fma(pp, v2a, Oacc[qi][0]);
                Oacc[qi][1] = f2fma(pp, v2b, Oacc[qi][1]);
            }
        }
        __syncthreads();
    }

    const int b = bh >> 4, h = bh & 15;
    #pragma unroll
    for (int qi = 0; qi < 8; qi++) {
        int s = q0 + ty*8 + qi;
        float inv = 1.0f / lrow[qi];
        float o0, o1, o2, o3;
        f2unpack(Oacc[qi][0], o0, o1);
        f2unpack(Oacc[qi][1], o2, o3);
        float4 o4 = make_float4(o0*inv, o1*inv, o2*inv, o3*inv);
        *(float4*)(Out + ((size_t)(b*SEQ + s))*DMODEL + h*64 + tx*4) = o4;
    }
}

// ---------------- launch ----------------
extern "C" void kernel_launch(void* const* d_in, const int* in_sizes, int n_in,
                              void* d_out, int out_size)
{
    const float* x  = (const float*)d_in[0];
    const float* wq = (const float*)d_in[1];
    const float* wk = (const float*)d_in[2];
    const float* wv = (const float*)d_in[3];
    const float* wo = (const float*)d_in[4];
    const int*  pos = (const int*)d_in[5];
    float* out = (float*)d_out;

    float *qp, *kp, *vp, *aop, *rc, *rs;
    __nv_bfloat16 *xhi, *xlo, *whi, *wlo, *aohi, *aolo;
    cudaGetSymbolAddress((void**)&qp,   g_q);
    cudaGetSymbolAddress((void**)&kp,   g_k);
    cudaGetSymbolAddress((void**)&vp,   g_v);
    cudaGetSymbolAddress((void**)&aop,  g_ao);
    cudaGetSymbolAddress((void**)&rc,   g_ropec);
    cudaGetSymbolAddress((void**)&rs,   g_ropes);
    cudaGetSymbolAddress((void**)&xhi,  g_xhi);
    cudaGetSymbolAddress((void**)&xlo,  g_xlo);
    cudaGetSymbolAddress((void**)&whi,  g_whi);
    cudaGetSymbolAddress((void**)&wlo,  g_wlo);
    cudaGetSymbolAddress((void**)&aohi, g_aohi);
    cudaGetSymbolAddress((void**)&aolo, g_aolo);

    static bool attr_done = false;
    if (!attr_done) {
        cudaFuncSetAttribute(gemm_mma<0>, cudaFuncAttributeMaxDynamicSharedMemorySize, GEMM_SMEM);
        cudaFuncSetAttribute(gemm_mma<1>, cudaFuncAttributeMaxDynamicSharedMemorySize, GEMM_SMEM);
        cudaFuncSetAttribute(gemm_mma<2>, cudaFuncAttributeMaxDynamicSharedMemorySize, GEMM_SMEM);
        cudaFuncSetAttribute(attn_kernel, cudaFuncAttributeMaxDynamicSharedMemorySize, ATTN_SMEM_BYTES);
        attr_done = true;
    }

    const int WN = DMODEL*DMODEL;   // 1M

    rope_table_kernel<<<(SEQ*32)/256, 256>>>(pos, rc, rs);
    conv_kernel<<<(M_TOT*DMODEL/4 + 255)/256, 256>>>(x,  xhi, xlo, M_TOT*DMODEL/4);
    conv_kernel<<<(WN/4 + 255)/256, 256>>>(wq, whi + 0*(size_t)WN, wlo + 0*(size_t)WN, WN/4);
    conv_kernel<<<(WN/4 + 255)/256, 256>>>(wk, whi + 1*(size_t)WN, wlo + 1*(size_t)WN, WN/4);
    conv_kernel<<<(WN/4 + 255)/256, 256>>>(wv, whi + 2*(size_t)WN, wlo + 2*(size_t)WN, WN/4);
    conv_kernel<<<(WN/4 + 255)/256, 256>>>(wo, whi + 3*(size_t)WN, wlo + 3*(size_t)WN, WN/4);

    dim3 gg(DMODEL/128, M_TOT/128);   // (8, 32)
    gemm_mma<2><<<gg, 256, GEMM_SMEM>>>(xhi, xlo, whi + 0*(size_t)WN, wlo + 0*(size_t)WN, qp, rc, rs);
    gemm_mma<2><<<gg, 256, GEMM_SMEM>>>(xhi, xlo, whi + 1*(size_t)WN, wlo + 1*(size_t)WN, kp, rc, rs);
    gemm_mma<1><<<gg, 256, GEMM_SMEM>>>(xhi, xlo, whi + 2*(size_t)WN, wlo + 2*(size_t)WN, vp, rc, rs);

    dim3 ga(SEQ/128, BATCH*NHEADS);   // (16, 32)
    attn_kernel<<<ga, 256, ATTN_SMEM_BYTES>>>(qp, kp, vp, aop);

    conv_kernel<<<(M_TOT*DMODEL/4 + 255)/256, 256>>>(aop, aohi, aolo, M_TOT*DMODEL/4);
    gemm_mma<0><<<gg, 256, GEMM_SMEM>>>(aohi, aolo, whi + 3*(size_t)WN, wlo + 3*(size_t)WN, out, rc, rs);
}

// round 6
// speedup vs baseline: 2.3783x; 1.6228x over previous
#include <cuda_runtime.h>
#include <cuda_bf16.h>
#include <math.h>
#include <cstdint>

#define BATCH   2
#define SEQ     2048
#define DMODEL  1024
#define NHEADS  16
#define DKH     64
#define M_TOT   (BATCH*SEQ)   // 4096
#define QKV_ELEMS (BATCH*NHEADS*SEQ*DKH)

// ---------------- scratch (static device globals; no allocs) ----------------
__device__ __align__(256) __nv_bfloat16 g_xhi[M_TOT*DMODEL];
__device__ __align__(256) __nv_bfloat16 g_xlo[M_TOT*DMODEL];
__device__ __align__(256) __nv_bfloat16 g_whi[4*DMODEL*DMODEL];
__device__ __align__(256) __nv_bfloat16 g_wlo[4*DMODEL*DMODEL];
__device__ __align__(256) __nv_bfloat16 g_qhi[QKV_ELEMS];
__device__ __align__(256) __nv_bfloat16 g_qlo[QKV_ELEMS];
__device__ __align__(256) __nv_bfloat16 g_khi[QKV_ELEMS];
__device__ __align__(256) __nv_bfloat16 g_klo[QKV_ELEMS];
__device__ __align__(256) __nv_bfloat16 g_vhi[QKV_ELEMS];
__device__ __align__(256) __nv_bfloat16 g_vlo[QKV_ELEMS];
__device__ __align__(256) __nv_bfloat16 g_aohi[M_TOT*DMODEL];
__device__ __align__(256) __nv_bfloat16 g_aolo[M_TOT*DMODEL];
__device__ float g_ropec[SEQ*32];   // [s][ip]
__device__ float g_ropes[SEQ*32];

// ---------------- PTX helpers ----------------
__device__ __forceinline__ uint32_t smem_u32(const void* p) {
    uint32_t a;
    asm("{ .reg .u64 t; cvta.to.shared.u64 t, %1; cvt.u32.u64 %0, t; }" : "=r"(a) : "l"(p));
    return a;
}
__device__ __forceinline__ void cp16(uint32_t dst, const void* src) {
    asm volatile("cp.async.cg.shared.global [%0], [%1], 16;" :: "r"(dst), "l"(src) : "memory");
}
#define CP_COMMIT() asm volatile("cp.async.commit_group;" ::: "memory")
template<int N>
__device__ __forceinline__ void cp_wait() {
    asm volatile("cp.async.wait_group %0;" :: "n"(N) : "memory");
}
__device__ __forceinline__ void ldsm_x4(uint32_t& r0, uint32_t& r1, uint32_t& r2,
                                        uint32_t& r3, uint32_t addr) {
    asm volatile("ldmatrix.sync.aligned.m8n8.x4.shared.b16 {%0,%1,%2,%3}, [%4];"
                 : "=r"(r0), "=r"(r1), "=r"(r2), "=r"(r3) : "r"(addr));
}
__device__ __forceinline__ void ldsm_x2(uint32_t& r0, uint32_t& r1, uint32_t addr) {
    asm volatile("ldmatrix.sync.aligned.m8n8.x2.shared.b16 {%0,%1}, [%2];"
                 : "=r"(r0), "=r"(r1) : "r"(addr));
}
__device__ __forceinline__ void mma_bf16(float* c, const uint32_t* a, const uint32_t* b) {
    asm volatile("mma.sync.aligned.m16n8k16.row.col.f32.bf16.bf16.f32 "
                 "{%0,%1,%2,%3}, {%4,%5,%6,%7}, {%8,%9}, {%0,%1,%2,%3};"
                 : "+f"(c[0]), "+f"(c[1]), "+f"(c[2]), "+f"(c[3])
                 : "r"(a[0]), "r"(a[1]), "r"(a[2]), "r"(a[3]), "r"(b[0]), "r"(b[1]));
}
// split pair of floats into packed bf16x2 hi + lo residual
__device__ __forceinline__ void split2(float a, float b, uint32_t& hi, uint32_t& lo) {
    __nv_bfloat162 h = __floats2bfloat162_rn(a, b);
    float ha = __low2float(h), hb = __high2float(h);
    __nv_bfloat162 l = __floats2bfloat162_rn(a - ha, b - hb);
    hi = *(uint32_t*)&h;
    lo = *(uint32_t*)&l;
}

// ---------------- small prep kernels ----------------
__global__ void conv_kernel(const float* __restrict__ src,
                            __nv_bfloat16* __restrict__ hi,
                            __nv_bfloat16* __restrict__ lo, int n4)
{
    int i = blockIdx.x * blockDim.x + threadIdx.x;
    if (i >= n4) return;
    float4 v = *(const float4*)(src + i*4);
    uint32_t h0, l0, h1, l1;
    split2(v.x, v.y, h0, l0);
    split2(v.z, v.w, h1, l1);
    *(uint32_t*)(hi + i*4)     = h0;
    *(uint32_t*)(hi + i*4 + 2) = h1;
    *(uint32_t*)(lo + i*4)     = l0;
    *(uint32_t*)(lo + i*4 + 2) = l1;
}

__global__ void rope_table_kernel(const int* __restrict__ pos,
                                  float* __restrict__ cosT, float* __restrict__ sinT)
{
    int idx = blockIdx.x * blockDim.x + threadIdx.x;   // 0..SEQ*32-1
    int s  = idx >> 5;
    int ip = idx & 31;
    double invf = exp2(-(double)ip * 0.41524101186092028);  // log2(10000)/32
    float ang = (float)pos[s] * (float)invf;
    float sn, cs;
    sincosf(ang, &sn, &cs);
    cosT[idx] = cs;
    sinT[idx] = sn;
}

// ---------------- mma.sync GEMM: C = A[M,K] * W[N,K]^T, bf16x3 split ----------------
// MODE 0: row-major fp32 C; MODE 1: bf16 hi/lo scatter [b,h,s,dk]; MODE 2: + RoPE
#define KC 32
#define NKCH (DMODEL/KC)          // 32
#define LDSTR 40                  // b16 stride (80B)
#define TILE_B16 (128*LDSTR)      // 5120
#define OFF_AHI 0
#define OFF_ALO (1*TILE_B16)
#define OFF_BHI (2*TILE_B16)
#define OFF_BLO (3*TILE_B16)
#define STAGE_B16 (4*TILE_B16)    // 20480
#define GEMM_SMEM (2*STAGE_B16*2) // 81920 bytes

template<int MODE>
__global__ __launch_bounds__(256, 1)
void gemm_mma(const __nv_bfloat16* __restrict__ Ahi, const __nv_bfloat16* __restrict__ Alo,
              const __nv_bfloat16* __restrict__ Bhi, const __nv_bfloat16* __restrict__ Blo,
              float* __restrict__ C,
              __nv_bfloat16* __restrict__ Chi, __nv_bfloat16* __restrict__ Clo,
              const float* __restrict__ ropec, const float* __restrict__ ropes)
{
    extern __shared__ __nv_bfloat16 smb[];
    const uint32_t sbase = smem_u32(smb);
    const int tid  = threadIdx.x;
    const int wid  = tid >> 5;
    const int lane = tid & 31;
    const int bm = blockIdx.y, bn = blockIdx.x;
    const int wm = wid & 3;
    const int wn = wid >> 2;

    float acc[2][8][4];
    #pragma unroll
    for (int mt = 0; mt < 2; mt++)
        #pragma unroll
        for (int nt = 0; nt < 8; nt++)
            #pragma unroll
            for (int j = 0; j < 4; j++) acc[mt][nt][j] = 0.f;

    const __nv_bfloat16* Ah = Ahi + (size_t)(bm*128)*DMODEL;
    const __nv_bfloat16* Al = Alo + (size_t)(bm*128)*DMODEL;
    const __nv_bfloat16* Bh = Bhi + (size_t)(bn*128)*DMODEL;
    const __nv_bfloat16* Bl = Blo + (size_t)(bn*128)*DMODEL;

    auto load_stage = [&](int st, int kc) {
        const int koff = kc*KC;
        const uint32_t sb = sbase + st*(STAGE_B16*2);
        #pragma unroll
        for (int i = 0; i < 2; i++) {
            int item = tid + i*256;
            int r = item >> 2;
            int c = item & 3;
            uint32_t d = sb + (uint32_t)(r*LDSTR + c*8)*2;
            const __nv_bfloat16* sa = Ah + (size_t)r*DMODEL + koff + c*8;
            cp16(d + OFF_AHI*2, sa);
            cp16(d + OFF_ALO*2, Al + (sa - Ah));
            const __nv_bfloat16* sbp = Bh + (size_t)r*DMODEL + koff + c*8;
            cp16(d + OFF_BHI*2, sbp);
            cp16(d + OFF_BLO*2, Bl + (sbp - Bh));
        }
    };

    load_stage(0, 0); CP_COMMIT();
    load_stage(1, 1); CP_COMMIT();

    const int a_row = wm*32 + (lane & 15);
    const int a_co  = (lane >> 4) * 8;
    const int b_row = wn*64 + (lane & 7);
    const int b_co  = ((lane >> 3) & 1) * 8;

    for (int kc = 0; kc < NKCH; kc++) {
        if (kc + 1 < NKCH) cp_wait<1>(); else cp_wait<0>();
        __syncthreads();
        const uint32_t sb = sbase + (kc & 1)*(STAGE_B16*2);

        #pragma unroll
        for (int ks = 0; ks < 2; ks++) {
            const int kof = ks*16;
            uint32_t ah[2][4], al[2][4];
            #pragma unroll
            for (int mt = 0; mt < 2; mt++) {
                uint32_t aaddr = sb + (uint32_t)((a_row + mt*16)*LDSTR + kof + a_co)*2;
                ldsm_x4(ah[mt][0], ah[mt][1], ah[mt][2], ah[mt][3], aaddr + OFF_AHI*2);
                ldsm_x4(al[mt][0], al[mt][1], al[mt][2], al[mt][3], aaddr + OFF_ALO*2);
            }
            #pragma unroll
            for (int nt = 0; nt < 8; nt++) {
                uint32_t baddr = sb + (uint32_t)((b_row + nt*8)*LDSTR + kof + b_co)*2;
                uint32_t bh[2], bl[2];
                ldsm_x2(bh[0], bh[1], baddr + OFF_BHI*2);
                ldsm_x2(bl[0], bl[1], baddr + OFF_BLO*2);
                #pragma unroll
                for (int mt = 0; mt < 2; mt++) {
                    mma_bf16(acc[mt][nt], ah[mt], bh);
                    mma_bf16(acc[mt][nt], al[mt], bh);
                    mma_bf16(acc[mt][nt], ah[mt], bl);
                }
            }
        }
        __syncthreads();
        if (kc + 2 < NKCH) { load_stage(kc & 1, kc + 2); CP_COMMIT(); }
    }

    // ---- epilogue ----
    const int row_base = bm*128 + wm*32;
    const int col_base = bn*128 + wn*64;
    #pragma unroll
    for (int mt = 0; mt < 2; mt++) {
        #pragma unroll
        for (int rg = 0; rg < 2; rg++) {
            int row = row_base + mt*16 + rg*8 + (lane >> 2);
            int s = row & (SEQ-1);
            int b = row >> 11;
            #pragma unroll
            for (int nt = 0; nt < 8; nt++) {
                int col = col_base + nt*8 + 2*(lane & 3);
                float e = acc[mt][nt][rg*2];
                float o = acc[mt][nt][rg*2+1];
                if (MODE == 2) {
                    int ip = (col & 63) >> 1;
                    float cs = ropec[s*32 + ip];
                    float sn = ropes[s*32 + ip];
                    float ne = e*cs - o*sn;
                    float no = e*sn + o*cs;
                    e = ne; o = no;
                }
                if (MODE == 0) {
                    *(float2*)(C + (size_t)row*DMODEL + col) = make_float2(e, o);
                } else {
                    int h = col >> 6, dk = col & 63;
                    size_t idx = ((size_t)(b*NHEADS + h)*SEQ + s)*DKH + dk;
                    uint32_t hi, lo;
                    split2(e, o, hi, lo);
                    *(uint32_t*)(Chi + idx) = hi;
                    *(uint32_t*)(Clo + idx) = lo;
                }
            }
        }
    }
}

// ---------------- mma.sync flash attention (causal), bf16x3 ----------------
// CTA: 128 queries x one (b,h). 8 warps; warp = 16 q rows x ALL 64 keys of tile.
// smem (b16 units): Qh[128][72], Ql, Kh[64][72], Kl, VtH[64][72] (d-major,
// chunk-XOR swizzled), VtL.
#define AQ_STR 72
#define SQH 0
#define SQL (128*AQ_STR)                // 9216
#define SKH (2*128*AQ_STR)              // 18432
#define SKL (SKH + 64*AQ_STR)
#define SVH (SKH + 2*64*AQ_STR)
#define SVL (SKH + 3*64*AQ_STR)
#define ATTN_SMEM_B16 (SKH + 4*64*AQ_STR)     // 36864
#define ATTN_SMEM_BYTES (ATTN_SMEM_B16*2)     // 73728

__global__ __launch_bounds__(256, 2)
void attn_mma(const __nv_bfloat16* __restrict__ Qh_g, const __nv_bfloat16* __restrict__ Ql_g,
              const __nv_bfloat16* __restrict__ Kh_g, const __nv_bfloat16* __restrict__ Kl_g,
              const __nv_bfloat16* __restrict__ Vh_g, const __nv_bfloat16* __restrict__ Vl_g,
              __nv_bfloat16* __restrict__ Ohi, __nv_bfloat16* __restrict__ Olo)
{
    extern __shared__ __nv_bfloat16 smb[];
    const uint32_t sb = smem_u32(smb);
    const int tid  = threadIdx.x;
    const int wq   = tid >> 5;        // warp id = q group
    const int lane = tid & 31;
    const int bh   = blockIdx.y;
    const int qt   = gridDim.x - 1 - blockIdx.x;   // big tiles first
    const int q0   = qt * 128;
    const size_t boff = (size_t)bh*SEQ*DKH;

    // ---- Q tiles (hi+lo) via cp.async ----
    #pragma unroll
    for (int l = 0; l < 4; l++) {
        int item = tid + l*256;       // 0..1023
        int r = item >> 3;            // 0..127
        int c = item & 7;             // 8 b16 chunks
        uint32_t d = sb + (uint32_t)(r*AQ_STR + c*8)*2;
        const __nv_bfloat16* src = Qh_g + boff + (size_t)(q0+r)*DKH + c*8;
        cp16(d + SQH*2, src);
        cp16(d + SQL*2, Ql_g + (src - Qh_g));
    }
    CP_COMMIT();

    float sc[8][4];
    float o[8][4];
    #pragma unroll
    for (int nt = 0; nt < 8; nt++)
        #pragma unroll
        for (int j = 0; j < 4; j++) o[nt][j] = 0.f;
    float m0 = -INFINITY, m1 = -INFINITY, l0 = 0.f, l1 = 0.f;

    const int nkt = qt*2 + 2;

    for (int t = 0; t < nkt; t++) {
        const int k0 = t * 64;
        if (t > 0) __syncthreads();       // prior tile reads done
        // K (hi/lo) via cp.async
        #pragma unroll
        for (int l = 0; l < 2; l++) {
            int item = tid + l*256;       // 0..511
            int r = item >> 3;            // 0..63
            int c = item & 7;
            uint32_t d = sb + (uint32_t)(r*AQ_STR + c*8)*2;
            const __nv_bfloat16* src = Kh_g + boff + (size_t)(k0+r)*DKH + c*8;
            cp16(d + SKH*2, src);
            cp16(d + SKL*2, Kl_g + (src - Kh_g));
        }
        CP_COMMIT();
        // V: ldg + transposed swizzled store (Vt[d][key])
        #pragma unroll
        for (int l = 0; l < 2; l++) {
            int item = tid + l*256;
            int r = item >> 3;            // key 0..63
            int c = item & 7;             // d chunk
            const __nv_bfloat16* src = Vh_g + boff + (size_t)(k0+r)*DKH + c*8;
            uint4 vh = *(const uint4*)src;
            uint4 vl = *(const uint4*)(Vl_g + (src - Vh_g));
            __nv_bfloat16 th[8], tl[8];
            *(uint4*)th = vh; *(uint4*)tl = vl;
            int kc_sw = ((r >> 3) ^ c) << 3;
            #pragma unroll
            for (int j = 0; j < 8; j++) {
                int d = c*8 + j;
                smb[SVH + d*AQ_STR + kc_sw + (r & 7)] = th[j];
                smb[SVL + d*AQ_STR + kc_sw + (r & 7)] = tl[j];
            }
        }
        cp_wait<0>();
        __syncthreads();

        const bool active = (k0 <= q0 + wq*16 + 15);
        if (active) {
            // ---- S = Q K^T (3 passes) ----
            #pragma unroll
            for (int nt = 0; nt < 8; nt++)
                #pragma unroll
                for (int j = 0; j < 4; j++) sc[nt][j] = 0.f;
            #pragma unroll
            for (int kt = 0; kt < 4; kt++) {
                uint32_t ah[4], al[4];
                uint32_t aaddr = sb + (uint32_t)((wq*16 + (lane & 15))*AQ_STR + kt*16 + (lane >> 4)*8)*2;
                ldsm_x4(ah[0], ah[1], ah[2], ah[3], aaddr + SQH*2);
                ldsm_x4(al[0], al[1], al[2], al[3], aaddr + SQL*2);
                #pragma unroll
                for (int nt = 0; nt < 8; nt++) {
                    uint32_t baddr = sb + (uint32_t)((nt*8 + (lane & 7))*AQ_STR + kt*16 + ((lane >> 3) & 1)*8)*2;
                    uint32_t kh[2], kl[2];
                    ldsm_x2(kh[0], kh[1], baddr + SKH*2);
                    ldsm_x2(kl[0], kl[1], baddr + SKL*2);
                    mma_bf16(sc[nt], ah, kh);
                    mma_bf16(sc[nt], al, kh);
                    mma_bf16(sc[nt], ah, kl);
                }
            }

            // ---- softmax (online) ----
            const int qrow = q0 + wq*16 + (lane >> 2);
            const bool needmask = (k0 + 63 > q0 + wq*16);
            float mx0 = -1e30f, mx1 = -1e30f;
            #pragma unroll
            for (int nt = 0; nt < 8; nt++) {
                #pragma unroll
                for (int j = 0; j < 4; j++) sc[nt][j] *= 0.125f;
                if (needmask) {
                    int kcol = k0 + nt*8 + 2*(lane & 3);
                    if (kcol+0 > qrow)   sc[nt][0] = -1e30f;
                    if (kcol+1 > qrow)   sc[nt][1] = -1e30f;
                    if (kcol+0 > qrow+8) sc[nt][2] = -1e30f;
                    if (kcol+1 > qrow+8) sc[nt][3] = -1e30f;
                }
                mx0 = fmaxf(mx0, fmaxf(sc[nt][0], sc[nt][1]));
                mx1 = fmaxf(mx1, fmaxf(sc[nt][2], sc[nt][3]));
            }
            mx0 = fmaxf(mx0, __shfl_xor_sync(0xffffffffu, mx0, 1));
            mx0 = fmaxf(mx0, __shfl_xor_sync(0xffffffffu, mx0, 2));
            mx1 = fmaxf(mx1, __shfl_xor_sync(0xffffffffu, mx1, 1));
            mx1 = fmaxf(mx1, __shfl_xor_sync(0xffffffffu, mx1, 2));
            float mn0 = fmaxf(m0, mx0), mn1 = fmaxf(m1, mx1);
            float f0 = __expf(m0 - mn0), f1 = __expf(m1 - mn1);
            m0 = mn0; m1 = mn1;
            float sum0 = 0.f, sum1 = 0.f;
            #pragma unroll
            for (int nt = 0; nt < 8; nt++) {
                sc[nt][0] = __expf(sc[nt][0] - mn0);
                sc[nt][1] = __expf(sc[nt][1] - mn0);
                sc[nt][2] = __expf(sc[nt][2] - mn1);
                sc[nt][3] = __expf(sc[nt][3] - mn1);
                sum0 += sc[nt][0] + sc[nt][1];
                sum1 += sc[nt][2] + sc[nt][3];
            }
            sum0 += __shfl_xor_sync(0xffffffffu, sum0, 1);
            sum0 += __shfl_xor_sync(0xffffffffu, sum0, 2);
            sum1 += __shfl_xor_sync(0xffffffffu, sum1, 1);
            sum1 += __shfl_xor_sync(0xffffffffu, sum1, 2);
            l0 = l0*f0 + sum0;
            l1 = l1*f1 + sum1;
            #pragma unroll
            for (int nt = 0; nt < 8; nt++) {
                o[nt][0] *= f0; o[nt][1] *= f0;
                o[nt][2] *= f1; o[nt][3] *= f1;
            }

            // ---- O += P V (3 passes), P frags from S accumulators ----
            #pragma unroll
            for (int kt = 0; kt < 4; kt++) {
                uint32_t ph[4], pl[4];
                split2(sc[2*kt][0],   sc[2*kt][1],   ph[0], pl[0]);
                split2(sc[2*kt][2],   sc[2*kt][3],   ph[1], pl[1]);
                split2(sc[2*kt+1][0], sc[2*kt+1][1], ph[2], pl[2]);
                split2(sc[2*kt+1][2], sc[2*kt+1][3], ph[3], pl[3]);
                #pragma unroll
                for (int nt = 0; nt < 8; nt++) {
                    int chunk = (kt*2 + ((lane >> 3) & 1)) ^ nt;
                    uint32_t vaddr = sb + (uint32_t)((nt*8 + (lane & 7))*AQ_STR + chunk*8)*2;
                    uint32_t vh[2], vl[2];
                    ldsm_x2(vh[0], vh[1], vaddr + SVH*2);
                    ldsm_x2(vl[0], vl[1], vaddr + SVL*2);
                    mma_bf16(o[nt], ph, vh);
                    mma_bf16(o[nt], pl, vh);
                    mma_bf16(o[nt], ph, vl);
                }
            }
        }
    }

    // ---- epilogue: normalize, split to bf16 hi/lo, store [b*s][h*64+d] ----
    const int b = bh >> 4, h = bh & 15;
    const float i0 = 1.f / l0, i1 = 1.f / l1;
    const int srow = q0 + wq*16 + (lane >> 2);
    const size_t base0 = ((size_t)(b*SEQ + srow))*DMODEL + h*64;
    const size_t base1 = base0 + (size_t)8*DMODEL;
    #pragma unroll
    for (int nt = 0; nt < 8; nt++) {
        int col = nt*8 + 2*(lane & 3);
        uint32_t hi, lo;
        split2(o[nt][0]*i0, o[nt][1]*i0, hi, lo);
        *(uint32_t*)(Ohi + base0 + col) = hi;
        *(uint32_t*)(Olo + base0 + col) = lo;
        split2(o[nt][2]*i1, o[nt][3]*i1, hi, lo);
        *(uint32_t*)(Ohi + base1 + col) = hi;
        *(uint32_t*)(Olo + base1 + col) = lo;
    }
}

// ---------------- launch ----------------
extern "C" void kernel_launch(void* const* d_in, const int* in_sizes, int n_in,
                              void* d_out, int out_size)
{
    const float* x  = (const float*)d_in[0];
    const float* wq = (const float*)d_in[1];
    const float* wk = (const float*)d_in[2];
    const float* wv = (const float*)d_in[3];
    const float* wo = (const float*)d_in[4];
    const int*  pos = (const int*)d_in[5];
    float* out = (float*)d_out;

    float *rc, *rs;
    __nv_bfloat16 *xhi, *xlo, *whi, *wlo, *aohi, *aolo;
    __nv_bfloat16 *qhi, *qlo, *khi, *klo, *vhi, *vlo;
    cudaGetSymbolAddress((void**)&rc,   g_ropec);
    cudaGetSymbolAddress((void**)&rs,   g_ropes);
    cudaGetSymbolAddress((void**)&xhi,  g_xhi);
    cudaGetSymbolAddress((void**)&xlo,  g_xlo);
    cudaGetSymbolAddress((void**)&whi,  g_whi);
    cudaGetSymbolAddress((void**)&wlo,  g_wlo);
    cudaGetSymbolAddress((void**)&aohi, g_aohi);
    cudaGetSymbolAddress((void**)&aolo, g_aolo);
    cudaGetSymbolAddress((void**)&qhi,  g_qhi);
    cudaGetSymbolAddress((void**)&qlo,  g_qlo);
    cudaGetSymbolAddress((void**)&khi,  g_khi);
    cudaGetSymbolAddress((void**)&klo,  g_klo);
    cudaGetSymbolAddress((void**)&vhi,  g_vhi);
    cudaGetSymbolAddress((void**)&vlo,  g_vlo);

    static bool attr_done = false;
    if (!attr_done) {
        cudaFuncSetAttribute(gemm_mma<0>, cudaFuncAttributeMaxDynamicSharedMemorySize, GEMM_SMEM);
        cudaFuncSetAttribute(gemm_mma<1>, cudaFuncAttributeMaxDynamicSharedMemorySize, GEMM_SMEM);
        cudaFuncSetAttribute(gemm_mma<2>, cudaFuncAttributeMaxDynamicSharedMemorySize, GEMM_SMEM);
        cudaFuncSetAttribute(attn_mma, cudaFuncAttributeMaxDynamicSharedMemorySize, ATTN_SMEM_BYTES);
        attr_done = true;
    }

    const size_t WN = (size_t)DMODEL*DMODEL;   // 1M

    rope_table_kernel<<<(SEQ*32)/256, 256>>>(pos, rc, rs);
    conv_kernel<<<(M_TOT*DMODEL/4 + 255)/256, 256>>>(x,  xhi, xlo, M_TOT*DMODEL/4);
    conv_kernel<<<(WN/4 + 255)/256, 256>>>(wq, whi + 0*WN, wlo + 0*WN, WN/4);
    conv_kernel<<<(WN/4 + 255)/256, 256>>>(wk, whi + 1*WN, wlo + 1*WN, WN/4);
    conv_kernel<<<(WN/4 + 255)/256, 256>>>(wv, whi + 2*WN, wlo + 2*WN, WN/4);
    conv_kernel<<<(WN/4 + 255)/256, 256>>>(wo, whi + 3*WN, wlo + 3*WN, WN/4);

    dim3 gg(DMODEL/128, M_TOT/128);   // (8, 32)
    gemm_mma<2><<<gg, 256, GEMM_SMEM>>>(xhi, xlo, whi + 0*WN, wlo + 0*WN,
                                        nullptr, qhi, qlo, rc, rs);
    gemm_mma<2><<<gg, 256, GEMM_SMEM>>>(xhi, xlo, whi + 1*WN, wlo + 1*WN,
                                        nullptr, khi, klo, rc, rs);
    gemm_mma<1><<<gg, 256, GEMM_SMEM>>>(xhi, xlo, whi + 2*WN, wlo + 2*WN,
                                        nullptr, vhi, vlo, rc, rs);

    dim3 ga(SEQ/128, BATCH*NHEADS);   // (16, 32)
    attn_mma<<<ga, 256, ATTN_SMEM_BYTES>>>(qhi, qlo, khi, klo, vhi, vlo, aohi, aolo);

    gemm_mma<0><<<gg, 256, GEMM_SMEM>>>(aohi, aolo, whi + 3*WN, wlo + 3*WN,
                                        out, nullptr, nullptr, rc, rs);
}

// round 7
// speedup vs baseline: 2.7428x; 1.1533x over previous
#include <cuda_runtime.h>
#include <cuda_bf16.h>
#include <math.h>
#include <cstdint>

#define BATCH   2
#define SEQ     2048
#define DMODEL  1024
#define NHEADS  16
#define DKH     64
#define M_TOT   (BATCH*SEQ)   // 4096
#define QKV_ELEMS (BATCH*NHEADS*SEQ*DKH)

// ---------------- scratch (static device globals; no allocs) ----------------
__device__ __align__(256) __nv_bfloat16 g_xhi[M_TOT*DMODEL];
__device__ __align__(256) __nv_bfloat16 g_xlo[M_TOT*DMODEL];
__device__ __align__(256) __nv_bfloat16 g_whi[4*DMODEL*DMODEL];
__device__ __align__(256) __nv_bfloat16 g_wlo[4*DMODEL*DMODEL];
__device__ __align__(256) __nv_bfloat16 g_qhi[QKV_ELEMS];
__device__ __align__(256) __nv_bfloat16 g_qlo[QKV_ELEMS];
__device__ __align__(256) __nv_bfloat16 g_khi[QKV_ELEMS];
__device__ __align__(256) __nv_bfloat16 g_klo[QKV_ELEMS];
__device__ __align__(256) __nv_bfloat16 g_vhi[QKV_ELEMS];
__device__ __align__(256) __nv_bfloat16 g_vlo[QKV_ELEMS];
__device__ __align__(256) __nv_bfloat16 g_aohi[M_TOT*DMODEL];
__device__ __align__(256) __nv_bfloat16 g_aolo[M_TOT*DMODEL];
__device__ float g_ropec[SEQ*32];   // [s][ip]
__device__ float g_ropes[SEQ*32];

// ---------------- PTX helpers ----------------
__device__ __forceinline__ uint32_t smem_u32(const void* p) {
    uint32_t a;
    asm("{ .reg .u64 t; cvta.to.shared.u64 t, %1; cvt.u32.u64 %0, t; }" : "=r"(a) : "l"(p));
    return a;
}
__device__ __forceinline__ void cp16(uint32_t dst, const void* src) {
    asm volatile("cp.async.cg.shared.global [%0], [%1], 16;" :: "r"(dst), "l"(src) : "memory");
}
#define CP_COMMIT() asm volatile("cp.async.commit_group;" ::: "memory")
template<int N>
__device__ __forceinline__ void cp_wait() {
    asm volatile("cp.async.wait_group %0;" :: "n"(N) : "memory");
}
__device__ __forceinline__ void ldsm_x4(uint32_t& r0, uint32_t& r1, uint32_t& r2,
                                        uint32_t& r3, uint32_t addr) {
    asm volatile("ldmatrix.sync.aligned.m8n8.x4.shared.b16 {%0,%1,%2,%3}, [%4];"
                 : "=r"(r0), "=r"(r1), "=r"(r2), "=r"(r3) : "r"(addr));
}
__device__ __forceinline__ void mma_bf16(float* c, const uint32_t* a, const uint32_t* b) {
    asm volatile("mma.sync.aligned.m16n8k16.row.col.f32.bf16.bf16.f32 "
                 "{%0,%1,%2,%3}, {%4,%5,%6,%7}, {%8,%9}, {%0,%1,%2,%3};"
                 : "+f"(c[0]), "+f"(c[1]), "+f"(c[2]), "+f"(c[3])
                 : "r"(a[0]), "r"(a[1]), "r"(a[2]), "r"(a[3]), "r"(b[0]), "r"(b[1]));
}
// split pair of floats into packed bf16x2 hi + lo residual
__device__ __forceinline__ void split2(float a, float b, uint32_t& hi, uint32_t& lo) {
    __nv_bfloat162 h = __floats2bfloat162_rn(a, b);
    float ha = __low2float(h), hb = __high2float(h);
    __nv_bfloat162 l = __floats2bfloat162_rn(a - ha, b - hb);
    hi = *(uint32_t*)&h;
    lo = *(uint32_t*)&l;
}

// ---------------- small prep kernels ----------------
__global__ void conv_kernel(const float* __restrict__ src,
                            __nv_bfloat16* __restrict__ hi,
                            __nv_bfloat16* __restrict__ lo, int n4)
{
    int i = blockIdx.x * blockDim.x + threadIdx.x;
    if (i >= n4) return;
    float4 v = *(const float4*)(src + i*4);
    uint32_t h0, l0, h1, l1;
    split2(v.x, v.y, h0, l0);
    split2(v.z, v.w, h1, l1);
    *(uint32_t*)(hi + i*4)     = h0;
    *(uint32_t*)(hi + i*4 + 2) = h1;
    *(uint32_t*)(lo + i*4)     = l0;
    *(uint32_t*)(lo + i*4 + 2) = l1;
}

// convert all 4 weight matrices in one launch (z selects matrix)
__global__ void conv4_kernel(const float* __restrict__ w0, const float* __restrict__ w1,
                             const float* __restrict__ w2, const float* __restrict__ w3,
                             __nv_bfloat16* __restrict__ hi, __nv_bfloat16* __restrict__ lo)
{
    const int z = blockIdx.y;
    const float* src = (z == 0) ? w0 : (z == 1) ? w1 : (z == 2) ? w2 : w3;
    const size_t off = (size_t)z * DMODEL * DMODEL;
    int i = blockIdx.x * blockDim.x + threadIdx.x;   // float4 index
    float4 v = *(const float4*)(src + i*4);
    uint32_t h0, l0, h1, l1;
    split2(v.x, v.y, h0, l0);
    split2(v.z, v.w, h1, l1);
    *(uint32_t*)(hi + off + i*4)     = h0;
    *(uint32_t*)(hi + off + i*4 + 2) = h1;
    *(uint32_t*)(lo + off + i*4)     = l0;
    *(uint32_t*)(lo + off + i*4 + 2) = l1;
}

__global__ void rope_table_kernel(const int* __restrict__ pos,
                                  float* __restrict__ cosT, float* __restrict__ sinT)
{
    int idx = blockIdx.x * blockDim.x + threadIdx.x;   // 0..SEQ*32-1
    int s  = idx >> 5;
    int ip = idx & 31;
    double invf = exp2(-(double)ip * 0.41524101186092028);  // log2(10000)/32
    float ang = (float)pos[s] * (float)invf;
    float sn, cs;
    sincosf(ang, &sn, &cs);
    cosT[idx] = cs;
    sinT[idx] = sn;
}

// ---------------- mma.sync GEMM: C = A[M,K] * W[N,K]^T, bf16x3 split ----------------
// MODE 0: row-major fp32 C; MODE 1: bf16 hi/lo scatter [b,h,s,dk]; MODE 2: + RoPE
// MODE 3: fused QKV — blockIdx.z selects weight set / output (z=0,1: RoPE; z=2: plain)
#define KC 32
#define NKCH (DMODEL/KC)          // 32
#define LDSTR 40                  // b16 stride (80B)
#define TILE_B16 (128*LDSTR)      // 5120
#define OFF_AHI 0
#define OFF_ALO (1*TILE_B16)
#define OFF_BHI (2*TILE_B16)
#define OFF_BLO (3*TILE_B16)
#define STAGE_B16 (4*TILE_B16)    // 20480
#define GEMM_SMEM (2*STAGE_B16*2) // 81920 bytes

template<int MODE>
__global__ __launch_bounds__(256, 2)
void gemm_mma(const __nv_bfloat16* __restrict__ Ahi, const __nv_bfloat16* __restrict__ Alo,
              const __nv_bfloat16* __restrict__ Bhi_, const __nv_bfloat16* __restrict__ Blo_,
              float* __restrict__ C,
              __nv_bfloat16* __restrict__ Chi_, __nv_bfloat16* __restrict__ Clo_,
              __nv_bfloat16* __restrict__ Chi1, __nv_bfloat16* __restrict__ Clo1,
              __nv_bfloat16* __restrict__ Chi2, __nv_bfloat16* __restrict__ Clo2,
              const float* __restrict__ ropec, const float* __restrict__ ropes)
{
    extern __shared__ __nv_bfloat16 smb[];
    const uint32_t sbase = smem_u32(smb);
    const int tid  = threadIdx.x;
    const int wid  = tid >> 5;
    const int lane = tid & 31;
    const int bm = blockIdx.y, bn = blockIdx.x;
    const int wm = wid & 3;
    const int wn = wid >> 2;

    const __nv_bfloat16* Bhi = Bhi_;
    const __nv_bfloat16* Blo = Blo_;
    __nv_bfloat16* Chi = Chi_;
    __nv_bfloat16* Clo = Clo_;
    bool do_rope = (MODE == 2);
    if (MODE == 3) {
        const int z = blockIdx.z;
        const size_t woff = (size_t)z * DMODEL * DMODEL;
        Bhi = Bhi_ + woff; Blo = Blo_ + woff;
        if (z == 1)      { Chi = Chi1; Clo = Clo1; }
        else if (z == 2) { Chi = Chi2; Clo = Clo2; }
        do_rope = (z < 2);
    }

    float acc[2][8][4];
    #pragma unroll
    for (int mt = 0; mt < 2; mt++)
        #pragma unroll
        for (int nt = 0; nt < 8; nt++)
            #pragma unroll
            for (int j = 0; j < 4; j++) acc[mt][nt][j] = 0.f;

    const __nv_bfloat16* Ah = Ahi + (size_t)(bm*128)*DMODEL;
    const __nv_bfloat16* Al = Alo + (size_t)(bm*128)*DMODEL;
    const __nv_bfloat16* Bh = Bhi + (size_t)(bn*128)*DMODEL;
    const __nv_bfloat16* Bl = Blo + (size_t)(bn*128)*DMODEL;

    auto load_stage = [&](int st, int kc) {
        const int koff = kc*KC;
        const uint32_t sb = sbase + st*(STAGE_B16*2);
        #pragma unroll
        for (int i = 0; i < 2; i++) {
            int item = tid + i*256;
            int r = item >> 2;
            int c = item & 3;
            uint32_t d = sb + (uint32_t)(r*LDSTR + c*8)*2;
            const __nv_bfloat16* sa = Ah + (size_t)r*DMODEL + koff + c*8;
            cp16(d + OFF_AHI*2, sa);
            cp16(d + OFF_ALO*2, Al + (sa - Ah));
            const __nv_bfloat16* sbp = Bh + (size_t)r*DMODEL + koff + c*8;
            cp16(d + OFF_BHI*2, sbp);
            cp16(d + OFF_BLO*2, Bl + (sbp - Bh));
        }
    };

    load_stage(0, 0); CP_COMMIT();
    load_stage(1, 1); CP_COMMIT();

    const int a_row = wm*32 + (lane & 15);
    const int a_co  = (lane >> 4) * 8;
    // ldsm_x4 B pairing: one x4 covers two adjacent n8 tiles x k16
    const int b_row_p = wn*64 + (lane & 7) + ((lane >> 4) << 3);  // + p*16
    const int b_co    = ((lane >> 3) & 1) * 8;

    for (int kc = 0; kc < NKCH; kc++) {
        if (kc + 1 < NKCH) cp_wait<1>(); else cp_wait<0>();
        __syncthreads();
        const uint32_t sb = sbase + (kc & 1)*(STAGE_B16*2);

        #pragma unroll
        for (int ks = 0; ks < 2; ks++) {
            const int kof = ks*16;
            uint32_t ah[2][4], al[2][4];
            #pragma unroll
            for (int mt = 0; mt < 2; mt++) {
                uint32_t aaddr = sb + (uint32_t)((a_row + mt*16)*LDSTR + kof + a_co)*2;
                ldsm_x4(ah[mt][0], ah[mt][1], ah[mt][2], ah[mt][3], aaddr + OFF_AHI*2);
                ldsm_x4(al[mt][0], al[mt][1], al[mt][2], al[mt][3], aaddr + OFF_ALO*2);
            }
            #pragma unroll
            for (int p = 0; p < 4; p++) {
                uint32_t baddr = sb + (uint32_t)((b_row_p + p*16)*LDSTR + kof + b_co)*2;
                uint32_t bh4[4], bl4[4];
                ldsm_x4(bh4[0], bh4[1], bh4[2], bh4[3], baddr + OFF_BHI*2);
                ldsm_x4(bl4[0], bl4[1], bl4[2], bl4[3], baddr + OFF_BLO*2);
                #pragma unroll
                for (int mt = 0; mt < 2; mt++) {
                    mma_bf16(acc[mt][2*p],   ah[mt], bh4);
                    mma_bf16(acc[mt][2*p],   al[mt], bh4);
                    mma_bf16(acc[mt][2*p],   ah[mt], bl4);
                    mma_bf16(acc[mt][2*p+1], ah[mt], bh4+2);
                    mma_bf16(acc[mt][2*p+1], al[mt], bh4+2);
                    mma_bf16(acc[mt][2*p+1], ah[mt], bl4+2);
                }
            }
        }
        __syncthreads();
        if (kc + 2 < NKCH) { load_stage(kc & 1, kc + 2); CP_COMMIT(); }
    }

    // ---- epilogue ----
    const int row_base = bm*128 + wm*32;
    const int col_base = bn*128 + wn*64;
    #pragma unroll
    for (int mt = 0; mt < 2; mt++) {
        #pragma unroll
        for (int rg = 0; rg < 2; rg++) {
            int row = row_base + mt*16 + rg*8 + (lane >> 2);
            int s = row & (SEQ-1);
            int b = row >> 11;
            #pragma unroll
            for (int nt = 0; nt < 8; nt++) {
                int col = col_base + nt*8 + 2*(lane & 3);
                float e = acc[mt][nt][rg*2];
                float o = acc[mt][nt][rg*2+1];
                if (MODE != 0 && do_rope) {
                    int ip = (col & 63) >> 1;
                    float cs = ropec[s*32 + ip];
                    float sn = ropes[s*32 + ip];
                    float ne = e*cs - o*sn;
                    float no = e*sn + o*cs;
                    e = ne; o = no;
                }
                if (MODE == 0) {
                    *(float2*)(C + (size_t)row*DMODEL + col) = make_float2(e, o);
                } else {
                    int h = col >> 6, dk = col & 63;
                    size_t idx = ((size_t)(b*NHEADS + h)*SEQ + s)*DKH + dk;
                    uint32_t hi, lo;
                    split2(e, o, hi, lo);
                    *(uint32_t*)(Chi + idx) = hi;
                    *(uint32_t*)(Clo + idx) = lo;
                }
            }
        }
    }
}

// ---------------- mma.sync flash attention (causal), bf16x3 ----------------
#define AQ_STR 72
#define SQH 0
#define SQL (128*AQ_STR)
#define SKH (2*128*AQ_STR)
#define SKL (SKH + 64*AQ_STR)
#define SVH (SKH + 2*64*AQ_STR)
#define SVL (SKH + 3*64*AQ_STR)
#define ATTN_SMEM_B16 (SKH + 4*64*AQ_STR)     // 36864
#define ATTN_SMEM_BYTES (ATTN_SMEM_B16*2)     // 73728

__global__ __launch_bounds__(256, 2)
void attn_mma(const __nv_bfloat16* __restrict__ Qh_g, const __nv_bfloat16* __restrict__ Ql_g,
              const __nv_bfloat16* __restrict__ Kh_g, const __nv_bfloat16* __restrict__ Kl_g,
              const __nv_bfloat16* __restrict__ Vh_g, const __nv_bfloat16* __restrict__ Vl_g,
              __nv_bfloat16* __restrict__ Ohi, __nv_bfloat16* __restrict__ Olo)
{
    extern __shared__ __nv_bfloat16 smb[];
    const uint32_t sb = smem_u32(smb);
    const int tid  = threadIdx.x;
    const int wq   = tid >> 5;
    const int lane = tid & 31;
    const int bh   = blockIdx.y;
    const int qt   = gridDim.x - 1 - blockIdx.x;
    const int q0   = qt * 128;
    const size_t boff = (size_t)bh*SEQ*DKH;

    #pragma unroll
    for (int l = 0; l < 4; l++) {
        int item = tid + l*256;
        int r = item >> 3;
        int c = item & 7;
        uint32_t d = sb + (uint32_t)(r*AQ_STR + c*8)*2;
        const __nv_bfloat16* src = Qh_g + boff + (size_t)(q0+r)*DKH + c*8;
        cp16(d + SQH*2, src);
        cp16(d + SQL*2, Ql_g + (src - Qh_g));
    }
    CP_COMMIT();

    float sc[8][4];
    float o[8][4];
    #pragma unroll
    for (int nt = 0; nt < 8; nt++)
        #pragma unroll
        for (int j = 0; j < 4; j++) o[nt][j] = 0.f;
    float m0 = -INFINITY, m1 = -INFINITY, l0 = 0.f, l1 = 0.f;

    const int nkt = qt*2 + 2;

    for (int t = 0; t < nkt; t++) {
        const int k0 = t * 64;
        if (t > 0) __syncthreads();
        #pragma unroll
        for (int l = 0; l < 2; l++) {
            int item = tid + l*256;
            int r = item >> 3;
            int c = item & 7;
            uint32_t d = sb + (uint32_t)(r*AQ_STR + c*8)*2;
            const __nv_bfloat16* src = Kh_g + boff + (size_t)(k0+r)*DKH + c*8;
            cp16(d + SKH*2, src);
            cp16(d + SKL*2, Kl_g + (src - Kh_g));
        }
        CP_COMMIT();
        #pragma unroll
        for (int l = 0; l < 2; l++) {
            int item = tid + l*256;
            int r = item >> 3;
            int c = item & 7;
            const __nv_bfloat16* src = Vh_g + boff + (size_t)(k0+r)*DKH + c*8;
            uint4 vh = *(const uint4*)src;
            uint4 vl = *(const uint4*)(Vl_g + (src - Vh_g));
            __nv_bfloat16 th[8], tl[8];
            *(uint4*)th = vh; *(uint4*)tl = vl;
            int kc_sw = ((r >> 3) ^ c) << 3;
            #pragma unroll
            for (int j = 0; j < 8; j++) {
                int d = c*8 + j;
                smb[SVH + d*AQ_STR + kc_sw + (r & 7)] = th[j];
                smb[SVL + d*AQ_STR + kc_sw + (r & 7)] = tl[j];
            }
        }
        cp_wait<0>();
        __syncthreads();

        const bool active = (k0 <= q0 + wq*16 + 15);
        if (active) {
            // ---- S = Q K^T (3 passes), ldsm_x4-paired K frags ----
            #pragma unroll
            for (int nt = 0; nt < 8; nt++)
                #pragma unroll
                for (int j = 0; j < 4; j++) sc[nt][j] = 0.f;
            #pragma unroll
            for (int kt = 0; kt < 4; kt++) {
                uint32_t ah[4], al[4];
                uint32_t aaddr = sb + (uint32_t)((wq*16 + (lane & 15))*AQ_STR + kt*16 + (lane >> 4)*8)*2;
                ldsm_x4(ah[0], ah[1], ah[2], ah[3], aaddr + SQH*2);
                ldsm_x4(al[0], al[1], al[2], al[3], aaddr + SQL*2);
                #pragma unroll
                for (int p = 0; p < 4; p++) {
                    int brow = p*16 + (lane & 7) + ((lane >> 4) << 3);
                    uint32_t baddr = sb + (uint32_t)(brow*AQ_STR + kt*16 + ((lane >> 3) & 1)*8)*2;
                    uint32_t kh4[4], kl4[4];
                    ldsm_x4(kh4[0], kh4[1], kh4[2], kh4[3], baddr + SKH*2);
                    ldsm_x4(kl4[0], kl4[1], kl4[2], kl4[3], baddr + SKL*2);
                    mma_bf16(sc[2*p],   ah, kh4);
                    mma_bf16(sc[2*p],   al, kh4);
                    mma_bf16(sc[2*p],   ah, kl4);
                    mma_bf16(sc[2*p+1], ah, kh4+2);
                    mma_bf16(sc[2*p+1], al, kh4+2);
                    mma_bf16(sc[2*p+1], ah, kl4+2);
                }
            }

            // ---- softmax (online) ----
            const int qrow = q0 + wq*16 + (lane >> 2);
            const bool needmask = (k0 + 63 > q0 + wq*16);
            float mx0 = -1e30f, mx1 = -1e30f;
            #pragma unroll
            for (int nt = 0; nt < 8; nt++) {
                #pragma unroll
                for (int j = 0; j < 4; j++) sc[nt][j] *= 0.125f;
                if (needmask) {
                    int kcol = k0 + nt*8 + 2*(lane & 3);
                    if (kcol+0 > qrow)   sc[nt][0] = -1e30f;
                    if (kcol+1 > qrow)   sc[nt][1] = -1e30f;
                    if (kcol+0 > qrow+8) sc[nt][2] = -1e30f;
                    if (kcol+1 > qrow+8) sc[nt][3] = -1e30f;
                }
                mx0 = fmaxf(mx0, fmaxf(sc[nt][0], sc[nt][1]));
                mx1 = fmaxf(mx1, fmaxf(sc[nt][2], sc[nt][3]));
            }
            mx0 = fmaxf(mx0, __shfl_xor_sync(0xffffffffu, mx0, 1));
            mx0 = fmaxf(mx0, __shfl_xor_sync(0xffffffffu, mx0, 2));
            mx1 = fmaxf(mx1, __shfl_xor_sync(0xffffffffu, mx1, 1));
            mx1 = fmaxf(mx1, __shfl_xor_sync(0xffffffffu, mx1, 2));
            float mn0 = fmaxf(m0, mx0), mn1 = fmaxf(m1, mx1);
            float f0 = __expf(m0 - mn0), f1 = __expf(m1 - mn1);
            m0 = mn0; m1 = mn1;
            float sum0 = 0.f, sum1 = 0.f;
            #pragma unroll
            for (int nt = 0; nt < 8; nt++) {
                sc[nt][0] = __expf(sc[nt][0] - mn0);
                sc[nt][1] = __expf(sc[nt][1] - mn0);
                sc[nt][2] = __expf(sc[nt][2] - mn1);
                sc[nt][3] = __expf(sc[nt][3] - mn1);
                sum0 += sc[nt][0] + sc[nt][1];
                sum1 += sc[nt][2] + sc[nt][3];
            }
            sum0 += __shfl_xor_sync(0xffffffffu, sum0, 1);
            sum0 += __shfl_xor_sync(0xffffffffu, sum0, 2);
            sum1 += __shfl_xor_sync(0xffffffffu, sum1, 1);
            sum1 += __shfl_xor_sync(0xffffffffu, sum1, 2);
            l0 = l0*f0 + sum0;
            l1 = l1*f1 + sum1;
            #pragma unroll
            for (int nt = 0; nt < 8; nt++) {
                o[nt][0] *= f0; o[nt][1] *= f0;
                o[nt][2] *= f1; o[nt][3] *= f1;
            }

            // ---- O += P V (3 passes), ldsm_x4-paired V frags ----
            #pragma unroll
            for (int kt = 0; kt < 4; kt++) {
                uint32_t ph[4], pl[4];
                split2(sc[2*kt][0],   sc[2*kt][1],   ph[0], pl[0]);
                split2(sc[2*kt][2],   sc[2*kt][3],   ph[1], pl[1]);
                split2(sc[2*kt+1][0], sc[2*kt+1][1], ph[2], pl[2]);
                split2(sc[2*kt+1][2], sc[2*kt+1][3], ph[3], pl[3]);
                #pragma unroll
                for (int p = 0; p < 4; p++) {
                    int ntl = 2*p + (lane >> 4);
                    int vrow = ntl*8 + (lane & 7);
                    int chunk = (kt*2 + ((lane >> 3) & 1)) ^ ntl;
                    uint32_t vaddr = sb + (uint32_t)(vrow*AQ_STR + chunk*8)*2;
                    uint32_t vh4[4], vl4[4];
                    ldsm_x4(vh4[0], vh4[1], vh4[2], vh4[3], vaddr + SVH*2);
                    ldsm_x4(vl4[0], vl4[1], vl4[2], vl4[3], vaddr + SVL*2);
                    mma_bf16(o[2*p],   ph, vh4);
                    mma_bf16(o[2*p],   pl, vh4);
                    mma_bf16(o[2*p],   ph, vl4);
                    mma_bf16(o[2*p+1], ph, vh4+2);
                    mma_bf16(o[2*p+1], pl, vh4+2);
                    mma_bf16(o[2*p+1], ph, vl4+2);
                }
            }
        }
    }

    // ---- epilogue ----
    const int b = bh >> 4, h = bh & 15;
    const float i0 = 1.f / l0, i1 = 1.f / l1;
    const int srow = q0 + wq*16 + (lane >> 2);
    const size_t base0 = ((size_t)(b*SEQ + srow))*DMODEL + h*64;
    const size_t base1 = base0 + (size_t)8*DMODEL;
    #pragma unroll
    for (int nt = 0; nt < 8; nt++) {
        int col = nt*8 + 2*(lane & 3);
        uint32_t hi, lo;
        split2(o[nt][0]*i0, o[nt][1]*i0, hi, lo);
        *(uint32_t*)(Ohi + base0 + col) = hi;
        *(uint32_t*)(Olo + base0 + col) = lo;
        split2(o[nt][2]*i1, o[nt][3]*i1, hi, lo);
        *(uint32_t*)(Ohi + base1 + col) = hi;
        *(uint32_t*)(Olo + base1 + col) = lo;
    }
}

// ---------------- launch ----------------
extern "C" void kernel_launch(void* const* d_in, const int* in_sizes, int n_in,
                              void* d_out, int out_size)
{
    const float* x  = (const float*)d_in[0];
    const float* wq = (const float*)d_in[1];
    const float* wk = (const float*)d_in[2];
    const float* wv = (const float*)d_in[3];
    const float* wo = (const float*)d_in[4];
    const int*  pos = (const int*)d_in[5];
    float* out = (float*)d_out;

    float *rc, *rs;
    __nv_bfloat16 *xhi, *xlo, *whi, *wlo, *aohi, *aolo;
    __nv_bfloat16 *qhi, *qlo, *khi, *klo, *vhi, *vlo;
    cudaGetSymbolAddress((void**)&rc,   g_ropec);
    cudaGetSymbolAddress((void**)&rs,   g_ropes);
    cudaGetSymbolAddress((void**)&xhi,  g_xhi);
    cudaGetSymbolAddress((void**)&xlo,  g_xlo);
    cudaGetSymbolAddress((void**)&whi,  g_whi);
    cudaGetSymbolAddress((void**)&wlo,  g_wlo);
    cudaGetSymbolAddress((void**)&aohi, g_aohi);
    cudaGetSymbolAddress((void**)&aolo, g_aolo);
    cudaGetSymbolAddress((void**)&qhi,  g_qhi);
    cudaGetSymbolAddress((void**)&qlo,  g_qlo);
    cudaGetSymbolAddress((void**)&khi,  g_khi);
    cudaGetSymbolAddress((void**)&klo,  g_klo);
    cudaGetSymbolAddress((void**)&vhi,  g_vhi);
    cudaGetSymbolAddress((void**)&vlo,  g_vlo);

    static bool attr_done = false;
    if (!attr_done) {
        cudaFuncSetAttribute(gemm_mma<0>, cudaFuncAttributeMaxDynamicSharedMemorySize, GEMM_SMEM);
        cudaFuncSetAttribute(gemm_mma<3>, cudaFuncAttributeMaxDynamicSharedMemorySize, GEMM_SMEM);
        cudaFuncSetAttribute(attn_mma, cudaFuncAttributeMaxDynamicSharedMemorySize, ATTN_SMEM_BYTES);
        attr_done = true;
    }

    rope_table_kernel<<<(SEQ*32)/256, 256>>>(pos, rc, rs);
    conv_kernel<<<(M_TOT*DMODEL/4 + 255)/256, 256>>>(x, xhi, xlo, M_TOT*DMODEL/4);
    {
        dim3 gc(DMODEL*DMODEL/4/256, 4);
        conv4_kernel<<<gc, 256>>>(wq, wk, wv, wo, whi, wlo);
    }

    const size_t WN = (size_t)DMODEL*DMODEL;

    // fused QKV projection: z=0 -> Q(+RoPE), z=1 -> K(+RoPE), z=2 -> V
    dim3 gqkv(DMODEL/128, M_TOT/128, 3);   // (8, 32, 3)
    gemm_mma<3><<<gqkv, 256, GEMM_SMEM>>>(xhi, xlo, whi, wlo,
                                          nullptr, qhi, qlo, khi, klo, vhi, vlo, rc, rs);

    dim3 ga(SEQ/128, BATCH*NHEADS);   // (16, 32)
    attn_mma<<<ga, 256, ATTN_SMEM_BYTES>>>(qhi, qlo, khi, klo, vhi, vlo, aohi, aolo);

    dim3 gg(DMODEL/128, M_TOT/128);   // (8, 32)
    gemm_mma<0><<<gg, 256, GEMM_SMEM>>>(aohi, aolo, whi + 3*WN, wlo + 3*WN,
                                        out, nullptr, nullptr, nullptr, nullptr,
                                        nullptr, nullptr, rc, rs);
}

// round 8
// speedup vs baseline: 2.8037x; 1.0222x over previous
#include <cuda_runtime.h>
#include <cuda_bf16.h>
#include <math.h>
#include <cstdint>

#define BATCH   2
#define SEQ     2048
#define DMODEL  1024
#define NHEADS  16
#define DKH     64
#define M_TOT   (BATCH*SEQ)   // 4096
#define QKV_ELEMS (BATCH*NHEADS*SEQ*DKH)

// ---------------- scratch (static device globals; no allocs) ----------------
__device__ __align__(256) __nv_bfloat16 g_xhi[M_TOT*DMODEL];
__device__ __align__(256) __nv_bfloat16 g_xlo[M_TOT*DMODEL];
__device__ __align__(256) __nv_bfloat16 g_whi[4*DMODEL*DMODEL];
__device__ __align__(256) __nv_bfloat16 g_wlo[4*DMODEL*DMODEL];
__device__ __align__(256) __nv_bfloat16 g_qhi[QKV_ELEMS];
__device__ __align__(256) __nv_bfloat16 g_qlo[QKV_ELEMS];
__device__ __align__(256) __nv_bfloat16 g_khi[QKV_ELEMS];
__device__ __align__(256) __nv_bfloat16 g_klo[QKV_ELEMS];
__device__ __align__(256) __nv_bfloat16 g_vhi[QKV_ELEMS];
__device__ __align__(256) __nv_bfloat16 g_vlo[QKV_ELEMS];
__device__ __align__(256) __nv_bfloat16 g_aohi[M_TOT*DMODEL];
__device__ __align__(256) __nv_bfloat16 g_aolo[M_TOT*DMODEL];
__device__ float g_ropec[SEQ*32];   // [s][ip]
__device__ float g_ropes[SEQ*32];

// ---------------- PTX helpers ----------------
__device__ __forceinline__ uint32_t smem_u32(const void* p) {
    uint32_t a;
    asm("{ .reg .u64 t; cvta.to.shared.u64 t, %1; cvt.u32.u64 %0, t; }" : "=r"(a) : "l"(p));
    return a;
}
__device__ __forceinline__ void cp16(uint32_t dst, const void* src) {
    asm volatile("cp.async.cg.shared.global [%0], [%1], 16;" :: "r"(dst), "l"(src) : "memory");
}
#define CP_COMMIT() asm volatile("cp.async.commit_group;" ::: "memory")
template<int N>
__device__ __forceinline__ void cp_wait() {
    asm volatile("cp.async.wait_group %0;" :: "n"(N) : "memory");
}
__device__ __forceinline__ void ldsm_x4(uint32_t& r0, uint32_t& r1, uint32_t& r2,
                                        uint32_t& r3, uint32_t addr) {
    asm volatile("ldmatrix.sync.aligned.m8n8.x4.shared.b16 {%0,%1,%2,%3}, [%4];"
                 : "=r"(r0), "=r"(r1), "=r"(r2), "=r"(r3) : "r"(addr));
}
__device__ __forceinline__ void ldsm_x4t(uint32_t& r0, uint32_t& r1, uint32_t& r2,
                                         uint32_t& r3, uint32_t addr) {
    asm volatile("ldmatrix.sync.aligned.m8n8.x4.trans.shared.b16 {%0,%1,%2,%3}, [%4];"
                 : "=r"(r0), "=r"(r1), "=r"(r2), "=r"(r3) : "r"(addr));
}
__device__ __forceinline__ void mma_bf16(float* c, const uint32_t* a, const uint32_t* b) {
    asm volatile("mma.sync.aligned.m16n8k16.row.col.f32.bf16.bf16.f32 "
                 "{%0,%1,%2,%3}, {%4,%5,%6,%7}, {%8,%9}, {%0,%1,%2,%3};"
                 : "+f"(c[0]), "+f"(c[1]), "+f"(c[2]), "+f"(c[3])
                 : "r"(a[0]), "r"(a[1]), "r"(a[2]), "r"(a[3]), "r"(b[0]), "r"(b[1]));
}
// split pair of floats into packed bf16x2 hi + lo residual
__device__ __forceinline__ void split2(float a, float b, uint32_t& hi, uint32_t& lo) {
    __nv_bfloat162 h = __floats2bfloat162_rn(a, b);
    float ha = __low2float(h), hb = __high2float(h);
    __nv_bfloat162 l = __floats2bfloat162_rn(a - ha, b - hb);
    hi = *(uint32_t*)&h;
    lo = *(uint32_t*)&l;
}

// ---------------- small prep kernels ----------------
__global__ void conv_kernel(const float* __restrict__ src,
                            __nv_bfloat16* __restrict__ hi,
                            __nv_bfloat16* __restrict__ lo, int n4)
{
    int i = blockIdx.x * blockDim.x + threadIdx.x;
    if (i >= n4) return;
    float4 v = *(const float4*)(src + i*4);
    uint32_t h0, l0, h1, l1;
    split2(v.x, v.y, h0, l0);
    split2(v.z, v.w, h1, l1);
    *(uint32_t*)(hi + i*4)     = h0;
    *(uint32_t*)(hi + i*4 + 2) = h1;
    *(uint32_t*)(lo + i*4)     = l0;
    *(uint32_t*)(lo + i*4 + 2) = l1;
}

__global__ void conv4_kernel(const float* __restrict__ w0, const float* __restrict__ w1,
                             const float* __restrict__ w2, const float* __restrict__ w3,
                             __nv_bfloat16* __restrict__ hi, __nv_bfloat16* __restrict__ lo)
{
    const int z = blockIdx.y;
    const float* src = (z == 0) ? w0 : (z == 1) ? w1 : (z == 2) ? w2 : w3;
    const size_t off = (size_t)z * DMODEL * DMODEL;
    int i = blockIdx.x * blockDim.x + threadIdx.x;   // float4 index
    float4 v = *(const float4*)(src + i*4);
    uint32_t h0, l0, h1, l1;
    split2(v.x, v.y, h0, l0);
    split2(v.z, v.w, h1, l1);
    *(uint32_t*)(hi + off + i*4)     = h0;
    *(uint32_t*)(hi + off + i*4 + 2) = h1;
    *(uint32_t*)(lo + off + i*4)     = l0;
    *(uint32_t*)(lo + off + i*4 + 2) = l1;
}

__global__ void rope_table_kernel(const int* __restrict__ pos,
                                  float* __restrict__ cosT, float* __restrict__ sinT)
{
    int idx = blockIdx.x * blockDim.x + threadIdx.x;   // 0..SEQ*32-1
    int s  = idx >> 5;
    int ip = idx & 31;
    double invf = exp2(-(double)ip * 0.41524101186092028);  // log2(10000)/32
    float ang = (float)pos[s] * (float)invf;
    float sn, cs;
    sincosf(ang, &sn, &cs);
    cosT[idx] = cs;
    sinT[idx] = sn;
}

// ---------------- mma.sync GEMM, 4-stage cp.async pipeline, KC=16 ----------------
// CTA tile 128x128, 256 threads (8 warps 4m x 2n; warp 32x64).
// MODE 0: row-major fp32 C; MODE 3: fused QKV (z: 0=Q+RoPE, 1=K+RoPE, 2=V)
#define NKCH (DMODEL/16)          // 64
#define GROW 24                   // b16 row stride (48B, 16B-aligned, conflict-free)
#define G_TILE_BYTES (128*GROW*2) // 6144
#define G_STAGE_BYTES (4*G_TILE_BYTES)  // 24576 (Ahi,Alo,Bhi,Blo)
#define GEMM_SMEM (4*G_STAGE_BYTES)     // 98304

template<int MODE>
__global__ __launch_bounds__(256, 2)
void gemm_mma(const __nv_bfloat16* __restrict__ Ahi, const __nv_bfloat16* __restrict__ Alo,
              const __nv_bfloat16* __restrict__ Bhi_, const __nv_bfloat16* __restrict__ Blo_,
              float* __restrict__ C,
              __nv_bfloat16* __restrict__ Chi_, __nv_bfloat16* __restrict__ Clo_,
              __nv_bfloat16* __restrict__ Chi1, __nv_bfloat16* __restrict__ Clo1,
              __nv_bfloat16* __restrict__ Chi2, __nv_bfloat16* __restrict__ Clo2,
              const float* __restrict__ ropec, const float* __restrict__ ropes)
{
    extern __shared__ __nv_bfloat16 smb[];
    const uint32_t sbase = smem_u32(smb);
    const int tid  = threadIdx.x;
    const int wid  = tid >> 5;
    const int lane = tid & 31;
    const int bm = blockIdx.y, bn = blockIdx.x;
    const int wm = wid & 3;
    const int wn = wid >> 2;

    const __nv_bfloat16* Bhi = Bhi_;
    const __nv_bfloat16* Blo = Blo_;
    __nv_bfloat16* Chi = Chi_;
    __nv_bfloat16* Clo = Clo_;
    bool do_rope = false;
    if (MODE == 3) {
        const int z = blockIdx.z;
        const size_t woff = (size_t)z * DMODEL * DMODEL;
        Bhi = Bhi_ + woff; Blo = Blo_ + woff;
        if (z == 1)      { Chi = Chi1; Clo = Clo1; }
        else if (z == 2) { Chi = Chi2; Clo = Clo2; }
        do_rope = (z < 2);
    }

    float acc[2][8][4];
    #pragma unroll
    for (int mt = 0; mt < 2; mt++)
        #pragma unroll
        for (int nt = 0; nt < 8; nt++)
            #pragma unroll
            for (int j = 0; j < 4; j++) acc[mt][nt][j] = 0.f;

    const __nv_bfloat16* Ah = Ahi + (size_t)(bm*128)*DMODEL;
    const __nv_bfloat16* Al = Alo + (size_t)(bm*128)*DMODEL;
    const __nv_bfloat16* Bh = Bhi + (size_t)(bn*128)*DMODEL;
    const __nv_bfloat16* Bl = Blo + (size_t)(bn*128)*DMODEL;

    // per-thread load role: bsel buffer, lc 16B chunk, rb row base
    const int bsel = tid & 3;
    const int lc   = (tid >> 2) & 1;
    const int rb   = tid >> 3;              // 0..31
    const __nv_bfloat16* Pb =
        (bsel == 0) ? Ah : (bsel == 1) ? Al : (bsel == 2) ? Bh : Bl;
    const __nv_bfloat16* Psrc = Pb + (size_t)rb*DMODEL + lc*8;
    const uint32_t dbase = sbase + (uint32_t)(bsel*G_TILE_BYTES + rb*48 + lc*16);

    auto load_stage = [&](int stg, int kc) {
        const uint32_t d = dbase + stg*G_STAGE_BYTES;
        const __nv_bfloat16* s = Psrc + kc*16;
        #pragma unroll
        for (int i = 0; i < 4; i++)
            cp16(d + i*(32*48), s + (size_t)(i*32)*DMODEL);
        CP_COMMIT();
    };

    load_stage(0, 0);
    load_stage(1, 1);
    load_stage(2, 2);

    const int a_row   = wm*32 + (lane & 15);
    const int a_co    = (lane >> 4) * 8;
    const int b_row_p = wn*64 + (lane & 7) + ((lane >> 4) << 3);
    const int b_co    = ((lane >> 3) & 1) * 8;

    for (int kc = 0; kc < NKCH; kc++) {
        if (kc < NKCH-2)       cp_wait<2>();
        else if (kc == NKCH-2) cp_wait<1>();
        else                   cp_wait<0>();
        __syncthreads();
        const uint32_t sbk = sbase + (kc & 3)*G_STAGE_BYTES;

        uint32_t ah[2][4], al[2][4];
        #pragma unroll
        for (int mt = 0; mt < 2; mt++) {
            uint32_t aaddr = sbk + (uint32_t)(((a_row + mt*16)*GROW + a_co)*2);
            ldsm_x4(ah[mt][0], ah[mt][1], ah[mt][2], ah[mt][3], aaddr);
            ldsm_x4(al[mt][0], al[mt][1], al[mt][2], al[mt][3], aaddr + G_TILE_BYTES);
        }
        #pragma unroll
        for (int p = 0; p < 4; p++) {
            uint32_t baddr = sbk + 2*G_TILE_BYTES +
                             (uint32_t)(((b_row_p + p*16)*GROW + b_co)*2);
            uint32_t bh4[4], bl4[4];
            ldsm_x4(bh4[0], bh4[1], bh4[2], bh4[3], baddr);
            ldsm_x4(bl4[0], bl4[1], bl4[2], bl4[3], baddr + G_TILE_BYTES);
            #pragma unroll
            for (int mt = 0; mt < 2; mt++) {
                mma_bf16(acc[mt][2*p],   ah[mt], bh4);
                mma_bf16(acc[mt][2*p],   al[mt], bh4);
                mma_bf16(acc[mt][2*p],   ah[mt], bl4);
                mma_bf16(acc[mt][2*p+1], ah[mt], bh4+2);
                mma_bf16(acc[mt][2*p+1], al[mt], bh4+2);
                mma_bf16(acc[mt][2*p+1], ah[mt], bl4+2);
            }
        }
        if (kc + 3 < NKCH) load_stage((kc + 3) & 3, kc + 3);
    }

    // ---- epilogue ----
    const int row_base = bm*128 + wm*32;
    const int col_base = bn*128 + wn*64;
    #pragma unroll
    for (int mt = 0; mt < 2; mt++) {
        #pragma unroll
        for (int rg = 0; rg < 2; rg++) {
            int row = row_base + mt*16 + rg*8 + (lane >> 2);
            int s = row & (SEQ-1);
            int b = row >> 11;
            #pragma unroll
            for (int nt = 0; nt < 8; nt++) {
                int col = col_base + nt*8 + 2*(lane & 3);
                float e = acc[mt][nt][rg*2];
                float o = acc[mt][nt][rg*2+1];
                if (MODE == 3 && do_rope) {
                    int ip = (col & 63) >> 1;
                    float cs = ropec[s*32 + ip];
                    float sn = ropes[s*32 + ip];
                    float ne = e*cs - o*sn;
                    float no = e*sn + o*cs;
                    e = ne; o = no;
                }
                if (MODE == 0) {
                    *(float2*)(C + (size_t)row*DMODEL + col) = make_float2(e, o);
                } else {
                    int h = col >> 6, dk = col & 63;
                    size_t idx = ((size_t)(b*NHEADS + h)*SEQ + s)*DKH + dk;
                    uint32_t hi, lo;
                    split2(e, o, hi, lo);
                    *(uint32_t*)(Chi + idx) = hi;
                    *(uint32_t*)(Clo + idx) = lo;
                }
            }
        }
    }
}

// ---------------- mma.sync flash attention, double-buffered K/V, trans-V ----------------
// CTA: 128 q x one (b,h). 8 warps; warp = 16 q x 64 keys.
// smem b16: Qhi[128][72] @0, Qlo @9216; 2 stages @18432: {Khi,Klo,Vhi,Vlo} 64x72 each.
#define A_STR 72
#define A_SQL 9216
#define A_SST 18432
#define A_BUF 4608                 // 64*72
#define A_STG (4*A_BUF)            // 18432
#define ATTN_SMEM_BYTES ((A_SST + 2*A_STG)*2)   // 110592

__global__ __launch_bounds__(256, 2)
void attn_mma(const __nv_bfloat16* __restrict__ Qh_g, const __nv_bfloat16* __restrict__ Ql_g,
              const __nv_bfloat16* __restrict__ Kh_g, const __nv_bfloat16* __restrict__ Kl_g,
              const __nv_bfloat16* __restrict__ Vh_g, const __nv_bfloat16* __restrict__ Vl_g,
              __nv_bfloat16* __restrict__ Ohi, __nv_bfloat16* __restrict__ Olo)
{
    extern __shared__ __nv_bfloat16 smb[];
    const uint32_t sb = smem_u32(smb);
    const int tid  = threadIdx.x;
    const int wq   = tid >> 5;
    const int lane = tid & 31;
    const int bh   = blockIdx.y;
    const int qt   = gridDim.x - 1 - blockIdx.x;
    const int q0   = qt * 128;
    const size_t boff = (size_t)bh*SEQ*DKH;

    // ---- Q (hi+lo) ----
    #pragma unroll
    for (int l = 0; l < 4; l++) {
        int item = tid + l*256;
        int r = item >> 3;
        int c = item & 7;
        uint32_t d = sb + (uint32_t)(r*A_STR + c*8)*2;
        const __nv_bfloat16* src = Qh_g + boff + (size_t)(q0+r)*DKH + c*8;
        cp16(d, src);
        cp16(d + A_SQL*2, Ql_g + (src - Qh_g));
    }
    CP_COMMIT();

    // KV loader role: bsel in {Khi,Klo,Vhi,Vlo}; 64 threads per buffer
    const int bsel = tid >> 6;
    const int loc  = tid & 63;
    const int vc   = loc & 7;       // 16B chunk
    const int vr   = loc >> 3;      // rows vr, vr+8, ..., vr+56
    const __nv_bfloat16* Pk =
        (bsel == 0) ? Kh_g : (bsel == 1) ? Kl_g : (bsel == 2) ? Vh_g : Vl_g;
    const __nv_bfloat16* Pkv = Pk + boff + (size_t)vr*DKH + vc*8;
    const uint32_t dkv = sb + (uint32_t)((A_SST + bsel*A_BUF + vr*A_STR + vc*8)*2);

    auto load_kv = [&](int stg, int t) {
        const __nv_bfloat16* s = Pkv + (size_t)(t*64)*DKH;
        const uint32_t d = dkv + stg*(A_STG*2);
        #pragma unroll
        for (int i = 0; i < 8; i++)
            cp16(d + i*(8*A_STR*2), s + (size_t)(i*8)*DKH);
        CP_COMMIT();
    };

    load_kv(0, 0);

    float sc[8][4];
    float o[8][4];
    #pragma unroll
    for (int nt = 0; nt < 8; nt++)
        #pragma unroll
        for (int j = 0; j < 4; j++) o[nt][j] = 0.f;
    float m0 = -INFINITY, m1 = -INFINITY, l0 = 0.f, l1 = 0.f;

    const int nkt = qt*2 + 2;

    for (int t = 0; t < nkt; t++) {
        const int k0 = t * 64;
        if (t + 1 < nkt) { load_kv((t+1) & 1, t+1); cp_wait<1>(); }
        else             { cp_wait<0>(); }
        __syncthreads();
        const uint32_t stb = sb + (uint32_t)((A_SST + (t & 1)*A_STG)*2);

        const bool active = (k0 <= q0 + wq*16 + 15);
        if (active) {
            // ---- S = Q K^T (3 passes) ----
            #pragma unroll
            for (int nt = 0; nt < 8; nt++)
                #pragma unroll
                for (int j = 0; j < 4; j++) sc[nt][j] = 0.f;
            #pragma unroll
            for (int kt = 0; kt < 4; kt++) {
                uint32_t ah[4], al[4];
                uint32_t aaddr = sb + (uint32_t)(((wq*16 + (lane & 15))*A_STR + kt*16 + (lane >> 4)*8)*2);
                ldsm_x4(ah[0], ah[1], ah[2], ah[3], aaddr);
                ldsm_x4(al[0], al[1], al[2], al[3], aaddr + A_SQL*2);
                #pragma unroll
                for (int p = 0; p < 4; p++) {
                    int brow = p*16 + (lane & 7) + ((lane >> 4) << 3);
                    uint32_t baddr = stb + (uint32_t)((brow*A_STR + kt*16 + ((lane >> 3) & 1)*8)*2);
                    uint32_t kh4[4], kl4[4];
                    ldsm_x4(kh4[0], kh4[1], kh4[2], kh4[3], baddr);
                    ldsm_x4(kl4[0], kl4[1], kl4[2], kl4[3], baddr + A_BUF*2);
                    mma_bf16(sc[2*p],   ah, kh4);
                    mma_bf16(sc[2*p],   al, kh4);
                    mma_bf16(sc[2*p],   ah, kl4);
                    mma_bf16(sc[2*p+1], ah, kh4+2);
                    mma_bf16(sc[2*p+1], al, kh4+2);
                    mma_bf16(sc[2*p+1], ah, kl4+2);
                }
            }

            // ---- softmax (online) ----
            const int qrow = q0 + wq*16 + (lane >> 2);
            const bool needmask = (k0 + 63 > q0 + wq*16);
            float mx0 = -1e30f, mx1 = -1e30f;
            #pragma unroll
            for (int nt = 0; nt < 8; nt++) {
                #pragma unroll
                for (int j = 0; j < 4; j++) sc[nt][j] *= 0.125f;
                if (needmask) {
                    int kcol = k0 + nt*8 + 2*(lane & 3);
                    if (kcol+0 > qrow)   sc[nt][0] = -1e30f;
                    if (kcol+1 > qrow)   sc[nt][1] = -1e30f;
                    if (kcol+0 > qrow+8) sc[nt][2] = -1e30f;
                    if (kcol+1 > qrow+8) sc[nt][3] = -1e30f;
                }
                mx0 = fmaxf(mx0, fmaxf(sc[nt][0], sc[nt][1]));
                mx1 = fmaxf(mx1, fmaxf(sc[nt][2], sc[nt][3]));
            }
            mx0 = fmaxf(mx0, __shfl_xor_sync(0xffffffffu, mx0, 1));
            mx0 = fmaxf(mx0, __shfl_xor_sync(0xffffffffu, mx0, 2));
            mx1 = fmaxf(mx1, __shfl_xor_sync(0xffffffffu, mx1, 1));
            mx1 = fmaxf(mx1, __shfl_xor_sync(0xffffffffu, mx1, 2));
            float mn0 = fmaxf(m0, mx0), mn1 = fmaxf(m1, mx1);
            float f0 = __expf(m0 - mn0), f1 = __expf(m1 - mn1);
            m0 = mn0; m1 = mn1;
            float sum0 = 0.f, sum1 = 0.f;
            #pragma unroll
            for (int nt = 0; nt < 8; nt++) {
                sc[nt][0] = __expf(sc[nt][0] - mn0);
                sc[nt][1] = __expf(sc[nt][1] - mn0);
                sc[nt][2] = __expf(sc[nt][2] - mn1);
                sc[nt][3] = __expf(sc[nt][3] - mn1);
                sum0 += sc[nt][0] + sc[nt][1];
                sum1 += sc[nt][2] + sc[nt][3];
            }
            sum0 += __shfl_xor_sync(0xffffffffu, sum0, 1);
            sum0 += __shfl_xor_sync(0xffffffffu, sum0, 2);
            sum1 += __shfl_xor_sync(0xffffffffu, sum1, 1);
            sum1 += __shfl_xor_sync(0xffffffffu, sum1, 2);
            l0 = l0*f0 + sum0;
            l1 = l1*f1 + sum1;
            #pragma unroll
            for (int nt = 0; nt < 8; nt++) {
                o[nt][0] *= f0; o[nt][1] *= f0;
                o[nt][2] *= f1; o[nt][3] *= f1;
            }

            // ---- O += P V (3 passes), V frags via ldmatrix.trans ----
            #pragma unroll
            for (int kt = 0; kt < 4; kt++) {
                uint32_t ph[4], pl[4];
                split2(sc[2*kt][0],   sc[2*kt][1],   ph[0], pl[0]);
                split2(sc[2*kt][2],   sc[2*kt][3],   ph[1], pl[1]);
                split2(sc[2*kt+1][0], sc[2*kt+1][1], ph[2], pl[2]);
                split2(sc[2*kt+1][2], sc[2*kt+1][3], ph[3], pl[3]);
                #pragma unroll
                for (int dp = 0; dp < 4; dp++) {
                    uint32_t vaddr = stb + (uint32_t)((2*A_BUF +
                                     (kt*16 + (lane & 15))*A_STR +
                                     dp*16 + ((lane >> 4) & 1)*8)*2);
                    uint32_t vh4[4], vl4[4];
                    ldsm_x4t(vh4[0], vh4[1], vh4[2], vh4[3], vaddr);
                    ldsm_x4t(vl4[0], vl4[1], vl4[2], vl4[3], vaddr + A_BUF*2);
                    mma_bf16(o[2*dp],   ph, vh4);
                    mma_bf16(o[2*dp],   pl, vh4);
                    mma_bf16(o[2*dp],   ph, vl4);
                    mma_bf16(o[2*dp+1], ph, vh4+2);
                    mma_bf16(o[2*dp+1], pl, vh4+2);
                    mma_bf16(o[2*dp+1], ph, vl4+2);
                }
            }
        }
        __syncthreads();   // protect stage (t+1)&1 before next iteration's load
    }

    // ---- epilogue ----
    const int b = bh >> 4, h = bh & 15;
    const float i0 = 1.f / l0, i1 = 1.f / l1;
    const int srow = q0 + wq*16 + (lane >> 2);
    const size_t base0 = ((size_t)(b*SEQ + srow))*DMODEL + h*64;
    const size_t base1 = base0 + (size_t)8*DMODEL;
    #pragma unroll
    for (int nt = 0; nt < 8; nt++) {
        int col = nt*8 + 2*(lane & 3);
        uint32_t hi, lo;
        split2(o[nt][0]*i0, o[nt][1]*i0, hi, lo);
        *(uint32_t*)(Ohi + base0 + col) = hi;
        *(uint32_t*)(Olo + base0 + col) = lo;
        split2(o[nt][2]*i1, o[nt][3]*i1, hi, lo);
        *(uint32_t*)(Ohi + base1 + col) = hi;
        *(uint32_t*)(Olo + base1 + col) = lo;
    }
}

// ---------------- launch ----------------
extern "C" void kernel_launch(void* const* d_in, const int* in_sizes, int n_in,
                              void* d_out, int out_size)
{
    const float* x  = (const float*)d_in[0];
    const float* wq = (const float*)d_in[1];
    const float* wk = (const float*)d_in[2];
    const float* wv = (const float*)d_in[3];
    const float* wo = (const float*)d_in[4];
    const int*  pos = (const int*)d_in[5];
    float* out = (float*)d_out;

    float *rc, *rs;
    __nv_bfloat16 *xhi, *xlo, *whi, *wlo, *aohi, *aolo;
    __nv_bfloat16 *qhi, *qlo, *khi, *klo, *vhi, *vlo;
    cudaGetSymbolAddress((void**)&rc,   g_ropec);
    cudaGetSymbolAddress((void**)&rs,   g_ropes);
    cudaGetSymbolAddress((void**)&xhi,  g_xhi);
    cudaGetSymbolAddress((void**)&xlo,  g_xlo);
    cudaGetSymbolAddress((void**)&whi,  g_whi);
    cudaGetSymbolAddress((void**)&wlo,  g_wlo);
    cudaGetSymbolAddress((void**)&aohi, g_aohi);
    cudaGetSymbolAddress((void**)&aolo, g_aolo);
    cudaGetSymbolAddress((void**)&qhi,  g_qhi);
    cudaGetSymbolAddress((void**)&qlo,  g_qlo);
    cudaGetSymbolAddress((void**)&khi,  g_khi);
    cudaGetSymbolAddress((void**)&klo,  g_klo);
    cudaGetSymbolAddress((void**)&vhi,  g_vhi);
    cudaGetSymbolAddress((void**)&vlo,  g_vlo);

    static bool attr_done = false;
    if (!attr_done) {
        cudaFuncSetAttribute(gemm_mma<0>, cudaFuncAttributeMaxDynamicSharedMemorySize, GEMM_SMEM);
        cudaFuncSetAttribute(gemm_mma<3>, cudaFuncAttributeMaxDynamicSharedMemorySize, GEMM_SMEM);
        cudaFuncSetAttribute(attn_mma, cudaFuncAttributeMaxDynamicSharedMemorySize, ATTN_SMEM_BYTES);
        attr_done = true;
    }

    rope_table_kernel<<<(SEQ*32)/256, 256>>>(pos, rc, rs);
    conv_kernel<<<(M_TOT*DMODEL/4 + 255)/256, 256>>>(x, xhi, xlo, M_TOT*DMODEL/4);
    {
        dim3 gc(DMODEL*DMODEL/4/256, 4);
        conv4_kernel<<<gc, 256>>>(wq, wk, wv, wo, whi, wlo);
    }

    const size_t WN = (size_t)DMODEL*DMODEL;

    dim3 gqkv(DMODEL/128, M_TOT/128, 3);   // (8, 32, 3)
    gemm_mma<3><<<gqkv, 256, GEMM_SMEM>>>(xhi, xlo, whi, wlo,
                                          nullptr, qhi, qlo, khi, klo, vhi, vlo, rc, rs);

    dim3 ga(SEQ/128, BATCH*NHEADS);   // (16, 32)
    attn_mma<<<ga, 256, ATTN_SMEM_BYTES>>>(qhi, qlo, khi, klo, vhi, vlo, aohi, aolo);

    dim3 gg(DMODEL/128, M_TOT/128);   // (8, 32)
    gemm_mma<0><<<gg, 256, GEMM_SMEM>>>(aohi, aolo, whi + 3*WN, wlo + 3*WN,
                                        out, nullptr, nullptr, nullptr, nullptr,
                                        nullptr, nullptr, rc, rs);
}

// round 9
// speedup vs baseline: 2.8417x; 1.0136x over previous
#include <cuda_runtime.h>
#include <cuda_bf16.h>
#include <math.h>
#include <cstdint>

#define BATCH   2
#define SEQ     2048
#define DMODEL  1024
#define NHEADS  16
#define DKH     64
#define M_TOT   (BATCH*SEQ)   // 4096
#define QKV_ELEMS (BATCH*NHEADS*SEQ*DKH)

// ---------------- scratch (static device globals; no allocs) ----------------
__device__ __align__(256) __nv_bfloat16 g_xhi[M_TOT*DMODEL];
__device__ __align__(256) __nv_bfloat16 g_xlo[M_TOT*DMODEL];
__device__ __align__(256) __nv_bfloat16 g_whi[4*DMODEL*DMODEL];
__device__ __align__(256) __nv_bfloat16 g_wlo[4*DMODEL*DMODEL];
__device__ __align__(256) __nv_bfloat16 g_qhi[QKV_ELEMS];
__device__ __align__(256) __nv_bfloat16 g_qlo[QKV_ELEMS];
__device__ __align__(256) __nv_bfloat16 g_khi[QKV_ELEMS];
__device__ __align__(256) __nv_bfloat16 g_klo[QKV_ELEMS];
__device__ __align__(256) __nv_bfloat16 g_vhi[QKV_ELEMS];
__device__ __align__(256) __nv_bfloat16 g_vlo[QKV_ELEMS];
__device__ __align__(256) __nv_bfloat16 g_aohi[M_TOT*DMODEL];
__device__ __align__(256) __nv_bfloat16 g_aolo[M_TOT*DMODEL];
__device__ float g_ropec[SEQ*32];   // [s][ip]
__device__ float g_ropes[SEQ*32];

// ---------------- PTX helpers ----------------
__device__ __forceinline__ uint32_t smem_u32(const void* p) {
    uint32_t a;
    asm("{ .reg .u64 t; cvta.to.shared.u64 t, %1; cvt.u32.u64 %0, t; }" : "=r"(a) : "l"(p));
    return a;
}
__device__ __forceinline__ void cp16(uint32_t dst, const void* src) {
    asm volatile("cp.async.cg.shared.global [%0], [%1], 16;" :: "r"(dst), "l"(src) : "memory");
}
#define CP_COMMIT() asm volatile("cp.async.commit_group;" ::: "memory")
template<int N>
__device__ __forceinline__ void cp_wait() {
    asm volatile("cp.async.wait_group %0;" :: "n"(N) : "memory");
}
__device__ __forceinline__ void ldsm_x4(uint32_t& r0, uint32_t& r1, uint32_t& r2,
                                        uint32_t& r3, uint32_t addr) {
    asm volatile("ldmatrix.sync.aligned.m8n8.x4.shared.b16 {%0,%1,%2,%3}, [%4];"
                 : "=r"(r0), "=r"(r1), "=r"(r2), "=r"(r3) : "r"(addr));
}
__device__ __forceinline__ void ldsm_x4t(uint32_t& r0, uint32_t& r1, uint32_t& r2,
                                         uint32_t& r3, uint32_t addr) {
    asm volatile("ldmatrix.sync.aligned.m8n8.x4.trans.shared.b16 {%0,%1,%2,%3}, [%4];"
                 : "=r"(r0), "=r"(r1), "=r"(r2), "=r"(r3) : "r"(addr));
}
__device__ __forceinline__ void mma_bf16(float* c, const uint32_t* a, const uint32_t* b) {
    asm volatile("mma.sync.aligned.m16n8k16.row.col.f32.bf16.bf16.f32 "
                 "{%0,%1,%2,%3}, {%4,%5,%6,%7}, {%8,%9}, {%0,%1,%2,%3};"
                 : "+f"(c[0]), "+f"(c[1]), "+f"(c[2]), "+f"(c[3])
                 : "r"(a[0]), "r"(a[1]), "r"(a[2]), "r"(a[3]), "r"(b[0]), "r"(b[1]));
}
// split pair of floats into packed bf16x2 hi + lo residual
__device__ __forceinline__ void split2(float a, float b, uint32_t& hi, uint32_t& lo) {
    __nv_bfloat162 h = __floats2bfloat162_rn(a, b);
    float ha = __low2float(h), hb = __high2float(h);
    __nv_bfloat162 l = __floats2bfloat162_rn(a - ha, b - hb);
    hi = *(uint32_t*)&h;
    lo = *(uint32_t*)&l;
}

// ---------------- fused prep: x (4 quarters) + 4 weights, uniform segments ----------------
// blockIdx.y: 0..3 -> quarter of x; 4..7 -> w[y-4]. Each segment = 262144 float4.
__global__ void convall_kernel(const float* __restrict__ x,
                               const float* __restrict__ w0, const float* __restrict__ w1,
                               const float* __restrict__ w2, const float* __restrict__ w3,
                               __nv_bfloat16* __restrict__ xhi, __nv_bfloat16* __restrict__ xlo,
                               __nv_bfloat16* __restrict__ whi, __nv_bfloat16* __restrict__ wlo)
{
    const int y = blockIdx.y;
    const float* src;
    __nv_bfloat16 *hi, *lo;
    size_t off;
    if (y < 4) {
        src = x + (size_t)y * (M_TOT*DMODEL/4);
        off = (size_t)y * (M_TOT*DMODEL/4);
        hi = xhi; lo = xlo;
    } else {
        const float* ws[4] = {w0, w1, w2, w3};
        src = ws[y-4];
        off = (size_t)(y-4) * DMODEL * DMODEL;
        hi = whi; lo = wlo;
    }
    int i = blockIdx.x * blockDim.x + threadIdx.x;   // float4 index within segment
    float4 v = *(const float4*)(src + (size_t)i*4);
    uint32_t h0, l0, h1, l1;
    split2(v.x, v.y, h0, l0);
    split2(v.z, v.w, h1, l1);
    *(uint32_t*)(hi + off + (size_t)i*4)     = h0;
    *(uint32_t*)(hi + off + (size_t)i*4 + 2) = h1;
    *(uint32_t*)(lo + off + (size_t)i*4)     = l0;
    *(uint32_t*)(lo + off + (size_t)i*4 + 2) = l1;
}

__global__ void rope_table_kernel(const int* __restrict__ pos,
                                  float* __restrict__ cosT, float* __restrict__ sinT)
{
    int idx = blockIdx.x * blockDim.x + threadIdx.x;   // 0..SEQ*32-1
    int s  = idx >> 5;
    int ip = idx & 31;
    double invf = exp2(-(double)ip * 0.41524101186092028);  // log2(10000)/32
    float ang = (float)pos[s] * (float)invf;
    float sn, cs;
    sincosf(ang, &sn, &cs);
    cosT[idx] = cs;
    sinT[idx] = sn;
}

// ---------------- mma.sync GEMM, 4-stage cp.async pipeline, KC=16, pass-major MMA ----------------
#define NKCH (DMODEL/16)          // 64
#define GROW 24                   // b16 row stride (48B)
#define G_TILE_BYTES (128*GROW*2) // 6144
#define G_STAGE_BYTES (4*G_TILE_BYTES)  // 24576
#define GEMM_SMEM (4*G_STAGE_BYTES)     // 98304

template<int MODE>
__global__ __launch_bounds__(256, 2)
void gemm_mma(const __nv_bfloat16* __restrict__ Ahi, const __nv_bfloat16* __restrict__ Alo,
              const __nv_bfloat16* __restrict__ Bhi_, const __nv_bfloat16* __restrict__ Blo_,
              float* __restrict__ C,
              __nv_bfloat16* __restrict__ Chi_, __nv_bfloat16* __restrict__ Clo_,
              __nv_bfloat16* __restrict__ Chi1, __nv_bfloat16* __restrict__ Clo1,
              __nv_bfloat16* __restrict__ Chi2, __nv_bfloat16* __restrict__ Clo2,
              const float* __restrict__ ropec, const float* __restrict__ ropes)
{
    extern __shared__ __nv_bfloat16 smb[];
    const uint32_t sbase = smem_u32(smb);
    const int tid  = threadIdx.x;
    const int wid  = tid >> 5;
    const int lane = tid & 31;
    const int bm = blockIdx.y, bn = blockIdx.x;
    const int wm = wid & 3;
    const int wn = wid >> 2;

    const __nv_bfloat16* Bhi = Bhi_;
    const __nv_bfloat16* Blo = Blo_;
    __nv_bfloat16* Chi = Chi_;
    __nv_bfloat16* Clo = Clo_;
    bool do_rope = false;
    if (MODE == 3) {
        const int z = blockIdx.z;
        const size_t woff = (size_t)z * DMODEL * DMODEL;
        Bhi = Bhi_ + woff; Blo = Blo_ + woff;
        if (z == 1)      { Chi = Chi1; Clo = Clo1; }
        else if (z == 2) { Chi = Chi2; Clo = Clo2; }
        do_rope = (z < 2);
    }

    float acc[2][8][4];
    #pragma unroll
    for (int mt = 0; mt < 2; mt++)
        #pragma unroll
        for (int nt = 0; nt < 8; nt++)
            #pragma unroll
            for (int j = 0; j < 4; j++) acc[mt][nt][j] = 0.f;

    const __nv_bfloat16* Ah = Ahi + (size_t)(bm*128)*DMODEL;
    const __nv_bfloat16* Al = Alo + (size_t)(bm*128)*DMODEL;
    const __nv_bfloat16* Bh = Bhi + (size_t)(bn*128)*DMODEL;
    const __nv_bfloat16* Bl = Blo + (size_t)(bn*128)*DMODEL;

    const int bsel = tid & 3;
    const int lc   = (tid >> 2) & 1;
    const int rb   = tid >> 3;              // 0..31
    const __nv_bfloat16* Pb =
        (bsel == 0) ? Ah : (bsel == 1) ? Al : (bsel == 2) ? Bh : Bl;
    const __nv_bfloat16* Psrc = Pb + (size_t)rb*DMODEL + lc*8;
    const uint32_t dbase = sbase + (uint32_t)(bsel*G_TILE_BYTES + rb*48 + lc*16);

    auto load_stage = [&](int stg, int kc) {
        const uint32_t d = dbase + stg*G_STAGE_BYTES;
        const __nv_bfloat16* s = Psrc + kc*16;
        #pragma unroll
        for (int i = 0; i < 4; i++)
            cp16(d + i*(32*48), s + (size_t)(i*32)*DMODEL);
        CP_COMMIT();
    };

    load_stage(0, 0);
    load_stage(1, 1);
    load_stage(2, 2);

    const int a_row   = wm*32 + (lane & 15);
    const int a_co    = (lane >> 4) * 8;
    const int b_row_p = wn*64 + (lane & 7) + ((lane >> 4) << 3);
    const int b_co    = ((lane >> 3) & 1) * 8;

    for (int kc = 0; kc < NKCH; kc++) {
        if (kc < NKCH-2)       cp_wait<2>();
        else if (kc == NKCH-2) cp_wait<1>();
        else                   cp_wait<0>();
        __syncthreads();
        const uint32_t sbk = sbase + (kc & 3)*G_STAGE_BYTES;

        uint32_t ah[2][4], al[2][4];
        #pragma unroll
        for (int mt = 0; mt < 2; mt++) {
            uint32_t aaddr = sbk + (uint32_t)(((a_row + mt*16)*GROW + a_co)*2);
            ldsm_x4(ah[mt][0], ah[mt][1], ah[mt][2], ah[mt][3], aaddr);
            ldsm_x4(al[mt][0], al[mt][1], al[mt][2], al[mt][3], aaddr + G_TILE_BYTES);
        }
        // process n in two halves; within a half, pass-major (8 independent mma per pass)
        #pragma unroll
        for (int pp = 0; pp < 2; pp++) {
            uint32_t bh4[2][4], bl4[2][4];
            #pragma unroll
            for (int i = 0; i < 2; i++) {
                int p = 2*pp + i;
                uint32_t baddr = sbk + 2*G_TILE_BYTES +
                                 (uint32_t)(((b_row_p + p*16)*GROW + b_co)*2);
                ldsm_x4(bh4[i][0], bh4[i][1], bh4[i][2], bh4[i][3], baddr);
                ldsm_x4(bl4[i][0], bl4[i][1], bl4[i][2], bl4[i][3], baddr + G_TILE_BYTES);
            }
            // pass 1: Ah*Bh
            #pragma unroll
            for (int i = 0; i < 2; i++) {
                int p = 2*pp + i;
                #pragma unroll
                for (int mt = 0; mt < 2; mt++) {
                    mma_bf16(acc[mt][2*p],   ah[mt], bh4[i]);
                    mma_bf16(acc[mt][2*p+1], ah[mt], bh4[i]+2);
                }
            }
            // pass 2: Al*Bh
            #pragma unroll
            for (int i = 0; i < 2; i++) {
                int p = 2*pp + i;
                #pragma unroll
                for (int mt = 0; mt < 2; mt++) {
                    mma_bf16(acc[mt][2*p],   al[mt], bh4[i]);
                    mma_bf16(acc[mt][2*p+1], al[mt], bh4[i]+2);
                }
            }
            // pass 3: Ah*Bl
            #pragma unroll
            for (int i = 0; i < 2; i++) {
                int p = 2*pp + i;
                #pragma unroll
                for (int mt = 0; mt < 2; mt++) {
                    mma_bf16(acc[mt][2*p],   ah[mt], bl4[i]);
                    mma_bf16(acc[mt][2*p+1], ah[mt], bl4[i]+2);
                }
            }
        }
        if (kc + 3 < NKCH) load_stage((kc + 3) & 3, kc + 3);
    }

    // ---- epilogue ----
    const int row_base = bm*128 + wm*32;
    const int col_base = bn*128 + wn*64;
    #pragma unroll
    for (int mt = 0; mt < 2; mt++) {
        #pragma unroll
        for (int rg = 0; rg < 2; rg++) {
            int row = row_base + mt*16 + rg*8 + (lane >> 2);
            int s = row & (SEQ-1);
            int b = row >> 11;
            #pragma unroll
            for (int nt = 0; nt < 8; nt++) {
                int col = col_base + nt*8 + 2*(lane & 3);
                float e = acc[mt][nt][rg*2];
                float o = acc[mt][nt][rg*2+1];
                if (MODE == 3 && do_rope) {
                    int ip = (col & 63) >> 1;
                    float cs = ropec[s*32 + ip];
                    float sn = ropes[s*32 + ip];
                    float ne = e*cs - o*sn;
                    float no = e*sn + o*cs;
                    e = ne; o = no;
                }
                if (MODE == 0) {
                    *(float2*)(C + (size_t)row*DMODEL + col) = make_float2(e, o);
                } else {
                    int h = col >> 6, dk = col & 63;
                    size_t idx = ((size_t)(b*NHEADS + h)*SEQ + s)*DKH + dk;
                    uint32_t hi, lo;
                    split2(e, o, hi, lo);
                    *(uint32_t*)(Chi + idx) = hi;
                    *(uint32_t*)(Clo + idx) = lo;
                }
            }
        }
    }
}

// ---------------- mma.sync flash attention, double-buffered K/V, pass-major MMA ----------------
#define A_STR 72
#define A_SQL 9216
#define A_SST 18432
#define A_BUF 4608                 // 64*72
#define A_STG (4*A_BUF)            // 18432
#define ATTN_SMEM_BYTES ((A_SST + 2*A_STG)*2)   // 110592

__global__ __launch_bounds__(256, 2)
void attn_mma(const __nv_bfloat16* __restrict__ Qh_g, const __nv_bfloat16* __restrict__ Ql_g,
              const __nv_bfloat16* __restrict__ Kh_g, const __nv_bfloat16* __restrict__ Kl_g,
              const __nv_bfloat16* __restrict__ Vh_g, const __nv_bfloat16* __restrict__ Vl_g,
              __nv_bfloat16* __restrict__ Ohi, __nv_bfloat16* __restrict__ Olo)
{
    extern __shared__ __nv_bfloat16 smb[];
    const uint32_t sb = smem_u32(smb);
    const int tid  = threadIdx.x;
    const int wq   = tid >> 5;
    const int lane = tid & 31;
    const int bh   = blockIdx.y;
    const int qt   = gridDim.x - 1 - blockIdx.x;
    const int q0   = qt * 128;
    const size_t boff = (size_t)bh*SEQ*DKH;

    // ---- Q (hi+lo) ----
    #pragma unroll
    for (int l = 0; l < 4; l++) {
        int item = tid + l*256;
        int r = item >> 3;
        int c = item & 7;
        uint32_t d = sb + (uint32_t)(r*A_STR + c*8)*2;
        const __nv_bfloat16* src = Qh_g + boff + (size_t)(q0+r)*DKH + c*8;
        cp16(d, src);
        cp16(d + A_SQL*2, Ql_g + (src - Qh_g));
    }
    CP_COMMIT();

    const int bsel = tid >> 6;
    const int loc  = tid & 63;
    const int vc   = loc & 7;
    const int vr   = loc >> 3;
    const __nv_bfloat16* Pk =
        (bsel == 0) ? Kh_g : (bsel == 1) ? Kl_g : (bsel == 2) ? Vh_g : Vl_g;
    const __nv_bfloat16* Pkv = Pk + boff + (size_t)vr*DKH + vc*8;
    const uint32_t dkv = sb + (uint32_t)((A_SST + bsel*A_BUF + vr*A_STR + vc*8)*2);

    auto load_kv = [&](int stg, int t) {
        const __nv_bfloat16* s = Pkv + (size_t)(t*64)*DKH;
        const uint32_t d = dkv + stg*(A_STG*2);
        #pragma unroll
        for (int i = 0; i < 8; i++)
            cp16(d + i*(8*A_STR*2), s + (size_t)(i*8)*DKH);
        CP_COMMIT();
    };

    load_kv(0, 0);

    float sc[8][4];
    float o[8][4];
    #pragma unroll
    for (int nt = 0; nt < 8; nt++)
        #pragma unroll
        for (int j = 0; j < 4; j++) o[nt][j] = 0.f;
    float m0 = -INFINITY, m1 = -INFINITY, l0 = 0.f, l1 = 0.f;

    const int nkt = qt*2 + 2;

    for (int t = 0; t < nkt; t++) {
        const int k0 = t * 64;
        if (t + 1 < nkt) { load_kv((t+1) & 1, t+1); cp_wait<1>(); }
        else             { cp_wait<0>(); }
        __syncthreads();
        const uint32_t stb = sb + (uint32_t)((A_SST + (t & 1)*A_STG)*2);

        const bool active = (k0 <= q0 + wq*16 + 15);
        if (active) {
            // ---- S = Q K^T, pass-major within p-pairs ----
            #pragma unroll
            for (int nt = 0; nt < 8; nt++)
                #pragma unroll
                for (int j = 0; j < 4; j++) sc[nt][j] = 0.f;
            #pragma unroll
            for (int kt = 0; kt < 4; kt++) {
                uint32_t ah[4], al[4];
                uint32_t aaddr = sb + (uint32_t)(((wq*16 + (lane & 15))*A_STR + kt*16 + (lane >> 4)*8)*2);
                ldsm_x4(ah[0], ah[1], ah[2], ah[3], aaddr);
                ldsm_x4(al[0], al[1], al[2], al[3], aaddr + A_SQL*2);
                #pragma unroll
                for (int pp = 0; pp < 2; pp++) {
                    uint32_t kh4[2][4], kl4[2][4];
                    #pragma unroll
                    for (int i = 0; i < 2; i++) {
                        int p = 2*pp + i;
                        int brow = p*16 + (lane & 7) + ((lane >> 4) << 3);
                        uint32_t baddr = stb + (uint32_t)((brow*A_STR + kt*16 + ((lane >> 3) & 1)*8)*2);
                        ldsm_x4(kh4[i][0], kh4[i][1], kh4[i][2], kh4[i][3], baddr);
                        ldsm_x4(kl4[i][0], kl4[i][1], kl4[i][2], kl4[i][3], baddr + A_BUF*2);
                    }
                    #pragma unroll
                    for (int i = 0; i < 2; i++) {
                        int p = 2*pp + i;
                        mma_bf16(sc[2*p],   ah, kh4[i]);
                        mma_bf16(sc[2*p+1], ah, kh4[i]+2);
                    }
                    #pragma unroll
                    for (int i = 0; i < 2; i++) {
                        int p = 2*pp + i;
                        mma_bf16(sc[2*p],   al, kh4[i]);
                        mma_bf16(sc[2*p+1], al, kh4[i]+2);
                    }
                    #pragma unroll
                    for (int i = 0; i < 2; i++) {
                        int p = 2*pp + i;
                        mma_bf16(sc[2*p],   ah, kl4[i]);
                        mma_bf16(sc[2*p+1], ah, kl4[i]+2);
                    }
                }
            }

            // ---- softmax (online) ----
            const int qrow = q0 + wq*16 + (lane >> 2);
            const bool needmask = (k0 + 63 > q0 + wq*16);
            float mx0 = -1e30f, mx1 = -1e30f;
            #pragma unroll
            for (int nt = 0; nt < 8; nt++) {
                #pragma unroll
                for (int j = 0; j < 4; j++) sc[nt][j] *= 0.125f;
                if (needmask) {
                    int kcol = k0 + nt*8 + 2*(lane & 3);
                    if (kcol+0 > qrow)   sc[nt][0] = -1e30f;
                    if (kcol+1 > qrow)   sc[nt][1] = -1e30f;
                    if (kcol+0 > qrow+8) sc[nt][2] = -1e30f;
                    if (kcol+1 > qrow+8) sc[nt][3] = -1e30f;
                }
                mx0 = fmaxf(mx0, fmaxf(sc[nt][0], sc[nt][1]));
                mx1 = fmaxf(mx1, fmaxf(sc[nt][2], sc[nt][3]));
            }
            mx0 = fmaxf(mx0, __shfl_xor_sync(0xffffffffu, mx0, 1));
            mx0 = fmaxf(mx0, __shfl_xor_sync(0xffffffffu, mx0, 2));
            mx1 = fmaxf(mx1, __shfl_xor_sync(0xffffffffu, mx1, 1));
            mx1 = fmaxf(mx1, __shfl_xor_sync(0xffffffffu, mx1, 2));
            float mn0 = fmaxf(m0, mx0), mn1 = fmaxf(m1, mx1);
            float f0 = __expf(m0 - mn0), f1 = __expf(m1 - mn1);
            m0 = mn0; m1 = mn1;
            float sum0 = 0.f, sum1 = 0.f;
            #pragma unroll
            for (int nt = 0; nt < 8; nt++) {
                sc[nt][0] = __expf(sc[nt][0] - mn0);
                sc[nt][1] = __expf(sc[nt][1] - mn0);
                sc[nt][2] = __expf(sc[nt][2] - mn1);
                sc[nt][3] = __expf(sc[nt][3] - mn1);
                sum0 += sc[nt][0] + sc[nt][1];
                sum1 += sc[nt][2] + sc[nt][3];
            }
            sum0 += __shfl_xor_sync(0xffffffffu, sum0, 1);
            sum0 += __shfl_xor_sync(0xffffffffu, sum0, 2);
            sum1 += __shfl_xor_sync(0xffffffffu, sum1, 1);
            sum1 += __shfl_xor_sync(0xffffffffu, sum1, 2);
            l0 = l0*f0 + sum0;
            l1 = l1*f1 + sum1;
            #pragma unroll
            for (int nt = 0; nt < 8; nt++) {
                o[nt][0] *= f0; o[nt][1] *= f0;
                o[nt][2] *= f1; o[nt][3] *= f1;
            }

            // ---- O += P V, pass-major within dp-pairs ----
            #pragma unroll
            for (int kt = 0; kt < 4; kt++) {
                uint32_t ph[4], pl[4];
                split2(sc[2*kt][0],   sc[2*kt][1],   ph[0], pl[0]);
                split2(sc[2*kt][2],   sc[2*kt][3],   ph[1], pl[1]);
                split2(sc[2*kt+1][0], sc[2*kt+1][1], ph[2], pl[2]);
                split2(sc[2*kt+1][2], sc[2*kt+1][3], ph[3], pl[3]);
                #pragma unroll
                for (int pp = 0; pp < 2; pp++) {
                    uint32_t vh4[2][4], vl4[2][4];
                    #pragma unroll
                    for (int i = 0; i < 2; i++) {
                        int dp = 2*pp + i;
                        uint32_t vaddr = stb + (uint32_t)((2*A_BUF +
                                         (kt*16 + (lane & 15))*A_STR +
                                         dp*16 + ((lane >> 4) & 1)*8)*2);
                        ldsm_x4t(vh4[i][0], vh4[i][1], vh4[i][2], vh4[i][3], vaddr);
                        ldsm_x4t(vl4[i][0], vl4[i][1], vl4[i][2], vl4[i][3], vaddr + A_BUF*2);
                    }
                    #pragma unroll
                    for (int i = 0; i < 2; i++) {
                        int dp = 2*pp + i;
                        mma_bf16(o[2*dp],   ph, vh4[i]);
                        mma_bf16(o[2*dp+1], ph, vh4[i]+2);
                    }
                    #pragma unroll
                    for (int i = 0; i < 2; i++) {
                        int dp = 2*pp + i;
                        mma_bf16(o[2*dp],   pl, vh4[i]);
                        mma_bf16(o[2*dp+1], pl, vh4[i]+2);
                    }
                    #pragma unroll
                    for (int i = 0; i < 2; i++) {
                        int dp = 2*pp + i;
                        mma_bf16(o[2*dp],   ph, vl4[i]);
                        mma_bf16(o[2*dp+1], ph, vl4[i]+2);
                    }
                }
            }
        }
        __syncthreads();   // protect stage (t+1)&1 before next iteration's load
    }

    // ---- epilogue ----
    const int b = bh >> 4, h = bh & 15;
    const float i0 = 1.f / l0, i1 = 1.f / l1;
    const int srow = q0 + wq*16 + (lane >> 2);
    const size_t base0 = ((size_t)(b*SEQ + srow))*DMODEL + h*64;
    const size_t base1 = base0 + (size_t)8*DMODEL;
    #pragma unroll
    for (int nt = 0; nt < 8; nt++) {
        int col = nt*8 + 2*(lane & 3);
        uint32_t hi, lo;
        split2(o[nt][0]*i0, o[nt][1]*i0, hi, lo);
        *(uint32_t*)(Ohi + base0 + col) = hi;
        *(uint32_t*)(Olo + base0 + col) = lo;
        split2(o[nt][2]*i1, o[nt][3]*i1, hi, lo);
        *(uint32_t*)(Ohi + base1 + col) = hi;
        *(uint32_t*)(Olo + base1 + col) = lo;
    }
}

// ---------------- launch ----------------
extern "C" void kernel_launch(void* const* d_in, const int* in_sizes, int n_in,
                              void* d_out, int out_size)
{
    const float* x  = (const float*)d_in[0];
    const float* wq = (const float*)d_in[1];
    const float* wk = (const float*)d_in[2];
    const float* wv = (const float*)d_in[3];
    const float* wo = (const float*)d_in[4];
    const int*  pos = (const int*)d_in[5];
    float* out = (float*)d_out;

    float *rc, *rs;
    __nv_bfloat16 *xhi, *xlo, *whi, *wlo, *aohi, *aolo;
    __nv_bfloat16 *qhi, *qlo, *khi, *klo, *vhi, *vlo;
    cudaGetSymbolAddress((void**)&rc,   g_ropec);
    cudaGetSymbolAddress((void**)&rs,   g_ropes);
    cudaGetSymbolAddress((void**)&xhi,  g_xhi);
    cudaGetSymbolAddress((void**)&xlo,  g_xlo);
    cudaGetSymbolAddress((void**)&whi,  g_whi);
    cudaGetSymbolAddress((void**)&wlo,  g_wlo);
    cudaGetSymbolAddress((void**)&aohi, g_aohi);
    cudaGetSymbolAddress((void**)&aolo, g_aolo);
    cudaGetSymbolAddress((void**)&qhi,  g_qhi);
    cudaGetSymbolAddress((void**)&qlo,  g_qlo);
    cudaGetSymbolAddress((void**)&khi,  g_khi);
    cudaGetSymbolAddress((void**)&klo,  g_klo);
    cudaGetSymbolAddress((void**)&vhi,  g_vhi);
    cudaGetSymbolAddress((void**)&vlo,  g_vlo);

    static bool attr_done = false;
    if (!attr_done) {
        cudaFuncSetAttribute(gemm_mma<0>, cudaFuncAttributeMaxDynamicSharedMemorySize, GEMM_SMEM);
        cudaFuncSetAttribute(gemm_mma<3>, cudaFuncAttributeMaxDynamicSharedMemorySize, GEMM_SMEM);
        cudaFuncSetAttribute(attn_mma, cudaFuncAttributeMaxDynamicSharedMemorySize, ATTN_SMEM_BYTES);
        attr_done = true;
    }

    rope_table_kernel<<<(SEQ*32)/256, 256>>>(pos, rc, rs);
    {
        dim3 gc(1024, 8);   // 8 uniform segments of 262144 float4
        convall_kernel<<<gc, 256>>>(x, wq, wk, wv, wo, xhi, xlo, whi, wlo);
    }

    const size_t WN = (size_t)DMODEL*DMODEL;

    dim3 gqkv(DMODEL/128, M_TOT/128, 3);   // (8, 32, 3)
    gemm_mma<3><<<gqkv, 256, GEMM_SMEM>>>(xhi, xlo, whi, wlo,
                                          nullptr, qhi, qlo, khi, klo, vhi, vlo, rc, rs);

    dim3 ga(SEQ/128, BATCH*NHEADS);   // (16, 32)
    attn_mma<<<ga, 256, ATTN_SMEM_BYTES>>>(qhi, qlo, khi, klo, vhi, vlo, aohi, aolo);

    dim3 gg(DMODEL/128, M_TOT/128);   // (8, 32)
    gemm_mma<0><<<gg, 256, GEMM_SMEM>>>(aohi, aolo, whi + 3*WN, wlo + 3*WN,
                                        out, nullptr, nullptr, nullptr, nullptr,
                                        nullptr, nullptr, rc, rs);
}

// round 10
// speedup vs baseline: 3.1611x; 1.1124x over previous
#include <cuda_runtime.h>
#include <cuda_bf16.h>
#include <cuda_fp16.h>
#include <math.h>
#include <cstdint>

#define BATCH   2
#define SEQ     2048
#define DMODEL  1024
#define NHEADS  16
#define DKH     64
#define M_TOT   (BATCH*SEQ)   // 4096
#define QKV_ELEMS (BATCH*NHEADS*SEQ*DKH)

// ---------------- scratch (static device globals; no allocs) ----------------
__device__ __align__(256) __nv_bfloat16 g_xhi[M_TOT*DMODEL];
__device__ __align__(256) __nv_bfloat16 g_xlo[M_TOT*DMODEL];
__device__ __align__(256) __nv_bfloat16 g_whi[4*DMODEL*DMODEL];
__device__ __align__(256) __nv_bfloat16 g_wlo[4*DMODEL*DMODEL];
__device__ __align__(256) __nv_bfloat16 g_qhi[QKV_ELEMS];
__device__ __align__(256) __nv_bfloat16 g_qlo[QKV_ELEMS];
__device__ __align__(256) __nv_bfloat16 g_khi[QKV_ELEMS];
__device__ __align__(256) __nv_bfloat16 g_klo[QKV_ELEMS];
__device__ __align__(256) __half       g_vh [QKV_ELEMS];   // V single fp16
__device__ __align__(256) __nv_bfloat16 g_aohi[M_TOT*DMODEL];
__device__ __align__(256) __nv_bfloat16 g_aolo[M_TOT*DMODEL];
__device__ float g_ropec[SEQ*32];   // [s][ip]
__device__ float g_ropes[SEQ*32];

// ---------------- PTX helpers ----------------
__device__ __forceinline__ uint32_t smem_u32(const void* p) {
    uint32_t a;
    asm("{ .reg .u64 t; cvta.to.shared.u64 t, %1; cvt.u32.u64 %0, t; }" : "=r"(a) : "l"(p));
    return a;
}
__device__ __forceinline__ void cp16(uint32_t dst, const void* src) {
    asm volatile("cp.async.cg.shared.global [%0], [%1], 16;" :: "r"(dst), "l"(src) : "memory");
}
#define CP_COMMIT() asm volatile("cp.async.commit_group;" ::: "memory")
template<int N>
__device__ __forceinline__ void cp_wait() {
    asm volatile("cp.async.wait_group %0;" :: "n"(N) : "memory");
}
__device__ __forceinline__ void ldsm_x4(uint32_t& r0, uint32_t& r1, uint32_t& r2,
                                        uint32_t& r3, uint32_t addr) {
    asm volatile("ldmatrix.sync.aligned.m8n8.x4.shared.b16 {%0,%1,%2,%3}, [%4];"
                 : "=r"(r0), "=r"(r1), "=r"(r2), "=r"(r3) : "r"(addr));
}
__device__ __forceinline__ void ldsm_x4t(uint32_t& r0, uint32_t& r1, uint32_t& r2,
                                         uint32_t& r3, uint32_t addr) {
    asm volatile("ldmatrix.sync.aligned.m8n8.x4.trans.shared.b16 {%0,%1,%2,%3}, [%4];"
                 : "=r"(r0), "=r"(r1), "=r"(r2), "=r"(r3) : "r"(addr));
}
__device__ __forceinline__ void mma_bf16(float* c, const uint32_t* a, const uint32_t* b) {
    asm volatile("mma.sync.aligned.m16n8k16.row.col.f32.bf16.bf16.f32 "
                 "{%0,%1,%2,%3}, {%4,%5,%6,%7}, {%8,%9}, {%0,%1,%2,%3};"
                 : "+f"(c[0]), "+f"(c[1]), "+f"(c[2]), "+f"(c[3])
                 : "r"(a[0]), "r"(a[1]), "r"(a[2]), "r"(a[3]), "r"(b[0]), "r"(b[1]));
}
__device__ __forceinline__ void mma_f16(float* c, const uint32_t* a, const uint32_t* b) {
    asm volatile("mma.sync.aligned.m16n8k16.row.col.f32.f16.f16.f32 "
                 "{%0,%1,%2,%3}, {%4,%5,%6,%7}, {%8,%9}, {%0,%1,%2,%3};"
                 : "+f"(c[0]), "+f"(c[1]), "+f"(c[2]), "+f"(c[3])
                 : "r"(a[0]), "r"(a[1]), "r"(a[2]), "r"(a[3]), "r"(b[0]), "r"(b[1]));
}
// split pair of floats into packed bf16x2 hi + lo residual
__device__ __forceinline__ void split2(float a, float b, uint32_t& hi, uint32_t& lo) {
    __nv_bfloat162 h = __floats2bfloat162_rn(a, b);
    float ha = __low2float(h), hb = __high2float(h);
    __nv_bfloat162 l = __floats2bfloat162_rn(a - ha, b - hb);
    hi = *(uint32_t*)&h;
    lo = *(uint32_t*)&l;
}
__device__ __forceinline__ uint32_t pack_h2(float a, float b) {
    __half2 h = __floats2half2_rn(a, b);
    return *(uint32_t*)&h;
}

// ---------------- fused prep: x (4 quarters) + 4 weights ----------------
__global__ void convall_kernel(const float* __restrict__ x,
                               const float* __restrict__ w0, const float* __restrict__ w1,
                               const float* __restrict__ w2, const float* __restrict__ w3,
                               __nv_bfloat16* __restrict__ xhi, __nv_bfloat16* __restrict__ xlo,
                               __nv_bfloat16* __restrict__ whi, __nv_bfloat16* __restrict__ wlo)
{
    const int y = blockIdx.y;
    const float* src;
    __nv_bfloat16 *hi, *lo;
    size_t off;
    if (y < 4) {
        src = x + (size_t)y * (M_TOT*DMODEL/4);
        off = (size_t)y * (M_TOT*DMODEL/4);
        hi = xhi; lo = xlo;
    } else {
        const float* ws[4] = {w0, w1, w2, w3};
        src = ws[y-4];
        off = (size_t)(y-4) * DMODEL * DMODEL;
        hi = whi; lo = wlo;
    }
    int i = blockIdx.x * blockDim.x + threadIdx.x;
    float4 v = *(const float4*)(src + (size_t)i*4);
    uint32_t h0, l0, h1, l1;
    split2(v.x, v.y, h0, l0);
    split2(v.z, v.w, h1, l1);
    *(uint32_t*)(hi + off + (size_t)i*4)     = h0;
    *(uint32_t*)(hi + off + (size_t)i*4 + 2) = h1;
    *(uint32_t*)(lo + off + (size_t)i*4)     = l0;
    *(uint32_t*)(lo + off + (size_t)i*4 + 2) = l1;
}

__global__ void rope_table_kernel(const int* __restrict__ pos,
                                  float* __restrict__ cosT, float* __restrict__ sinT)
{
    int idx = blockIdx.x * blockDim.x + threadIdx.x;
    int s  = idx >> 5;
    int ip = idx & 31;
    double invf = exp2(-(double)ip * 0.41524101186092028);  // log2(10000)/32
    float ang = (float)pos[s] * (float)invf;
    float sn, cs;
    sincosf(ang, &sn, &cs);
    cosT[idx] = cs;
    sinT[idx] = sn;
}

// ---------------- mma.sync GEMM, 4-stage cp.async pipeline, KC=16, pass-major ----------------
// MODE 0: row-major fp32 C; MODE 3: fused QKV (z=0 Q+RoPE, z=1 K+RoPE, z=2 V->fp16)
#define NKCH (DMODEL/16)          // 64
#define GROW 24
#define G_TILE_BYTES (128*GROW*2) // 6144
#define G_STAGE_BYTES (4*G_TILE_BYTES)
#define GEMM_SMEM (4*G_STAGE_BYTES)     // 98304

template<int MODE>
__global__ __launch_bounds__(256, 2)
void gemm_mma(const __nv_bfloat16* __restrict__ Ahi, const __nv_bfloat16* __restrict__ Alo,
              const __nv_bfloat16* __restrict__ Bhi_, const __nv_bfloat16* __restrict__ Blo_,
              float* __restrict__ C,
              __nv_bfloat16* __restrict__ Chi_, __nv_bfloat16* __restrict__ Clo_,
              __nv_bfloat16* __restrict__ Chi1, __nv_bfloat16* __restrict__ Clo1,
              __half* __restrict__ Vout,
              const float* __restrict__ ropec, const float* __restrict__ ropes)
{
    extern __shared__ __nv_bfloat16 smb[];
    const uint32_t sbase = smem_u32(smb);
    const int tid  = threadIdx.x;
    const int wid  = tid >> 5;
    const int lane = tid & 31;
    const int bm = blockIdx.y, bn = blockIdx.x;
    const int wm = wid & 3;
    const int wn = wid >> 2;

    const __nv_bfloat16* Bhi = Bhi_;
    const __nv_bfloat16* Blo = Blo_;
    __nv_bfloat16* Chi = Chi_;
    __nv_bfloat16* Clo = Clo_;
    bool do_rope = false;
    bool v_out = false;
    if (MODE == 3) {
        const int z = blockIdx.z;
        const size_t woff = (size_t)z * DMODEL * DMODEL;
        Bhi = Bhi_ + woff; Blo = Blo_ + woff;
        if (z == 1)      { Chi = Chi1; Clo = Clo1; }
        else if (z == 2) { v_out = true; }
        do_rope = (z < 2);
    }

    float acc[2][8][4];
    #pragma unroll
    for (int mt = 0; mt < 2; mt++)
        #pragma unroll
        for (int nt = 0; nt < 8; nt++)
            #pragma unroll
            for (int j = 0; j < 4; j++) acc[mt][nt][j] = 0.f;

    const __nv_bfloat16* Ah = Ahi + (size_t)(bm*128)*DMODEL;
    const __nv_bfloat16* Al = Alo + (size_t)(bm*128)*DMODEL;
    const __nv_bfloat16* Bh = Bhi + (size_t)(bn*128)*DMODEL;
    const __nv_bfloat16* Bl = Blo + (size_t)(bn*128)*DMODEL;

    const int bsel = tid & 3;
    const int lc   = (tid >> 2) & 1;
    const int rb   = tid >> 3;
    const __nv_bfloat16* Pb =
        (bsel == 0) ? Ah : (bsel == 1) ? Al : (bsel == 2) ? Bh : Bl;
    const __nv_bfloat16* Psrc = Pb + (size_t)rb*DMODEL + lc*8;
    const uint32_t dbase = sbase + (uint32_t)(bsel*G_TILE_BYTES + rb*48 + lc*16);

    auto load_stage = [&](int stg, int kc) {
        const uint32_t d = dbase + stg*G_STAGE_BYTES;
        const __nv_bfloat16* s = Psrc + kc*16;
        #pragma unroll
        for (int i = 0; i < 4; i++)
            cp16(d + i*(32*48), s + (size_t)(i*32)*DMODEL);
        CP_COMMIT();
    };

    load_stage(0, 0);
    load_stage(1, 1);
    load_stage(2, 2);

    const int a_row   = wm*32 + (lane & 15);
    const int a_co    = (lane >> 4) * 8;
    const int b_row_p = wn*64 + (lane & 7) + ((lane >> 4) << 3);
    const int b_co    = ((lane >> 3) & 1) * 8;

    for (int kc = 0; kc < NKCH; kc++) {
        if (kc < NKCH-2)       cp_wait<2>();
        else if (kc == NKCH-2) cp_wait<1>();
        else                   cp_wait<0>();
        __syncthreads();
        const uint32_t sbk = sbase + (kc & 3)*G_STAGE_BYTES;

        uint32_t ah[2][4], al[2][4];
        #pragma unroll
        for (int mt = 0; mt < 2; mt++) {
            uint32_t aaddr = sbk + (uint32_t)(((a_row + mt*16)*GROW + a_co)*2);
            ldsm_x4(ah[mt][0], ah[mt][1], ah[mt][2], ah[mt][3], aaddr);
            ldsm_x4(al[mt][0], al[mt][1], al[mt][2], al[mt][3], aaddr + G_TILE_BYTES);
        }
        #pragma unroll
        for (int pp = 0; pp < 2; pp++) {
            uint32_t bh4[2][4], bl4[2][4];
            #pragma unroll
            for (int i = 0; i < 2; i++) {
                int p = 2*pp + i;
                uint32_t baddr = sbk + 2*G_TILE_BYTES +
                                 (uint32_t)(((b_row_p + p*16)*GROW + b_co)*2);
                ldsm_x4(bh4[i][0], bh4[i][1], bh4[i][2], bh4[i][3], baddr);
                ldsm_x4(bl4[i][0], bl4[i][1], bl4[i][2], bl4[i][3], baddr + G_TILE_BYTES);
            }
            #pragma unroll
            for (int i = 0; i < 2; i++) {
                int p = 2*pp + i;
                #pragma unroll
                for (int mt = 0; mt < 2; mt++) {
                    mma_bf16(acc[mt][2*p],   ah[mt], bh4[i]);
                    mma_bf16(acc[mt][2*p+1], ah[mt], bh4[i]+2);
                }
            }
            #pragma unroll
            for (int i = 0; i < 2; i++) {
                int p = 2*pp + i;
                #pragma unroll
                for (int mt = 0; mt < 2; mt++) {
                    mma_bf16(acc[mt][2*p],   al[mt], bh4[i]);
                    mma_bf16(acc[mt][2*p+1], al[mt], bh4[i]+2);
                }
            }
            #pragma unroll
            for (int i = 0; i < 2; i++) {
                int p = 2*pp + i;
                #pragma unroll
                for (int mt = 0; mt < 2; mt++) {
                    mma_bf16(acc[mt][2*p],   ah[mt], bl4[i]);
                    mma_bf16(acc[mt][2*p+1], ah[mt], bl4[i]+2);
                }
            }
        }
        if (kc + 3 < NKCH) load_stage((kc + 3) & 3, kc + 3);
    }

    // ---- epilogue ----
    const int row_base = bm*128 + wm*32;
    const int col_base = bn*128 + wn*64;
    #pragma unroll
    for (int mt = 0; mt < 2; mt++) {
        #pragma unroll
        for (int rg = 0; rg < 2; rg++) {
            int row = row_base + mt*16 + rg*8 + (lane >> 2);
            int s = row & (SEQ-1);
            int b = row >> 11;
            #pragma unroll
            for (int nt = 0; nt < 8; nt++) {
                int col = col_base + nt*8 + 2*(lane & 3);
                float e = acc[mt][nt][rg*2];
                float o = acc[mt][nt][rg*2+1];
                if (MODE == 3 && do_rope) {
                    int ip = (col & 63) >> 1;
                    float cs = ropec[s*32 + ip];
                    float sn = ropes[s*32 + ip];
                    float ne = e*cs - o*sn;
                    float no = e*sn + o*cs;
                    e = ne; o = no;
                }
                if (MODE == 0) {
                    *(float2*)(C + (size_t)row*DMODEL + col) = make_float2(e, o);
                } else {
                    int h = col >> 6, dk = col & 63;
                    size_t idx = ((size_t)(b*NHEADS + h)*SEQ + s)*DKH + dk;
                    if (v_out) {
                        *(uint32_t*)(Vout + idx) = pack_h2(e, o);
                    } else {
                        uint32_t hi, lo;
                        split2(e, o, hi, lo);
                        *(uint32_t*)(Chi + idx) = hi;
                        *(uint32_t*)(Clo + idx) = lo;
                    }
                }
            }
        }
    }
}

// ---------------- mma.sync flash attention: QK bf16x3, PV fp16 single-pass ----------------
// smem b16 units: Qhi[128][72] @0, Qlo @9216; 2 KV stages @18432: {Khi,Klo,Vf16} 64x72 each
#define A_STR 72
#define A_SQL 9216
#define A_SST 18432
#define A_BUF 4608                 // 64*72
#define A_STG (3*A_BUF)            // 13824
#define ATTN_SMEM_BYTES ((A_SST + 2*A_STG)*2)   // 92160
#define SCALE_LOG2 0.18033688011112042f         // 0.125 * log2(e)

__global__ __launch_bounds__(256, 2)
void attn_mma(const __nv_bfloat16* __restrict__ Qh_g, const __nv_bfloat16* __restrict__ Ql_g,
              const __nv_bfloat16* __restrict__ Kh_g, const __nv_bfloat16* __restrict__ Kl_g,
              const __half* __restrict__ Vh_g,
              __nv_bfloat16* __restrict__ Ohi, __nv_bfloat16* __restrict__ Olo)
{
    extern __shared__ __nv_bfloat16 smb[];
    const uint32_t sb = smem_u32(smb);
    const int tid  = threadIdx.x;
    const int wq   = tid >> 5;
    const int lane = tid & 31;
    const int bh   = blockIdx.y;
    const int qt   = gridDim.x - 1 - blockIdx.x;
    const int q0   = qt * 128;
    const size_t boff = (size_t)bh*SEQ*DKH;

    // ---- Q (hi+lo) ----
    #pragma unroll
    for (int l = 0; l < 4; l++) {
        int item = tid + l*256;
        int r = item >> 3;
        int c = item & 7;
        uint32_t d = sb + (uint32_t)(r*A_STR + c*8)*2;
        const __nv_bfloat16* src = Qh_g + boff + (size_t)(q0+r)*DKH + c*8;
        cp16(d, src);
        cp16(d + A_SQL*2, Ql_g + (src - Qh_g));
    }
    CP_COMMIT();

    // KV loader roles: bsel 0 -> Khi (8 cp16), 1 -> Klo (8), 2/3 -> V halves (4 each)
    const int bsel = tid >> 6;
    const int loc  = tid & 63;
    const int vc   = loc & 7;
    const int vr   = loc >> 3;
    const __nv_bfloat16* PkK = (bsel == 1) ? Kl_g : Kh_g;
    const int vg = bsel - 2;

    auto load_kv = [&](int stg, int t) {
        if (bsel < 2) {
            const __nv_bfloat16* s = PkK + boff + (size_t)(t*64 + vr)*DKH + vc*8;
            uint32_t d = sb + (uint32_t)((A_SST + stg*A_STG + bsel*A_BUF + vr*A_STR + vc*8)*2);
            #pragma unroll
            for (int i = 0; i < 8; i++)
                cp16(d + i*(8*A_STR*2), s + (size_t)(i*8)*DKH);
        } else {
            const __half* s = Vh_g + boff + (size_t)(t*64 + vr + 32*vg)*DKH + vc*8;
            uint32_t d = sb + (uint32_t)((A_SST + stg*A_STG + 2*A_BUF + (vr + 32*vg)*A_STR + vc*8)*2);
            #pragma unroll
            for (int i = 0; i < 4; i++)
                cp16(d + i*(8*A_STR*2), s + (size_t)(i*8)*DKH);
        }
        CP_COMMIT();
    };

    load_kv(0, 0);

    float sc[8][4];
    float o[8][4];
    #pragma unroll
    for (int nt = 0; nt < 8; nt++)
        #pragma unroll
        for (int j = 0; j < 4; j++) o[nt][j] = 0.f;
    float m0 = -INFINITY, m1 = -INFINITY, l0 = 0.f, l1 = 0.f;

    const int nkt = qt*2 + 2;

    for (int t = 0; t < nkt; t++) {
        const int k0 = t * 64;
        if (t + 1 < nkt) { load_kv((t+1) & 1, t+1); cp_wait<1>(); }
        else             { cp_wait<0>(); }
        __syncthreads();
        const uint32_t stb = sb + (uint32_t)((A_SST + (t & 1)*A_STG)*2);

        const bool active = (k0 <= q0 + wq*16 + 15);
        if (active) {
            // ---- S = Q K^T (bf16x3, pass-major) ----
            #pragma unroll
            for (int nt = 0; nt < 8; nt++)
                #pragma unroll
                for (int j = 0; j < 4; j++) sc[nt][j] = 0.f;
            #pragma unroll
            for (int kt = 0; kt < 4; kt++) {
                uint32_t ah[4], al[4];
                uint32_t aaddr = sb + (uint32_t)(((wq*16 + (lane & 15))*A_STR + kt*16 + (lane >> 4)*8)*2);
                ldsm_x4(ah[0], ah[1], ah[2], ah[3], aaddr);
                ldsm_x4(al[0], al[1], al[2], al[3], aaddr + A_SQL*2);
                #pragma unroll
                for (int pp = 0; pp < 2; pp++) {
                    uint32_t kh4[2][4], kl4[2][4];
                    #pragma unroll
                    for (int i = 0; i < 2; i++) {
                        int p = 2*pp + i;
                        int brow = p*16 + (lane & 7) + ((lane >> 4) << 3);
                        uint32_t baddr = stb + (uint32_t)((brow*A_STR + kt*16 + ((lane >> 3) & 1)*8)*2);
                        ldsm_x4(kh4[i][0], kh4[i][1], kh4[i][2], kh4[i][3], baddr);
                        ldsm_x4(kl4[i][0], kl4[i][1], kl4[i][2], kl4[i][3], baddr + A_BUF*2);
                    }
                    #pragma unroll
                    for (int i = 0; i < 2; i++) {
                        int p = 2*pp + i;
                        mma_bf16(sc[2*p],   ah, kh4[i]);
                        mma_bf16(sc[2*p+1], ah, kh4[i]+2);
                    }
                    #pragma unroll
                    for (int i = 0; i < 2; i++) {
                        int p = 2*pp + i;
                        mma_bf16(sc[2*p],   al, kh4[i]);
                        mma_bf16(sc[2*p+1], al, kh4[i]+2);
                    }
                    #pragma unroll
                    for (int i = 0; i < 2; i++) {
                        int p = 2*pp + i;
                        mma_bf16(sc[2*p],   ah, kl4[i]);
                        mma_bf16(sc[2*p+1], ah, kl4[i]+2);
                    }
                }
            }

            // ---- softmax (online, log2 domain) ----
            const int qrow = q0 + wq*16 + (lane >> 2);
            const bool needmask = (k0 + 63 > q0 + wq*16);
            float mx0 = -1e30f, mx1 = -1e30f;
            #pragma unroll
            for (int nt = 0; nt < 8; nt++) {
                #pragma unroll
                for (int j = 0; j < 4; j++) sc[nt][j] *= SCALE_LOG2;
                if (needmask) {
                    int kcol = k0 + nt*8 + 2*(lane & 3);
                    if (kcol+0 > qrow)   sc[nt][0] = -1e30f;
                    if (kcol+1 > qrow)   sc[nt][1] = -1e30f;
                    if (kcol+0 > qrow+8) sc[nt][2] = -1e30f;
                    if (kcol+1 > qrow+8) sc[nt][3] = -1e30f;
                }
                mx0 = fmaxf(mx0, fmaxf(sc[nt][0], sc[nt][1]));
                mx1 = fmaxf(mx1, fmaxf(sc[nt][2], sc[nt][3]));
            }
            mx0 = fmaxf(mx0, __shfl_xor_sync(0xffffffffu, mx0, 1));
            mx0 = fmaxf(mx0, __shfl_xor_sync(0xffffffffu, mx0, 2));
            mx1 = fmaxf(mx1, __shfl_xor_sync(0xffffffffu, mx1, 1));
            mx1 = fmaxf(mx1, __shfl_xor_sync(0xffffffffu, mx1, 2));
            float mn0 = fmaxf(m0, mx0), mn1 = fmaxf(m1, mx1);
            float f0 = exp2f(m0 - mn0), f1 = exp2f(m1 - mn1);
            m0 = mn0; m1 = mn1;
            float sum0 = 0.f, sum1 = 0.f;
            #pragma unroll
            for (int nt = 0; nt < 8; nt++) {
                sc[nt][0] = exp2f(sc[nt][0] - mn0);
                sc[nt][1] = exp2f(sc[nt][1] - mn0);
                sc[nt][2] = exp2f(sc[nt][2] - mn1);
                sc[nt][3] = exp2f(sc[nt][3] - mn1);
                sum0 += sc[nt][0] + sc[nt][1];
                sum1 += sc[nt][2] + sc[nt][3];
            }
            sum0 += __shfl_xor_sync(0xffffffffu, sum0, 1);
            sum0 += __shfl_xor_sync(0xffffffffu, sum0, 2);
            sum1 += __shfl_xor_sync(0xffffffffu, sum1, 1);
            sum1 += __shfl_xor_sync(0xffffffffu, sum1, 2);
            l0 = l0*f0 + sum0;
            l1 = l1*f1 + sum1;
            #pragma unroll
            for (int nt = 0; nt < 8; nt++) {
                o[nt][0] *= f0; o[nt][1] *= f0;
                o[nt][2] *= f1; o[nt][3] *= f1;
            }

            // ---- O += P V (single-pass fp16) ----
            #pragma unroll
            for (int kt = 0; kt < 4; kt++) {
                uint32_t pf[4];
                pf[0] = pack_h2(sc[2*kt][0],   sc[2*kt][1]);
                pf[1] = pack_h2(sc[2*kt][2],   sc[2*kt][3]);
                pf[2] = pack_h2(sc[2*kt+1][0], sc[2*kt+1][1]);
                pf[3] = pack_h2(sc[2*kt+1][2], sc[2*kt+1][3]);
                #pragma unroll
                for (int pp = 0; pp < 2; pp++) {
                    uint32_t vh4[2][4];
                    #pragma unroll
                    for (int i = 0; i < 2; i++) {
                        int dp = 2*pp + i;
                        uint32_t vaddr = stb + (uint32_t)((2*A_BUF +
                                         (kt*16 + (lane & 15))*A_STR +
                                         dp*16 + ((lane >> 4) & 1)*8)*2);
                        ldsm_x4t(vh4[i][0], vh4[i][1], vh4[i][2], vh4[i][3], vaddr);
                    }
                    #pragma unroll
                    for (int i = 0; i < 2; i++) {
                        int dp = 2*pp + i;
                        mma_f16(o[2*dp],   pf, vh4[i]);
                        mma_f16(o[2*dp+1], pf, vh4[i]+2);
                    }
                }
            }
        }
        __syncthreads();   // protect stage (t+1)&1 before next iteration's load
    }

    // ---- epilogue ----
    const int b = bh >> 4, h = bh & 15;
    const float i0 = 1.f / l0, i1 = 1.f / l1;
    const int srow = q0 + wq*16 + (lane >> 2);
    const size_t base0 = ((size_t)(b*SEQ + srow))*DMODEL + h*64;
    const size_t base1 = base0 + (size_t)8*DMODEL;
    #pragma unroll
    for (int nt = 0; nt < 8; nt++) {
        int col = nt*8 + 2*(lane & 3);
        uint32_t hi, lo;
        split2(o[nt][0]*i0, o[nt][1]*i0, hi, lo);
        *(uint32_t*)(Ohi + base0 + col) = hi;
        *(uint32_t*)(Olo + base0 + col) = lo;
        split2(o[nt][2]*i1, o[nt][3]*i1, hi, lo);
        *(uint32_t*)(Ohi + base1 + col) = hi;
        *(uint32_t*)(Olo + base1 + col) = lo;
    }
}

// ---------------- launch ----------------
extern "C" void kernel_launch(void* const* d_in, const int* in_sizes, int n_in,
                              void* d_out, int out_size)
{
    const float* x  = (const float*)d_in[0];
    const float* wq = (const float*)d_in[1];
    const float* wk = (const float*)d_in[2];
    const float* wv = (const float*)d_in[3];
    const float* wo = (const float*)d_in[4];
    const int*  pos = (const int*)d_in[5];
    float* out = (float*)d_out;

    float *rc, *rs;
    __nv_bfloat16 *xhi, *xlo, *whi, *wlo, *aohi, *aolo;
    __nv_bfloat16 *qhi, *qlo, *khi, *klo;
    __half *vh;
    cudaGetSymbolAddress((void**)&rc,   g_ropec);
    cudaGetSymbolAddress((void**)&rs,   g_ropes);
    cudaGetSymbolAddress((void**)&xhi,  g_xhi);
    cudaGetSymbolAddress((void**)&xlo,  g_xlo);
    cudaGetSymbolAddress((void**)&whi,  g_whi);
    cudaGetSymbolAddress((void**)&wlo,  g_wlo);
    cudaGetSymbolAddress((void**)&aohi, g_aohi);
    cudaGetSymbolAddress((void**)&aolo, g_aolo);
    cudaGetSymbolAddress((void**)&qhi,  g_qhi);
    cudaGetSymbolAddress((void**)&qlo,  g_qlo);
    cudaGetSymbolAddress((void**)&khi,  g_khi);
    cudaGetSymbolAddress((void**)&klo,  g_klo);
    cudaGetSymbolAddress((void**)&vh,   g_vh);

    static bool attr_done = false;
    if (!attr_done) {
        cudaFuncSetAttribute(gemm_mma<0>, cudaFuncAttributeMaxDynamicSharedMemorySize, GEMM_SMEM);
        cudaFuncSetAttribute(gemm_mma<3>, cudaFuncAttributeMaxDynamicSharedMemorySize, GEMM_SMEM);
        cudaFuncSetAttribute(attn_mma, cudaFuncAttributeMaxDynamicSharedMemorySize, ATTN_SMEM_BYTES);
        attr_done = true;
    }

    rope_table_kernel<<<(SEQ*32)/256, 256>>>(pos, rc, rs);
    {
        dim3 gc(1024, 8);
        convall_kernel<<<gc, 256>>>(x, wq, wk, wv, wo, xhi, xlo, whi, wlo);
    }

    const size_t WN = (size_t)DMODEL*DMODEL;

    dim3 gqkv(DMODEL/128, M_TOT/128, 3);
    gemm_mma<3><<<gqkv, 256, GEMM_SMEM>>>(xhi, xlo, whi, wlo,
                                          nullptr, qhi, qlo, khi, klo, vh, rc, rs);

    dim3 ga(SEQ/128, BATCH*NHEADS);
    attn_mma<<<ga, 256, ATTN_SMEM_BYTES>>>(qhi, qlo, khi, klo, vh, aohi, aolo);

    dim3 gg(DMODEL/128, M_TOT/128);
    gemm_mma<0><<<gg, 256, GEMM_SMEM>>>(aohi, aolo, whi + 3*WN, wlo + 3*WN,
                                        out, nullptr, nullptr, nullptr, nullptr,
                                        nullptr, rc, rs);
}

// round 11
// speedup vs baseline: 4.2799x; 1.3539x over previous
#include <cuda_runtime.h>
#include <cuda_fp16.h>
#include <math.h>
#include <cstdint>

#define BATCH   2
#define SEQ     2048
#define DMODEL  1024
#define NHEADS  16
#define DKH     64
#define M_TOT   (BATCH*SEQ)   // 4096
#define QKV_ELEMS (BATCH*NHEADS*SEQ*DKH)

// ---------------- scratch (static device globals; no allocs) ----------------
__device__ __align__(256) __half g_xh[M_TOT*DMODEL];
__device__ __align__(256) __half g_xl[M_TOT*DMODEL];
__device__ __align__(256) __half g_wh[4*DMODEL*DMODEL];   // weights single fp16
__device__ __align__(256) __half g_qh[QKV_ELEMS];
__device__ __align__(256) __half g_ql[QKV_ELEMS];
__device__ __align__(256) __half g_kh[QKV_ELEMS];         // K single fp16
__device__ __align__(256) __half g_vh[QKV_ELEMS];         // V single fp16
__device__ __align__(256) __half g_aoh[M_TOT*DMODEL];
__device__ __align__(256) __half g_aol[M_TOT*DMODEL];
__device__ float g_ropec[SEQ*32];   // [s][ip]
__device__ float g_ropes[SEQ*32];

// ---------------- PTX helpers ----------------
__device__ __forceinline__ uint32_t smem_u32(const void* p) {
    uint32_t a;
    asm("{ .reg .u64 t; cvta.to.shared.u64 t, %1; cvt.u32.u64 %0, t; }" : "=r"(a) : "l"(p));
    return a;
}
__device__ __forceinline__ void cp16(uint32_t dst, const void* src) {
    asm volatile("cp.async.cg.shared.global [%0], [%1], 16;" :: "r"(dst), "l"(src) : "memory");
}
#define CP_COMMIT() asm volatile("cp.async.commit_group;" ::: "memory")
template<int N>
__device__ __forceinline__ void cp_wait() {
    asm volatile("cp.async.wait_group %0;" :: "n"(N) : "memory");
}
__device__ __forceinline__ void ldsm_x4(uint32_t& r0, uint32_t& r1, uint32_t& r2,
                                        uint32_t& r3, uint32_t addr) {
    asm volatile("ldmatrix.sync.aligned.m8n8.x4.shared.b16 {%0,%1,%2,%3}, [%4];"
                 : "=r"(r0), "=r"(r1), "=r"(r2), "=r"(r3) : "r"(addr));
}
__device__ __forceinline__ void ldsm_x4t(uint32_t& r0, uint32_t& r1, uint32_t& r2,
                                         uint32_t& r3, uint32_t addr) {
    asm volatile("ldmatrix.sync.aligned.m8n8.x4.trans.shared.b16 {%0,%1,%2,%3}, [%4];"
                 : "=r"(r0), "=r"(r1), "=r"(r2), "=r"(r3) : "r"(addr));
}
__device__ __forceinline__ void mma_f16(float* c, const uint32_t* a, const uint32_t* b) {
    asm volatile("mma.sync.aligned.m16n8k16.row.col.f32.f16.f16.f32 "
                 "{%0,%1,%2,%3}, {%4,%5,%6,%7}, {%8,%9}, {%0,%1,%2,%3};"
                 : "+f"(c[0]), "+f"(c[1]), "+f"(c[2]), "+f"(c[3])
                 : "r"(a[0]), "r"(a[1]), "r"(a[2]), "r"(a[3]), "r"(b[0]), "r"(b[1]));
}
__device__ __forceinline__ uint32_t pack_h2(float a, float b) {
    __half2 h = __floats2half2_rn(a, b);
    return *(uint32_t*)&h;
}
// split pair of floats into packed fp16x2 hi + lo residual (~22-bit effective)
__device__ __forceinline__ void split2h(float a, float b, uint32_t& hi, uint32_t& lo) {
    __half2 h = __floats2half2_rn(a, b);
    float ha = __low2float(h), hb = __high2float(h);
    __half2 l = __floats2half2_rn(a - ha, b - hb);
    hi = *(uint32_t*)&h;
    lo = *(uint32_t*)&l;
}

// ---------------- fused prep: x (4 quarters, split) + 4 weights (single fp16) ----------------
__global__ void convall_kernel(const float* __restrict__ x,
                               const float* __restrict__ w0, const float* __restrict__ w1,
                               const float* __restrict__ w2, const float* __restrict__ w3,
                               __half* __restrict__ xh, __half* __restrict__ xl,
                               __half* __restrict__ wh)
{
    const int y = blockIdx.y;
    int i = blockIdx.x * blockDim.x + threadIdx.x;   // float4 index within segment
    if (y < 4) {
        const float* src = x + (size_t)y * (M_TOT*DMODEL/4);
        size_t off = (size_t)y * (M_TOT*DMODEL/4);
        float4 v = *(const float4*)(src + (size_t)i*4);
        uint32_t h0, l0, h1, l1;
        split2h(v.x, v.y, h0, l0);
        split2h(v.z, v.w, h1, l1);
        *(uint32_t*)(xh + off + (size_t)i*4)     = h0;
        *(uint32_t*)(xh + off + (size_t)i*4 + 2) = h1;
        *(uint32_t*)(xl + off + (size_t)i*4)     = l0;
        *(uint32_t*)(xl + off + (size_t)i*4 + 2) = l1;
    } else {
        const float* ws[4] = {w0, w1, w2, w3};
        const float* src = ws[y-4];
        size_t off = (size_t)(y-4) * DMODEL * DMODEL;
        float4 v = *(const float4*)(src + (size_t)i*4);
        *(uint32_t*)(wh + off + (size_t)i*4)     = pack_h2(v.x, v.y);
        *(uint32_t*)(wh + off + (size_t)i*4 + 2) = pack_h2(v.z, v.w);
    }
}

__global__ void rope_table_kernel(const int* __restrict__ pos,
                                  float* __restrict__ cosT, float* __restrict__ sinT)
{
    int idx = blockIdx.x * blockDim.x + threadIdx.x;
    int s  = idx >> 5;
    int ip = idx & 31;
    double invf = exp2(-(double)ip * 0.41524101186092028);  // log2(10000)/32
    float ang = (float)pos[s] * (float)invf;
    float sn, cs;
    sincosf(ang, &sn, &cs);
    cosT[idx] = cs;
    sinT[idx] = sn;
}

// ---------------- fp16 split-A GEMM: C = (Ah+Al)[M,K] * B[N,K]^T, 2 passes ----------------
// MODE 0: row-major fp32 C; MODE 3: fused QKV (z=0 Q hi/lo + RoPE, z=1 K fp16 + RoPE, z=2 V fp16)
#define NKCH (DMODEL/16)          // 64
#define GROW 24                   // b16 row stride (48B)
#define G_TILE_BYTES (128*GROW*2) // 6144
#define G_STAGE_BYTES (3*G_TILE_BYTES)  // 18432 (Ah, Al, B)
#define GEMM_SMEM (4*G_STAGE_BYTES)     // 73728

template<int MODE>
__global__ __launch_bounds__(256, 2)
void gemm_mma(const __half* __restrict__ Ahi, const __half* __restrict__ Alo,
              const __half* __restrict__ B_,
              float* __restrict__ C,
              __half* __restrict__ Qhi, __half* __restrict__ Qlo,
              __half* __restrict__ Kout, __half* __restrict__ Vout,
              const float* __restrict__ ropec, const float* __restrict__ ropes)
{
    extern __shared__ __half smh[];
    const uint32_t sbase = smem_u32(smh);
    const int tid  = threadIdx.x;
    const int wid  = tid >> 5;
    const int lane = tid & 31;
    const int bm = blockIdx.y, bn = blockIdx.x;
    const int wm = wid & 3;
    const int wn = wid >> 2;

    const __half* Bw = B_;
    bool do_rope = false;
    int zsel = 0;
    if (MODE == 3) {
        zsel = blockIdx.z;
        Bw = B_ + (size_t)zsel * DMODEL * DMODEL;
        do_rope = (zsel < 2);
    }

    float acc[2][8][4];
    #pragma unroll
    for (int mt = 0; mt < 2; mt++)
        #pragma unroll
        for (int nt = 0; nt < 8; nt++)
            #pragma unroll
            for (int j = 0; j < 4; j++) acc[mt][nt][j] = 0.f;

    const __half* Ah = Ahi + (size_t)(bm*128)*DMODEL;
    const __half* Al = Alo + (size_t)(bm*128)*DMODEL;
    const __half* Bh = Bw  + (size_t)(bn*128)*DMODEL;

    // loader: each thread owns (row = tid>>1, chunk = tid&1), 3 cp16/stage
    const int lc = tid & 1;
    const int rb = tid >> 1;              // 0..127
    const __half* SAh = Ah + (size_t)rb*DMODEL + lc*8;
    const __half* SAl = Al + (size_t)rb*DMODEL + lc*8;
    const __half* SB  = Bh + (size_t)rb*DMODEL + lc*8;
    const uint32_t dsl = sbase + (uint32_t)(rb*48 + lc*16);

    auto load_stage = [&](int stg, int kc) {
        const uint32_t d = dsl + stg*G_STAGE_BYTES;
        const int ko = kc*16;
        cp16(d,                  SAh + ko);
        cp16(d +   G_TILE_BYTES, SAl + ko);
        cp16(d + 2*G_TILE_BYTES, SB  + ko);
        CP_COMMIT();
    };

    load_stage(0, 0);
    load_stage(1, 1);
    load_stage(2, 2);

    const int a_row   = wm*32 + (lane & 15);
    const int a_co    = (lane >> 4) * 8;
    const int b_row_p = wn*64 + (lane & 7) + ((lane >> 4) << 3);
    const int b_co    = ((lane >> 3) & 1) * 8;

    for (int kc = 0; kc < NKCH; kc++) {
        if (kc < NKCH-2)       cp_wait<2>();
        else if (kc == NKCH-2) cp_wait<1>();
        else                   cp_wait<0>();
        __syncthreads();
        const uint32_t sbk = sbase + (kc & 3)*G_STAGE_BYTES;

        uint32_t ah[2][4], al[2][4];
        #pragma unroll
        for (int mt = 0; mt < 2; mt++) {
            uint32_t aaddr = sbk + (uint32_t)(((a_row + mt*16)*GROW + a_co)*2);
            ldsm_x4(ah[mt][0], ah[mt][1], ah[mt][2], ah[mt][3], aaddr);
            ldsm_x4(al[mt][0], al[mt][1], al[mt][2], al[mt][3], aaddr + G_TILE_BYTES);
        }
        #pragma unroll
        for (int pp = 0; pp < 2; pp++) {
            uint32_t b4[2][4];
            #pragma unroll
            for (int i = 0; i < 2; i++) {
                int p = 2*pp + i;
                uint32_t baddr = sbk + 2*G_TILE_BYTES +
                                 (uint32_t)(((b_row_p + p*16)*GROW + b_co)*2);
                ldsm_x4(b4[i][0], b4[i][1], b4[i][2], b4[i][3], baddr);
            }
            // pass 1: Ah*B (8 independent)
            #pragma unroll
            for (int i = 0; i < 2; i++) {
                int p = 2*pp + i;
                #pragma unroll
                for (int mt = 0; mt < 2; mt++) {
                    mma_f16(acc[mt][2*p],   ah[mt], b4[i]);
                    mma_f16(acc[mt][2*p+1], ah[mt], b4[i]+2);
                }
            }
            // pass 2: Al*B
            #pragma unroll
            for (int i = 0; i < 2; i++) {
                int p = 2*pp + i;
                #pragma unroll
                for (int mt = 0; mt < 2; mt++) {
                    mma_f16(acc[mt][2*p],   al[mt], b4[i]);
                    mma_f16(acc[mt][2*p+1], al[mt], b4[i]+2);
                }
            }
        }
        if (kc + 3 < NKCH) load_stage((kc + 3) & 3, kc + 3);
    }

    // ---- epilogue ----
    const int row_base = bm*128 + wm*32;
    const int col_base = bn*128 + wn*64;
    #pragma unroll
    for (int mt = 0; mt < 2; mt++) {
        #pragma unroll
        for (int rg = 0; rg < 2; rg++) {
            int row = row_base + mt*16 + rg*8 + (lane >> 2);
            int s = row & (SEQ-1);
            int b = row >> 11;
            #pragma unroll
            for (int nt = 0; nt < 8; nt++) {
                int col = col_base + nt*8 + 2*(lane & 3);
                float e = acc[mt][nt][rg*2];
                float o = acc[mt][nt][rg*2+1];
                if (MODE == 3 && do_rope) {
                    int ip = (col & 63) >> 1;
                    float cs = ropec[s*32 + ip];
                    float sn = ropes[s*32 + ip];
                    float ne = e*cs - o*sn;
                    float no = e*sn + o*cs;
                    e = ne; o = no;
                }
                if (MODE == 0) {
                    *(float2*)(C + (size_t)row*DMODEL + col) = make_float2(e, o);
                } else {
                    int h = col >> 6, dk = col & 63;
                    size_t idx = ((size_t)(b*NHEADS + h)*SEQ + s)*DKH + dk;
                    if (zsel == 0) {
                        uint32_t hi, lo;
                        split2h(e, o, hi, lo);
                        *(uint32_t*)(Qhi + idx) = hi;
                        *(uint32_t*)(Qlo + idx) = lo;
                    } else if (zsel == 1) {
                        *(uint32_t*)(Kout + idx) = pack_h2(e, o);
                    } else {
                        *(uint32_t*)(Vout + idx) = pack_h2(e, o);
                    }
                }
            }
        }
    }
}

// ---------------- fp16 flash attention: QK split-Q x2, PV single-pass ----------------
// smem (half units): Qh[128][72] @0, Ql @9216; 2 KV stages @18432: {K, V} 64x72 each
#define A_STR 72
#define A_SQL 9216
#define A_SST 18432
#define A_BUF 4608                 // 64*72
#define A_STG (2*A_BUF)            // 9216
#define ATTN_SMEM_BYTES ((A_SST + 2*A_STG)*2)   // 73728
#define SCALE_LOG2 0.18033688011112042f         // 0.125 * log2(e)

__global__ __launch_bounds__(256, 2)
void attn_mma(const __half* __restrict__ Qh_g, const __half* __restrict__ Ql_g,
              const __half* __restrict__ Kh_g, const __half* __restrict__ Vh_g,
              __half* __restrict__ Ohi, __half* __restrict__ Olo)
{
    extern __shared__ __half smh[];
    const uint32_t sb = smem_u32(smh);
    const int tid  = threadIdx.x;
    const int wq   = tid >> 5;
    const int lane = tid & 31;
    const int bh   = blockIdx.y;
    const int qt   = gridDim.x - 1 - blockIdx.x;
    const int q0   = qt * 128;
    const size_t boff = (size_t)bh*SEQ*DKH;

    // ---- Q (hi+lo) ----
    #pragma unroll
    for (int l = 0; l < 4; l++) {
        int item = tid + l*256;
        int r = item >> 3;
        int c = item & 7;
        uint32_t d = sb + (uint32_t)(r*A_STR + c*8)*2;
        const __half* src = Qh_g + boff + (size_t)(q0+r)*DKH + c*8;
        cp16(d, src);
        cp16(d + A_SQL*2, Ql_g + (src - Qh_g));
    }
    CP_COMMIT();

    // KV loader: bsel 0 -> K, 1 -> V; each thread 4 cp16/stage
    const int bsel = tid >> 7;
    const int loc  = tid & 127;
    const int vc   = loc & 7;
    const int vr   = loc >> 3;          // 0..15
    const __half* Pk = bsel ? Vh_g : Kh_g;
    const __half* Pkv = Pk + boff + (size_t)vr*DKH + vc*8;
    const uint32_t dkv = sb + (uint32_t)((A_SST + bsel*A_BUF + vr*A_STR + vc*8)*2);

    auto load_kv = [&](int stg, int t) {
        const __half* s = Pkv + (size_t)(t*64)*DKH;
        const uint32_t d = dkv + stg*(A_STG*2);
        #pragma unroll
        for (int i = 0; i < 4; i++)
            cp16(d + i*(16*A_STR*2), s + (size_t)(i*16)*DKH);
        CP_COMMIT();
    };

    load_kv(0, 0);

    float sc[8][4];
    float o[8][4];
    #pragma unroll
    for (int nt = 0; nt < 8; nt++)
        #pragma unroll
        for (int j = 0; j < 4; j++) o[nt][j] = 0.f;
    float m0 = -INFINITY, m1 = -INFINITY, l0 = 0.f, l1 = 0.f;

    const int nkt = qt*2 + 2;

    for (int t = 0; t < nkt; t++) {
        const int k0 = t * 64;
        if (t + 1 < nkt) { load_kv((t+1) & 1, t+1); cp_wait<1>(); }
        else             { cp_wait<0>(); }
        __syncthreads();
        const uint32_t stb = sb + (uint32_t)((A_SST + (t & 1)*A_STG)*2);

        const bool active = (k0 <= q0 + wq*16 + 15);
        if (active) {
            // ---- S = Q K^T (split-Q, 2 passes) ----
            #pragma unroll
            for (int nt = 0; nt < 8; nt++)
                #pragma unroll
                for (int j = 0; j < 4; j++) sc[nt][j] = 0.f;
            #pragma unroll
            for (int kt = 0; kt < 4; kt++) {
                uint32_t ah[4], al[4];
                uint32_t aaddr = sb + (uint32_t)(((wq*16 + (lane & 15))*A_STR + kt*16 + (lane >> 4)*8)*2);
                ldsm_x4(ah[0], ah[1], ah[2], ah[3], aaddr);
                ldsm_x4(al[0], al[1], al[2], al[3], aaddr + A_SQL*2);
                #pragma unroll
                for (int pp = 0; pp < 2; pp++) {
                    uint32_t kh4[2][4];
                    #pragma unroll
                    for (int i = 0; i < 2; i++) {
                        int p = 2*pp + i;
                        int brow = p*16 + (lane & 7) + ((lane >> 4) << 3);
                        uint32_t baddr = stb + (uint32_t)((brow*A_STR + kt*16 + ((lane >> 3) & 1)*8)*2);
                        ldsm_x4(kh4[i][0], kh4[i][1], kh4[i][2], kh4[i][3], baddr);
                    }
                    #pragma unroll
                    for (int i = 0; i < 2; i++) {
                        int p = 2*pp + i;
                        mma_f16(sc[2*p],   ah, kh4[i]);
                        mma_f16(sc[2*p+1], ah, kh4[i]+2);
                    }
                    #pragma unroll
                    for (int i = 0; i < 2; i++) {
                        int p = 2*pp + i;
                        mma_f16(sc[2*p],   al, kh4[i]);
                        mma_f16(sc[2*p+1], al, kh4[i]+2);
                    }
                }
            }

            // ---- softmax (online, log2 domain) ----
            const int qrow = q0 + wq*16 + (lane >> 2);
            const bool needmask = (k0 + 63 > q0 + wq*16);
            float mx0 = -1e30f, mx1 = -1e30f;
            #pragma unroll
            for (int nt = 0; nt < 8; nt++) {
                #pragma unroll
                for (int j = 0; j < 4; j++) sc[nt][j] *= SCALE_LOG2;
                if (needmask) {
                    int kcol = k0 + nt*8 + 2*(lane & 3);
                    if (kcol+0 > qrow)   sc[nt][0] = -1e30f;
                    if (kcol+1 > qrow)   sc[nt][1] = -1e30f;
                    if (kcol+0 > qrow+8) sc[nt][2] = -1e30f;
                    if (kcol+1 > qrow+8) sc[nt][3] = -1e30f;
                }
                mx0 = fmaxf(mx0, fmaxf(sc[nt][0], sc[nt][1]));
                mx1 = fmaxf(mx1, fmaxf(sc[nt][2], sc[nt][3]));
            }
            mx0 = fmaxf(mx0, __shfl_xor_sync(0xffffffffu, mx0, 1));
            mx0 = fmaxf(mx0, __shfl_xor_sync(0xffffffffu, mx0, 2));
            mx1 = fmaxf(mx1, __shfl_xor_sync(0xffffffffu, mx1, 1));
            mx1 = fmaxf(mx1, __shfl_xor_sync(0xffffffffu, mx1, 2));
            float mn0 = fmaxf(m0, mx0), mn1 = fmaxf(m1, mx1);
            float f0 = exp2f(m0 - mn0), f1 = exp2f(m1 - mn1);
            m0 = mn0; m1 = mn1;
            float sum0 = 0.f, sum1 = 0.f;
            #pragma unroll
            for (int nt = 0; nt < 8; nt++) {
                sc[nt][0] = exp2f(sc[nt][0] - mn0);
                sc[nt][1] = exp2f(sc[nt][1] - mn0);
                sc[nt][2] = exp2f(sc[nt][2] - mn1);
                sc[nt][3] = exp2f(sc[nt][3] - mn1);
                sum0 += sc[nt][0] + sc[nt][1];
                sum1 += sc[nt][2] + sc[nt][3];
            }
            sum0 += __shfl_xor_sync(0xffffffffu, sum0, 1);
            sum0 += __shfl_xor_sync(0xffffffffu, sum0, 2);
            sum1 += __shfl_xor_sync(0xffffffffu, sum1, 1);
            sum1 += __shfl_xor_sync(0xffffffffu, sum1, 2);
            l0 = l0*f0 + sum0;
            l1 = l1*f1 + sum1;
            #pragma unroll
            for (int nt = 0; nt < 8; nt++) {
                o[nt][0] *= f0; o[nt][1] *= f0;
                o[nt][2] *= f1; o[nt][3] *= f1;
            }

            // ---- O += P V (single-pass fp16) ----
            #pragma unroll
            for (int kt = 0; kt < 4; kt++) {
                uint32_t pf[4];
                pf[0] = pack_h2(sc[2*kt][0],   sc[2*kt][1]);
                pf[1] = pack_h2(sc[2*kt][2],   sc[2*kt][3]);
                pf[2] = pack_h2(sc[2*kt+1][0], sc[2*kt+1][1]);
                pf[3] = pack_h2(sc[2*kt+1][2], sc[2*kt+1][3]);
                #pragma unroll
                for (int pp = 0; pp < 2; pp++) {
                    uint32_t vh4[2][4];
                    #pragma unroll
                    for (int i = 0; i < 2; i++) {
                        int dp = 2*pp + i;
                        uint32_t vaddr = stb + (uint32_t)((A_BUF +
                                         (kt*16 + (lane & 15))*A_STR +
                                         dp*16 + ((lane >> 4) & 1)*8)*2);
                        ldsm_x4t(vh4[i][0], vh4[i][1], vh4[i][2], vh4[i][3], vaddr);
                    }
                    #pragma unroll
                    for (int i = 0; i < 2; i++) {
                        int dp = 2*pp + i;
                        mma_f16(o[2*dp],   pf, vh4[i]);
                        mma_f16(o[2*dp+1], pf, vh4[i]+2);
                    }
                }
            }
        }
        __syncthreads();   // protect stage (t+1)&1 before next iteration's load
    }

    // ---- epilogue: split fp16 hi/lo ----
    const int b = bh >> 4, h = bh & 15;
    const float i0 = 1.f / l0, i1 = 1.f / l1;
    const int srow = q0 + wq*16 + (lane >> 2);
    const size_t base0 = ((size_t)(b*SEQ + srow))*DMODEL + h*64;
    const size_t base1 = base0 + (size_t)8*DMODEL;
    #pragma unroll
    for (int nt = 0; nt < 8; nt++) {
        int col = nt*8 + 2*(lane & 3);
        uint32_t hi, lo;
        split2h(o[nt][0]*i0, o[nt][1]*i0, hi, lo);
        *(uint32_t*)(Ohi + base0 + col) = hi;
        *(uint32_t*)(Olo + base0 + col) = lo;
        split2h(o[nt][2]*i1, o[nt][3]*i1, hi, lo);
        *(uint32_t*)(Ohi + base1 + col) = hi;
        *(uint32_t*)(Olo + base1 + col) = lo;
    }
}

// ---------------- launch ----------------
extern "C" void kernel_launch(void* const* d_in, const int* in_sizes, int n_in,
                              void* d_out, int out_size)
{
    const float* x  = (const float*)d_in[0];
    const float* wq = (const float*)d_in[1];
    const float* wk = (const float*)d_in[2];
    const float* wv = (const float*)d_in[3];
    const float* wo = (const float*)d_in[4];
    const int*  pos = (const int*)d_in[5];
    float* out = (float*)d_out;

    float *rc, *rs;
    __half *xh, *xl, *wh, *qh, *ql, *kh, *vh, *aoh, *aol;
    cudaGetSymbolAddress((void**)&rc,  g_ropec);
    cudaGetSymbolAddress((void**)&rs,  g_ropes);
    cudaGetSymbolAddress((void**)&xh,  g_xh);
    cudaGetSymbolAddress((void**)&xl,  g_xl);
    cudaGetSymbolAddress((void**)&wh,  g_wh);
    cudaGetSymbolAddress((void**)&qh,  g_qh);
    cudaGetSymbolAddress((void**)&ql,  g_ql);
    cudaGetSymbolAddress((void**)&kh,  g_kh);
    cudaGetSymbolAddress((void**)&vh,  g_vh);
    cudaGetSymbolAddress((void**)&aoh, g_aoh);
    cudaGetSymbolAddress((void**)&aol, g_aol);

    static bool attr_done = false;
    if (!attr_done) {
        cudaFuncSetAttribute(gemm_mma<0>, cudaFuncAttributeMaxDynamicSharedMemorySize, GEMM_SMEM);
        cudaFuncSetAttribute(gemm_mma<3>, cudaFuncAttributeMaxDynamicSharedMemorySize, GEMM_SMEM);
        cudaFuncSetAttribute(attn_mma, cudaFuncAttributeMaxDynamicSharedMemorySize, ATTN_SMEM_BYTES);
        attr_done = true;
    }

    rope_table_kernel<<<(SEQ*32)/256, 256>>>(pos, rc, rs);
    {
        dim3 gc(1024, 8);   // 8 uniform segments of 262144 float4
        convall_kernel<<<gc, 256>>>(x, wq, wk, wv, wo, xh, xl, wh);
    }

    const size_t WN = (size_t)DMODEL*DMODEL;

    dim3 gqkv(DMODEL/128, M_TOT/128, 3);   // z=0 Q, z=1 K, z=2 V
    gemm_mma<3><<<gqkv, 256, GEMM_SMEM>>>(xh, xl, wh,
                                          nullptr, qh, ql, kh, vh, rc, rs);

    dim3 ga(SEQ/128, BATCH*NHEADS);
    attn_mma<<<ga, 256, ATTN_SMEM_BYTES>>>(qh, ql, kh, vh, aoh, aol);

    dim3 gg(DMODEL/128, M_TOT/128);
    gemm_mma<0><<<gg, 256, GEMM_SMEM>>>(aoh, aol, wh + 3*WN,
                                        out, nullptr, nullptr, nullptr, nullptr, rc, rs);
}

// round 12
// speedup vs baseline: 4.3783x; 1.0230x over previous
#include <cuda_runtime.h>
#include <cuda_fp16.h>
#include <math.h>
#include <cstdint>

#define BATCH   2
#define SEQ     2048
#define DMODEL  1024
#define NHEADS  16
#define DKH     64
#define M_TOT   (BATCH*SEQ)   // 4096
#define QKV_ELEMS (BATCH*NHEADS*SEQ*DKH)

// ---------------- scratch (static device globals; no allocs) ----------------
__device__ __align__(256) __half g_xh[M_TOT*DMODEL];
__device__ __align__(256) __half g_xl[M_TOT*DMODEL];
__device__ __align__(256) __half g_wh[4*DMODEL*DMODEL];   // weights single fp16
__device__ __align__(256) __half g_qh[QKV_ELEMS];
__device__ __align__(256) __half g_ql[QKV_ELEMS];
__device__ __align__(256) __half g_kh[QKV_ELEMS];         // K single fp16
__device__ __align__(256) __half g_vh[QKV_ELEMS];         // V single fp16
__device__ __align__(256) __half g_aoh[M_TOT*DMODEL];
__device__ __align__(256) __half g_aol[M_TOT*DMODEL];
__device__ float g_ropec[SEQ*32];   // [s][ip]
__device__ float g_ropes[SEQ*32];

// ---------------- PTX helpers ----------------
__device__ __forceinline__ uint32_t smem_u32(const void* p) {
    uint32_t a;
    asm("{ .reg .u64 t; cvta.to.shared.u64 t, %1; cvt.u32.u64 %0, t; }" : "=r"(a) : "l"(p));
    return a;
}
__device__ __forceinline__ void cp16(uint32_t dst, const void* src) {
    asm volatile("cp.async.cg.shared.global [%0], [%1], 16;" :: "r"(dst), "l"(src) : "memory");
}
#define CP_COMMIT() asm volatile("cp.async.commit_group;" ::: "memory")
template<int N>
__device__ __forceinline__ void cp_wait() {
    asm volatile("cp.async.wait_group %0;" :: "n"(N) : "memory");
}
__device__ __forceinline__ void ldsm_x4(uint32_t& r0, uint32_t& r1, uint32_t& r2,
                                        uint32_t& r3, uint32_t addr) {
    asm volatile("ldmatrix.sync.aligned.m8n8.x4.shared.b16 {%0,%1,%2,%3}, [%4];"
                 : "=r"(r0), "=r"(r1), "=r"(r2), "=r"(r3) : "r"(addr));
}
__device__ __forceinline__ void ldsm_x4t(uint32_t& r0, uint32_t& r1, uint32_t& r2,
                                         uint32_t& r3, uint32_t addr) {
    asm volatile("ldmatrix.sync.aligned.m8n8.x4.trans.shared.b16 {%0,%1,%2,%3}, [%4];"
                 : "=r"(r0), "=r"(r1), "=r"(r2), "=r"(r3) : "r"(addr));
}
__device__ __forceinline__ void mma_f16(float* c, const uint32_t* a, const uint32_t* b) {
    asm volatile("mma.sync.aligned.m16n8k16.row.col.f32.f16.f16.f32 "
                 "{%0,%1,%2,%3}, {%4,%5,%6,%7}, {%8,%9}, {%0,%1,%2,%3};"
                 : "+f"(c[0]), "+f"(c[1]), "+f"(c[2]), "+f"(c[3])
                 : "r"(a[0]), "r"(a[1]), "r"(a[2]), "r"(a[3]), "r"(b[0]), "r"(b[1]));
}
__device__ __forceinline__ uint32_t pack_h2(float a, float b) {
    __half2 h = __floats2half2_rn(a, b);
    return *(uint32_t*)&h;
}
__device__ __forceinline__ uint32_t ex2_h2(uint32_t x) {
    uint32_t r;
    asm("ex2.approx.f16x2 %0, %1;" : "=r"(r) : "r"(x));
    return r;
}
// split pair of floats into packed fp16x2 hi + lo residual (~22-bit effective)
__device__ __forceinline__ void split2h(float a, float b, uint32_t& hi, uint32_t& lo) {
    __half2 h = __floats2half2_rn(a, b);
    float ha = __low2float(h), hb = __high2float(h);
    __half2 l = __floats2half2_rn(a - ha, b - hb);
    hi = *(uint32_t*)&h;
    lo = *(uint32_t*)&l;
}

// ---------------- fused prep: x (4 quarters, split) + 4 weights (single fp16) ----------------
__global__ void convall_kernel(const float* __restrict__ x,
                               const float* __restrict__ w0, const float* __restrict__ w1,
                               const float* __restrict__ w2, const float* __restrict__ w3,
                               __half* __restrict__ xh, __half* __restrict__ xl,
                               __half* __restrict__ wh)
{
    const int y = blockIdx.y;
    int i = blockIdx.x * blockDim.x + threadIdx.x;
    if (y < 4) {
        const float* src = x + (size_t)y * (M_TOT*DMODEL/4);
        size_t off = (size_t)y * (M_TOT*DMODEL/4);
        float4 v = *(const float4*)(src + (size_t)i*4);
        uint32_t h0, l0, h1, l1;
        split2h(v.x, v.y, h0, l0);
        split2h(v.z, v.w, h1, l1);
        *(uint32_t*)(xh + off + (size_t)i*4)     = h0;
        *(uint32_t*)(xh + off + (size_t)i*4 + 2) = h1;
        *(uint32_t*)(xl + off + (size_t)i*4)     = l0;
        *(uint32_t*)(xl + off + (size_t)i*4 + 2) = l1;
    } else {
        const float* ws[4] = {w0, w1, w2, w3};
        const float* src = ws[y-4];
        size_t off = (size_t)(y-4) * DMODEL * DMODEL;
        float4 v = *(const float4*)(src + (size_t)i*4);
        *(uint32_t*)(wh + off + (size_t)i*4)     = pack_h2(v.x, v.y);
        *(uint32_t*)(wh + off + (size_t)i*4 + 2) = pack_h2(v.z, v.w);
    }
}

__global__ void rope_table_kernel(const int* __restrict__ pos,
                                  float* __restrict__ cosT, float* __restrict__ sinT)
{
    int idx = blockIdx.x * blockDim.x + threadIdx.x;
    int s  = idx >> 5;
    int ip = idx & 31;
    double invf = exp2(-(double)ip * 0.41524101186092028);  // log2(10000)/32
    float ang = (float)pos[s] * (float)invf;
    float sn, cs;
    sincosf(ang, &sn, &cs);
    cosT[idx] = cs;
    sinT[idx] = sn;
}

// ---------------- fp16 split-A GEMM: C = (Ah+Al)[M,K] * B[N,K]^T, 2 passes ----------------
#define NKCH (DMODEL/16)          // 64
#define GROW 24                   // b16 row stride (48B)
#define G_TILE_BYTES (128*GROW*2) // 6144
#define G_STAGE_BYTES (3*G_TILE_BYTES)  // 18432 (Ah, Al, B)
#define GEMM_SMEM (4*G_STAGE_BYTES)     // 73728

template<int MODE>
__global__ __launch_bounds__(256, 2)
void gemm_mma(const __half* __restrict__ Ahi, const __half* __restrict__ Alo,
              const __half* __restrict__ B_,
              float* __restrict__ C,
              __half* __restrict__ Qhi, __half* __restrict__ Qlo,
              __half* __restrict__ Kout, __half* __restrict__ Vout,
              const float* __restrict__ ropec, const float* __restrict__ ropes)
{
    extern __shared__ __half smh[];
    const uint32_t sbase = smem_u32(smh);
    const int tid  = threadIdx.x;
    const int wid  = tid >> 5;
    const int lane = tid & 31;
    const int bm = blockIdx.y, bn = blockIdx.x;
    const int wm = wid & 3;
    const int wn = wid >> 2;

    const __half* Bw = B_;
    bool do_rope = false;
    int zsel = 0;
    if (MODE == 3) {
        zsel = blockIdx.z;
        Bw = B_ + (size_t)zsel * DMODEL * DMODEL;
        do_rope = (zsel < 2);
    }

    float acc[2][8][4];
    #pragma unroll
    for (int mt = 0; mt < 2; mt++)
        #pragma unroll
        for (int nt = 0; nt < 8; nt++)
            #pragma unroll
            for (int j = 0; j < 4; j++) acc[mt][nt][j] = 0.f;

    const __half* Ah = Ahi + (size_t)(bm*128)*DMODEL;
    const __half* Al = Alo + (size_t)(bm*128)*DMODEL;
    const __half* Bh = Bw  + (size_t)(bn*128)*DMODEL;

    const int lc = tid & 1;
    const int rb = tid >> 1;
    const __half* SAh = Ah + (size_t)rb*DMODEL + lc*8;
    const __half* SAl = Al + (size_t)rb*DMODEL + lc*8;
    const __half* SB  = Bh + (size_t)rb*DMODEL + lc*8;
    const uint32_t dsl = sbase + (uint32_t)(rb*48 + lc*16);

    auto load_stage = [&](int stg, int kc) {
        const uint32_t d = dsl + stg*G_STAGE_BYTES;
        const int ko = kc*16;
        cp16(d,                  SAh + ko);
        cp16(d +   G_TILE_BYTES, SAl + ko);
        cp16(d + 2*G_TILE_BYTES, SB  + ko);
        CP_COMMIT();
    };

    load_stage(0, 0);
    load_stage(1, 1);
    load_stage(2, 2);

    const int a_row   = wm*32 + (lane & 15);
    const int a_co    = (lane >> 4) * 8;
    const int b_row_p = wn*64 + (lane & 7) + ((lane >> 4) << 3);
    const int b_co    = ((lane >> 3) & 1) * 8;

    for (int kc = 0; kc < NKCH; kc++) {
        if (kc < NKCH-2)       cp_wait<2>();
        else if (kc == NKCH-2) cp_wait<1>();
        else                   cp_wait<0>();
        __syncthreads();
        const uint32_t sbk = sbase + (kc & 3)*G_STAGE_BYTES;

        uint32_t ah[2][4], al[2][4];
        #pragma unroll
        for (int mt = 0; mt < 2; mt++) {
            uint32_t aaddr = sbk + (uint32_t)(((a_row + mt*16)*GROW + a_co)*2);
            ldsm_x4(ah[mt][0], ah[mt][1], ah[mt][2], ah[mt][3], aaddr);
            ldsm_x4(al[mt][0], al[mt][1], al[mt][2], al[mt][3], aaddr + G_TILE_BYTES);
        }
        #pragma unroll
        for (int pp = 0; pp < 2; pp++) {
            uint32_t b4[2][4];
            #pragma unroll
            for (int i = 0; i < 2; i++) {
                int p = 2*pp + i;
                uint32_t baddr = sbk + 2*G_TILE_BYTES +
                                 (uint32_t)(((b_row_p + p*16)*GROW + b_co)*2);
                ldsm_x4(b4[i][0], b4[i][1], b4[i][2], b4[i][3], baddr);
            }
            #pragma unroll
            for (int i = 0; i < 2; i++) {
                int p = 2*pp + i;
                #pragma unroll
                for (int mt = 0; mt < 2; mt++) {
                    mma_f16(acc[mt][2*p],   ah[mt], b4[i]);
                    mma_f16(acc[mt][2*p+1], ah[mt], b4[i]+2);
                }
            }
            #pragma unroll
            for (int i = 0; i < 2; i++) {
                int p = 2*pp + i;
                #pragma unroll
                for (int mt = 0; mt < 2; mt++) {
                    mma_f16(acc[mt][2*p],   al[mt], b4[i]);
                    mma_f16(acc[mt][2*p+1], al[mt], b4[i]+2);
                }
            }
        }
        if (kc + 3 < NKCH) load_stage((kc + 3) & 3, kc + 3);
    }

    // ---- epilogue ----
    const int row_base = bm*128 + wm*32;
    const int col_base = bn*128 + wn*64;
    #pragma unroll
    for (int mt = 0; mt < 2; mt++) {
        #pragma unroll
        for (int rg = 0; rg < 2; rg++) {
            int row = row_base + mt*16 + rg*8 + (lane >> 2);
            int s = row & (SEQ-1);
            int b = row >> 11;
            #pragma unroll
            for (int nt = 0; nt < 8; nt++) {
                int col = col_base + nt*8 + 2*(lane & 3);
                float e = acc[mt][nt][rg*2];
                float o = acc[mt][nt][rg*2+1];
                if (MODE == 3 && do_rope) {
                    int ip = (col & 63) >> 1;
                    float cs = ropec[s*32 + ip];
                    float sn = ropes[s*32 + ip];
                    float ne = e*cs - o*sn;
                    float no = e*sn + o*cs;
                    e = ne; o = no;
                }
                if (MODE == 0) {
                    *(float2*)(C + (size_t)row*DMODEL + col) = make_float2(e, o);
                } else {
                    int h = col >> 6, dk = col & 63;
                    size_t idx = ((size_t)(b*NHEADS + h)*SEQ + s)*DKH + dk;
                    if (zsel == 0) {
                        uint32_t hi, lo;
                        split2h(e, o, hi, lo);
                        *(uint32_t*)(Qhi + idx) = hi;
                        *(uint32_t*)(Qlo + idx) = lo;
                    } else if (zsel == 1) {
                        *(uint32_t*)(Kout + idx) = pack_h2(e, o);
                    } else {
                        *(uint32_t*)(Vout + idx) = pack_h2(e, o);
                    }
                }
            }
        }
    }
}

// ---------------- fp16 flash attention: QK split-Q x2, PV single-pass ----------------
// softmax: P via ex2.approx.f16x2; row sums via ones-MMA (k-reduction in tensor core)
#define A_STR 72
#define A_SQL 9216
#define A_SST 18432
#define A_BUF 4608                 // 64*72
#define A_STG (2*A_BUF)            // 9216
#define ATTN_SMEM_BYTES ((A_SST + 2*A_STG)*2)   // 73728
#define SCALE_LOG2 0.18033688011112042f         // 0.125 * log2(e)

__global__ __launch_bounds__(256, 2)
void attn_mma(const __half* __restrict__ Qh_g, const __half* __restrict__ Ql_g,
              const __half* __restrict__ Kh_g, const __half* __restrict__ Vh_g,
              __half* __restrict__ Ohi, __half* __restrict__ Olo)
{
    extern __shared__ __half smh[];
    const uint32_t sb = smem_u32(smh);
    const int tid  = threadIdx.x;
    const int wq   = tid >> 5;
    const int lane = tid & 31;
    const int bh   = blockIdx.y;
    const int qt   = gridDim.x - 1 - blockIdx.x;
    const int q0   = qt * 128;
    const size_t boff = (size_t)bh*SEQ*DKH;

    // ---- Q (hi+lo) ----
    #pragma unroll
    for (int l = 0; l < 4; l++) {
        int item = tid + l*256;
        int r = item >> 3;
        int c = item & 7;
        uint32_t d = sb + (uint32_t)(r*A_STR + c*8)*2;
        const __half* src = Qh_g + boff + (size_t)(q0+r)*DKH + c*8;
        cp16(d, src);
        cp16(d + A_SQL*2, Ql_g + (src - Qh_g));
    }
    CP_COMMIT();

    const int bsel = tid >> 7;
    const int loc  = tid & 127;
    const int vc   = loc & 7;
    const int vr   = loc >> 3;
    const __half* Pk = bsel ? Vh_g : Kh_g;
    const __half* Pkv = Pk + boff + (size_t)vr*DKH + vc*8;
    const uint32_t dkv = sb + (uint32_t)((A_SST + bsel*A_BUF + vr*A_STR + vc*8)*2);

    auto load_kv = [&](int stg, int t) {
        const __half* s = Pkv + (size_t)(t*64)*DKH;
        const uint32_t d = dkv + stg*(A_STG*2);
        #pragma unroll
        for (int i = 0; i < 4; i++)
            cp16(d + i*(16*A_STR*2), s + (size_t)(i*16)*DKH);
        CP_COMMIT();
    };

    load_kv(0, 0);

    float sc[8][4];
    float o[8][4];
    #pragma unroll
    for (int nt = 0; nt < 8; nt++)
        #pragma unroll
        for (int j = 0; j < 4; j++) o[nt][j] = 0.f;
    float m0 = -INFINITY, m1 = -INFINITY, l0 = 0.f, l1 = 0.f;

    const int nkt = qt*2 + 2;
    const uint32_t ONES2 = 0x3C003C00u;
    uint32_t ones_b[2] = {ONES2, ONES2};

    for (int t = 0; t < nkt; t++) {
        const int k0 = t * 64;
        if (t + 1 < nkt) { load_kv((t+1) & 1, t+1); cp_wait<1>(); }
        else             { cp_wait<0>(); }
        __syncthreads();
        const uint32_t stb = sb + (uint32_t)((A_SST + (t & 1)*A_STG)*2);

        const bool active = (k0 <= q0 + wq*16 + 15);
        if (active) {
            // ---- S = Q K^T (split-Q, 2 passes) ----
            #pragma unroll
            for (int nt = 0; nt < 8; nt++)
                #pragma unroll
                for (int j = 0; j < 4; j++) sc[nt][j] = 0.f;
            #pragma unroll
            for (int kt = 0; kt < 4; kt++) {
                uint32_t ah[4], al[4];
                uint32_t aaddr = sb + (uint32_t)(((wq*16 + (lane & 15))*A_STR + kt*16 + (lane >> 4)*8)*2);
                ldsm_x4(ah[0], ah[1], ah[2], ah[3], aaddr);
                ldsm_x4(al[0], al[1], al[2], al[3], aaddr + A_SQL*2);
                #pragma unroll
                for (int pp = 0; pp < 2; pp++) {
                    uint32_t kh4[2][4];
                    #pragma unroll
                    for (int i = 0; i < 2; i++) {
                        int p = 2*pp + i;
                        int brow = p*16 + (lane & 7) + ((lane >> 4) << 3);
                        uint32_t baddr = stb + (uint32_t)((brow*A_STR + kt*16 + ((lane >> 3) & 1)*8)*2);
                        ldsm_x4(kh4[i][0], kh4[i][1], kh4[i][2], kh4[i][3], baddr);
                    }
                    #pragma unroll
                    for (int i = 0; i < 2; i++) {
                        int p = 2*pp + i;
                        mma_f16(sc[2*p],   ah, kh4[i]);
                        mma_f16(sc[2*p+1], ah, kh4[i]+2);
                    }
                    #pragma unroll
                    for (int i = 0; i < 2; i++) {
                        int p = 2*pp + i;
                        mma_f16(sc[2*p],   al, kh4[i]);
                        mma_f16(sc[2*p+1], al, kh4[i]+2);
                    }
                }
            }

            // ---- softmax: scale/mask/max, then P = ex2.f16x2, sums via ones-MMA ----
            const int qrow = q0 + wq*16 + (lane >> 2);
            const bool needmask = (k0 + 63 > q0 + wq*16);
            float mx0 = -1e30f, mx1 = -1e30f;
            #pragma unroll
            for (int nt = 0; nt < 8; nt++) {
                #pragma unroll
                for (int j = 0; j < 4; j++) sc[nt][j] *= SCALE_LOG2;
                if (needmask) {
                    int kcol = k0 + nt*8 + 2*(lane & 3);
                    if (kcol+0 > qrow)   sc[nt][0] = -1e30f;
                    if (kcol+1 > qrow)   sc[nt][1] = -1e30f;
                    if (kcol+0 > qrow+8) sc[nt][2] = -1e30f;
                    if (kcol+1 > qrow+8) sc[nt][3] = -1e30f;
                }
                mx0 = fmaxf(mx0, fmaxf(sc[nt][0], sc[nt][1]));
                mx1 = fmaxf(mx1, fmaxf(sc[nt][2], sc[nt][3]));
            }
            mx0 = fmaxf(mx0, __shfl_xor_sync(0xffffffffu, mx0, 1));
            mx0 = fmaxf(mx0, __shfl_xor_sync(0xffffffffu, mx0, 2));
            mx1 = fmaxf(mx1, __shfl_xor_sync(0xffffffffu, mx1, 1));
            mx1 = fmaxf(mx1, __shfl_xor_sync(0xffffffffu, mx1, 2));
            float mn0 = fmaxf(m0, mx0), mn1 = fmaxf(m1, mx1);
            float f0 = exp2f(m0 - mn0), f1 = exp2f(m1 - mn1);
            m0 = mn0; m1 = mn1;

            // P fragments directly in fp16 (pr[nt][0]: rows r; pr[nt][1]: rows r+8)
            uint32_t pr[8][2];
            #pragma unroll
            for (int nt = 0; nt < 8; nt++) {
                pr[nt][0] = ex2_h2(pack_h2(sc[nt][0] - mn0, sc[nt][1] - mn0));
                pr[nt][1] = ex2_h2(pack_h2(sc[nt][2] - mn1, sc[nt][3] - mn1));
            }

            // row sums via ones-MMA (k-reduction inside tensor core, no shuffles)
            float ps[4] = {0.f, 0.f, 0.f, 0.f};
            #pragma unroll
            for (int kt = 0; kt < 4; kt++) {
                uint32_t pf[4] = {pr[2*kt][0], pr[2*kt][1], pr[2*kt+1][0], pr[2*kt+1][1]};
                mma_f16(ps, pf, ones_b);
            }
            l0 = l0*f0 + ps[0];
            l1 = l1*f1 + ps[2];
            #pragma unroll
            for (int nt = 0; nt < 8; nt++) {
                o[nt][0] *= f0; o[nt][1] *= f0;
                o[nt][2] *= f1; o[nt][3] *= f1;
            }

            // ---- O += P V (single-pass fp16) ----
            #pragma unroll
            for (int kt = 0; kt < 4; kt++) {
                uint32_t pf[4] = {pr[2*kt][0], pr[2*kt][1], pr[2*kt+1][0], pr[2*kt+1][1]};
                #pragma unroll
                for (int pp = 0; pp < 2; pp++) {
                    uint32_t vh4[2][4];
                    #pragma unroll
                    for (int i = 0; i < 2; i++) {
                        int dp = 2*pp + i;
                        uint32_t vaddr = stb + (uint32_t)((A_BUF +
                                         (kt*16 + (lane & 15))*A_STR +
                                         dp*16 + ((lane >> 4) & 1)*8)*2);
                        ldsm_x4t(vh4[i][0], vh4[i][1], vh4[i][2], vh4[i][3], vaddr);
                    }
                    #pragma unroll
                    for (int i = 0; i < 2; i++) {
                        int dp = 2*pp + i;
                        mma_f16(o[2*dp],   pf, vh4[i]);
                        mma_f16(o[2*dp+1], pf, vh4[i]+2);
                    }
                }
            }
        }
        __syncthreads();   // protect stage (t+1)&1 before next iteration's load
    }

    // ---- epilogue: split fp16 hi/lo ----
    const int b = bh >> 4, h = bh & 15;
    const float i0 = 1.f / l0, i1 = 1.f / l1;
    const int srow = q0 + wq*16 + (lane >> 2);
    const size_t base0 = ((size_t)(b*SEQ + srow))*DMODEL + h*64;
    const size_t base1 = base0 + (size_t)8*DMODEL;
    #pragma unroll
    for (int nt = 0; nt < 8; nt++) {
        int col = nt*8 + 2*(lane & 3);
        uint32_t hi, lo;
        split2h(o[nt][0]*i0, o[nt][1]*i0, hi, lo);
        *(uint32_t*)(Ohi + base0 + col) = hi;
        *(uint32_t*)(Olo + base0 + col) = lo;
        split2h(o[nt][2]*i1, o[nt][3]*i1, hi, lo);
        *(uint32_t*)(Ohi + base1 + col) = hi;
        *(uint32_t*)(Olo + base1 + col) = lo;
    }
}

// ---------------- launch ----------------
extern "C" void kernel_launch(void* const* d_in, const int* in_sizes, int n_in,
                              void* d_out, int out_size)
{
    const float* x  = (const float*)d_in[0];
    const float* wq = (const float*)d_in[1];
    const float* wk = (const float*)d_in[2];
    const float* wv = (const float*)d_in[3];
    const float* wo = (const float*)d_in[4];
    const int*  pos = (const int*)d_in[5];
    float* out = (float*)d_out;

    float *rc, *rs;
    __half *xh, *xl, *wh, *qh, *ql, *kh, *vh, *aoh, *aol;
    cudaGetSymbolAddress((void**)&rc,  g_ropec);
    cudaGetSymbolAddress((void**)&rs,  g_ropes);
    cudaGetSymbolAddress((void**)&xh,  g_xh);
    cudaGetSymbolAddress((void**)&xl,  g_xl);
    cudaGetSymbolAddress((void**)&wh,  g_wh);
    cudaGetSymbolAddress((void**)&qh,  g_qh);
    cudaGetSymbolAddress((void**)&ql,  g_ql);
    cudaGetSymbolAddress((void**)&kh,  g_kh);
    cudaGetSymbolAddress((void**)&vh,  g_vh);
    cudaGetSymbolAddress((void**)&aoh, g_aoh);
    cudaGetSymbolAddress((void**)&aol, g_aol);

    static bool attr_done = false;
    if (!attr_done) {
        cudaFuncSetAttribute(gemm_mma<0>, cudaFuncAttributeMaxDynamicSharedMemorySize, GEMM_SMEM);
        cudaFuncSetAttribute(gemm_mma<3>, cudaFuncAttributeMaxDynamicSharedMemorySize, GEMM_SMEM);
        cudaFuncSetAttribute(attn_mma, cudaFuncAttributeMaxDynamicSharedMemorySize, ATTN_SMEM_BYTES);
        attr_done = true;
    }

    rope_table_kernel<<<(SEQ*32)/256, 256>>>(pos, rc, rs);
    {
        dim3 gc(1024, 8);
        convall_kernel<<<gc, 256>>>(x, wq, wk, wv, wo, xh, xl, wh);
    }

    const size_t WN = (size_t)DMODEL*DMODEL;

    dim3 gqkv(DMODEL/128, M_TOT/128, 3);
    gemm_mma<3><<<gqkv, 256, GEMM_SMEM>>>(xh, xl, wh,
                                          nullptr, qh, ql, kh, vh, rc, rs);

    dim3 ga(SEQ/128, BATCH*NHEADS);
    attn_mma<<<ga, 256, ATTN_SMEM_BYTES>>>(qh, ql, kh, vh, aoh, aol);

    dim3 gg(DMODEL/128, M_TOT/128);
    gemm_mma<0><<<gg, 256, GEMM_SMEM>>>(aoh, aol, wh + 3*WN,
                                        out, nullptr, nullptr, nullptr, nullptr, rc, rs);
}

// round 13
// speedup vs baseline: 4.7553x; 1.0861x over previous
#include <cuda_runtime.h>
#include <cuda_fp16.h>
#include <math.h>
#include <cstdint>

#define BATCH   2
#define SEQ     2048
#define DMODEL  1024
#define NHEADS  16
#define DKH     64
#define M_TOT   (BATCH*SEQ)   // 4096
#define QKV_ELEMS (BATCH*NHEADS*SEQ*DKH)

// ---------------- scratch (static device globals; no allocs) ----------------
__device__ __align__(256) __half g_xh[M_TOT*DMODEL];
__device__ __align__(256) __half g_xl[M_TOT*DMODEL];
__device__ __align__(256) __half g_wh[4*DMODEL*DMODEL];   // weights single fp16
__device__ __align__(256) __half g_qh[QKV_ELEMS];
__device__ __align__(256) __half g_ql[QKV_ELEMS];
__device__ __align__(256) __half g_kh[QKV_ELEMS];         // K single fp16
__device__ __align__(256) __half g_vh[QKV_ELEMS];         // V single fp16
__device__ __align__(256) __half g_aoh[M_TOT*DMODEL];     // attention out single fp16
__device__ float g_ropec[SEQ*32];   // [s][ip]
__device__ float g_ropes[SEQ*32];

// ---------------- PTX helpers ----------------
__device__ __forceinline__ uint32_t smem_u32(const void* p) {
    uint32_t a;
    asm("{ .reg .u64 t; cvta.to.shared.u64 t, %1; cvt.u32.u64 %0, t; }" : "=r"(a) : "l"(p));
    return a;
}
__device__ __forceinline__ void cp16(uint32_t dst, const void* src) {
    asm volatile("cp.async.cg.shared.global [%0], [%1], 16;" :: "r"(dst), "l"(src) : "memory");
}
#define CP_COMMIT() asm volatile("cp.async.commit_group;" ::: "memory")
template<int N>
__device__ __forceinline__ void cp_wait() {
    asm volatile("cp.async.wait_group %0;" :: "n"(N) : "memory");
}
__device__ __forceinline__ void ldsm_x4(uint32_t& r0, uint32_t& r1, uint32_t& r2,
                                        uint32_t& r3, uint32_t addr) {
    asm volatile("ldmatrix.sync.aligned.m8n8.x4.shared.b16 {%0,%1,%2,%3}, [%4];"
                 : "=r"(r0), "=r"(r1), "=r"(r2), "=r"(r3) : "r"(addr));
}
__device__ __forceinline__ void ldsm_x4t(uint32_t& r0, uint32_t& r1, uint32_t& r2,
                                         uint32_t& r3, uint32_t addr) {
    asm volatile("ldmatrix.sync.aligned.m8n8.x4.trans.shared.b16 {%0,%1,%2,%3}, [%4];"
                 : "=r"(r0), "=r"(r1), "=r"(r2), "=r"(r3) : "r"(addr));
}
__device__ __forceinline__ void mma_f16(float* c, const uint32_t* a, const uint32_t* b) {
    asm volatile("mma.sync.aligned.m16n8k16.row.col.f32.f16.f16.f32 "
                 "{%0,%1,%2,%3}, {%4,%5,%6,%7}, {%8,%9}, {%0,%1,%2,%3};"
                 : "+f"(c[0]), "+f"(c[1]), "+f"(c[2]), "+f"(c[3])
                 : "r"(a[0]), "r"(a[1]), "r"(a[2]), "r"(a[3]), "r"(b[0]), "r"(b[1]));
}
__device__ __forceinline__ uint32_t pack_h2(float a, float b) {
    __half2 h = __floats2half2_rn(a, b);
    return *(uint32_t*)&h;
}
__device__ __forceinline__ uint32_t ex2_h2(uint32_t x) {
    uint32_t r;
    asm("ex2.approx.f16x2 %0, %1;" : "=r"(r) : "r"(x));
    return r;
}
// split pair of floats into packed fp16x2 hi + lo residual (~22-bit effective)
__device__ __forceinline__ void split2h(float a, float b, uint32_t& hi, uint32_t& lo) {
    __half2 h = __floats2half2_rn(a, b);
    float ha = __low2float(h), hb = __high2float(h);
    __half2 l = __floats2half2_rn(a - ha, b - hb);
    hi = *(uint32_t*)&h;
    lo = *(uint32_t*)&l;
}

// ---------------- fused prep: x (4 quarters, split) + 4 weights (single fp16) ----------------
__global__ void convall_kernel(const float* __restrict__ x,
                               const float* __restrict__ w0, const float* __restrict__ w1,
                               const float* __restrict__ w2, const float* __restrict__ w3,
                               __half* __restrict__ xh, __half* __restrict__ xl,
                               __half* __restrict__ wh)
{
    const int y = blockIdx.y;
    int i = blockIdx.x * blockDim.x + threadIdx.x;
    if (y < 4) {
        const float* src = x + (size_t)y * (M_TOT*DMODEL/4);
        size_t off = (size_t)y * (M_TOT*DMODEL/4);
        float4 v = *(const float4*)(src + (size_t)i*4);
        uint32_t h0, l0, h1, l1;
        split2h(v.x, v.y, h0, l0);
        split2h(v.z, v.w, h1, l1);
        *(uint32_t*)(xh + off + (size_t)i*4)     = h0;
        *(uint32_t*)(xh + off + (size_t)i*4 + 2) = h1;
        *(uint32_t*)(xl + off + (size_t)i*4)     = l0;
        *(uint32_t*)(xl + off + (size_t)i*4 + 2) = l1;
    } else {
        const float* ws[4] = {w0, w1, w2, w3};
        const float* src = ws[y-4];
        size_t off = (size_t)(y-4) * DMODEL * DMODEL;
        float4 v = *(const float4*)(src + (size_t)i*4);
        *(uint32_t*)(wh + off + (size_t)i*4)     = pack_h2(v.x, v.y);
        *(uint32_t*)(wh + off + (size_t)i*4 + 2) = pack_h2(v.z, v.w);
    }
}

__global__ void rope_table_kernel(const int* __restrict__ pos,
                                  float* __restrict__ cosT, float* __restrict__ sinT)
{
    int idx = blockIdx.x * blockDim.x + threadIdx.x;
    int s  = idx >> 5;
    int ip = idx & 31;
    double invf = exp2(-(double)ip * 0.41524101186092028);  // log2(10000)/32
    float ang = (float)pos[s] * (float)invf;
    float sn, cs;
    sincosf(ang, &sn, &cs);
    cosT[idx] = cs;
    sinT[idx] = sn;
}

// ---------------- fp16 GEMM, KC=32, 3-stage ring, one barrier per chunk ----------------
// MODE 0: single-pass A (fp16), row-major fp32 C (output projection)
// MODE 3: split-A 2-pass, fused QKV (z=0 Q hi/lo + RoPE, z=1 K fp16 + RoPE, z=2 V fp16)
#define NKCH (DMODEL/32)          // 32
#define GROW 40                   // halves per row (80B; conflict-free ldsm)
#define GT_BYTES (128*GROW*2)     // 10240

template<int MODE>
__global__ __launch_bounds__(256, 2)
void gemm_mma(const __half* __restrict__ Ahi, const __half* __restrict__ Alo,
              const __half* __restrict__ B_,
              float* __restrict__ C,
              __half* __restrict__ Qhi, __half* __restrict__ Qlo,
              __half* __restrict__ Kout, __half* __restrict__ Vout,
              const float* __restrict__ ropec, const float* __restrict__ ropes)
{
    constexpr bool SPLITA = (MODE == 3);
    constexpr int OFF_B = SPLITA ? 2*GT_BYTES : GT_BYTES;
    constexpr int STG_BYTES = SPLITA ? 3*GT_BYTES : 2*GT_BYTES;

    extern __shared__ __half smh[];
    const uint32_t sbase = smem_u32(smh);
    const int tid  = threadIdx.x;
    const int wid  = tid >> 5;
    const int lane = tid & 31;
    const int bm = blockIdx.y, bn = blockIdx.x;
    const int wm = wid & 3;
    const int wn = wid >> 2;

    const __half* Bw = B_;
    bool do_rope = false;
    int zsel = 0;
    if (MODE == 3) {
        zsel = blockIdx.z;
        Bw = B_ + (size_t)zsel * DMODEL * DMODEL;
        do_rope = (zsel < 2);
    }

    float acc[2][8][4];
    #pragma unroll
    for (int mt = 0; mt < 2; mt++)
        #pragma unroll
        for (int nt = 0; nt < 8; nt++)
            #pragma unroll
            for (int j = 0; j < 4; j++) acc[mt][nt][j] = 0.f;

    const __half* Ah = Ahi + (size_t)(bm*128)*DMODEL;
    const __half* Al = SPLITA ? (Alo + (size_t)(bm*128)*DMODEL) : nullptr;
    const __half* Bh = Bw  + (size_t)(bn*128)*DMODEL;

    // loader: thread owns rows rb, rb+64; chunk lc (16B units over 64B of KC=32)
    const int lc = tid & 3;
    const int rb = tid >> 2;              // 0..63
    const __half* SA = Ah + (size_t)rb*DMODEL + lc*8;
    const __half* SAl = SPLITA ? (Al + (size_t)rb*DMODEL + lc*8) : nullptr;
    const __half* SB = Bh + (size_t)rb*DMODEL + lc*8;
    const uint32_t dsl = sbase + (uint32_t)(rb*GROW + lc*8)*2;
    const uint32_t rowhop = (uint32_t)(64*GROW)*2;
    const size_t   srchop = (size_t)64*DMODEL;

    auto load_stage = [&](int stg, int kc) {
        const uint32_t d = dsl + stg*STG_BYTES;
        const int ko = kc*32;
        cp16(d,              SA + ko);
        cp16(d + rowhop,     SA + srchop + ko);
        if (SPLITA) {
            cp16(d + GT_BYTES,          SAl + ko);
            cp16(d + GT_BYTES + rowhop, SAl + srchop + ko);
        }
        cp16(d + OFF_B,          SB + ko);
        cp16(d + OFF_B + rowhop, SB + srchop + ko);
        CP_COMMIT();
    };

    load_stage(0, 0);
    load_stage(1, 1);

    const int a_row   = wm*32 + (lane & 15);
    const int a_co    = (lane >> 4) * 8;
    const int b_row_p = wn*64 + (lane & 7) + ((lane >> 4) << 3);
    const int b_co    = ((lane >> 3) & 1) * 8;

    for (int kc = 0; kc < NKCH; kc++) {
        if (kc == NKCH-1) cp_wait<0>(); else cp_wait<1>();
        __syncthreads();
        if (kc + 2 < NKCH) load_stage((kc + 2) % 3, kc + 2);
        const uint32_t sbk = sbase + (kc % 3)*STG_BYTES;

        #pragma unroll
        for (int ks = 0; ks < 2; ks++) {
            const int kof = ks*16;
            uint32_t ah[2][4], al[2][4];
            #pragma unroll
            for (int mt = 0; mt < 2; mt++) {
                uint32_t aaddr = sbk + (uint32_t)(((a_row + mt*16)*GROW + kof + a_co)*2);
                ldsm_x4(ah[mt][0], ah[mt][1], ah[mt][2], ah[mt][3], aaddr);
                if (SPLITA)
                    ldsm_x4(al[mt][0], al[mt][1], al[mt][2], al[mt][3], aaddr + GT_BYTES);
            }
            #pragma unroll
            for (int pp = 0; pp < 2; pp++) {
                uint32_t b4[2][4];
                #pragma unroll
                for (int i = 0; i < 2; i++) {
                    int p = 2*pp + i;
                    uint32_t baddr = sbk + OFF_B +
                                     (uint32_t)(((b_row_p + p*16)*GROW + kof + b_co)*2);
                    ldsm_x4(b4[i][0], b4[i][1], b4[i][2], b4[i][3], baddr);
                }
                #pragma unroll
                for (int i = 0; i < 2; i++) {
                    int p = 2*pp + i;
                    #pragma unroll
                    for (int mt = 0; mt < 2; mt++) {
                        mma_f16(acc[mt][2*p],   ah[mt], b4[i]);
                        mma_f16(acc[mt][2*p+1], ah[mt], b4[i]+2);
                    }
                }
                if (SPLITA) {
                    #pragma unroll
                    for (int i = 0; i < 2; i++) {
                        int p = 2*pp + i;
                        #pragma unroll
                        for (int mt = 0; mt < 2; mt++) {
                            mma_f16(acc[mt][2*p],   al[mt], b4[i]);
                            mma_f16(acc[mt][2*p+1], al[mt], b4[i]+2);
                        }
                    }
                }
            }
        }
    }

    // ---- epilogue ----
    const int row_base = bm*128 + wm*32;
    const int col_base = bn*128 + wn*64;
    #pragma unroll
    for (int mt = 0; mt < 2; mt++) {
        #pragma unroll
        for (int rg = 0; rg < 2; rg++) {
            int row = row_base + mt*16 + rg*8 + (lane >> 2);
            int s = row & (SEQ-1);
            int b = row >> 11;
            #pragma unroll
            for (int nt = 0; nt < 8; nt++) {
                int col = col_base + nt*8 + 2*(lane & 3);
                float e = acc[mt][nt][rg*2];
                float o = acc[mt][nt][rg*2+1];
                if (MODE == 3 && do_rope) {
                    int ip = (col & 63) >> 1;
                    float cs = ropec[s*32 + ip];
                    float sn = ropes[s*32 + ip];
                    float ne = e*cs - o*sn;
                    float no = e*sn + o*cs;
                    e = ne; o = no;
                }
                if (MODE == 0) {
                    *(float2*)(C + (size_t)row*DMODEL + col) = make_float2(e, o);
                } else {
                    int h = col >> 6, dk = col & 63;
                    size_t idx = ((size_t)(b*NHEADS + h)*SEQ + s)*DKH + dk;
                    if (zsel == 0) {
                        uint32_t hi, lo;
                        split2h(e, o, hi, lo);
                        *(uint32_t*)(Qhi + idx) = hi;
                        *(uint32_t*)(Qlo + idx) = lo;
                    } else if (zsel == 1) {
                        *(uint32_t*)(Kout + idx) = pack_h2(e, o);
                    } else {
                        *(uint32_t*)(Vout + idx) = pack_h2(e, o);
                    }
                }
            }
        }
    }
}

// ---------------- fp16 flash attention: 3-stage KV ring, one sync per tile ----------------
// smem (half units): Qh[128][72] @0, Ql @9216; 3 KV stages @18432: {K, V} 64x72 each
#define A_STR 72
#define A_SQL 9216
#define A_SST 18432
#define A_BUF 4608                 // 64*72
#define A_STG (2*A_BUF)            // 9216 halves per stage
#define ATTN_SMEM_BYTES ((A_SST + 3*A_STG)*2)   // 92160
#define SCALE_LOG2 0.18033688011112042f         // 0.125 * log2(e)

__global__ __launch_bounds__(256, 2)
void attn_mma(const __half* __restrict__ Qh_g, const __half* __restrict__ Ql_g,
              const __half* __restrict__ Kh_g, const __half* __restrict__ Vh_g,
              __half* __restrict__ Oh)
{
    extern __shared__ __half smh[];
    const uint32_t sb = smem_u32(smh);
    const int tid  = threadIdx.x;
    const int wq   = tid >> 5;
    const int lane = tid & 31;
    const int bh   = blockIdx.y;
    const int qt   = gridDim.x - 1 - blockIdx.x;
    const int q0   = qt * 128;
    const size_t boff = (size_t)bh*SEQ*DKH;

    // ---- Q (hi+lo) ----
    #pragma unroll
    for (int l = 0; l < 4; l++) {
        int item = tid + l*256;
        int r = item >> 3;
        int c = item & 7;
        uint32_t d = sb + (uint32_t)(r*A_STR + c*8)*2;
        const __half* src = Qh_g + boff + (size_t)(q0+r)*DKH + c*8;
        cp16(d, src);
        cp16(d + A_SQL*2, Ql_g + (src - Qh_g));
    }
    CP_COMMIT();

    const int bsel = tid >> 7;
    const int loc  = tid & 127;
    const int vc   = loc & 7;
    const int vr   = loc >> 3;
    const __half* Pk = bsel ? Vh_g : Kh_g;
    const __half* Pkv = Pk + boff + (size_t)vr*DKH + vc*8;
    const uint32_t dkv = sb + (uint32_t)((A_SST + bsel*A_BUF + vr*A_STR + vc*8)*2);

    auto load_kv = [&](int stg, int t) {
        const __half* s = Pkv + (size_t)(t*64)*DKH;
        const uint32_t d = dkv + stg*(A_STG*2);
        #pragma unroll
        for (int i = 0; i < 4; i++)
            cp16(d + i*(16*A_STR*2), s + (size_t)(i*16)*DKH);
        CP_COMMIT();
    };

    const int nkt = qt*2 + 2;
    load_kv(0, 0);
    load_kv(1, 1);

    float sc[8][4];
    float o[8][4];
    #pragma unroll
    for (int nt = 0; nt < 8; nt++)
        #pragma unroll
        for (int j = 0; j < 4; j++) o[nt][j] = 0.f;
    float m0 = -INFINITY, m1 = -INFINITY, l0 = 0.f, l1 = 0.f;

    const uint32_t ONES2 = 0x3C003C00u;
    uint32_t ones_b[2] = {ONES2, ONES2};

    for (int t = 0; t < nkt; t++) {
        const int k0 = t * 64;
        if (t == nkt-1) cp_wait<0>(); else cp_wait<1>();
        __syncthreads();
        if (t + 2 < nkt) load_kv((t+2) % 3, t+2);
        const uint32_t stb = sb + (uint32_t)((A_SST + (t % 3)*A_STG)*2);

        const bool active = (k0 <= q0 + wq*16 + 15);
        if (active) {
            // ---- S = Q K^T (split-Q, 2 passes) ----
            #pragma unroll
            for (int nt = 0; nt < 8; nt++)
                #pragma unroll
                for (int j = 0; j < 4; j++) sc[nt][j] = 0.f;
            #pragma unroll
            for (int kt = 0; kt < 4; kt++) {
                uint32_t ah[4], al[4];
                uint32_t aaddr = sb + (uint32_t)(((wq*16 + (lane & 15))*A_STR + kt*16 + (lane >> 4)*8)*2);
                ldsm_x4(ah[0], ah[1], ah[2], ah[3], aaddr);
                ldsm_x4(al[0], al[1], al[2], al[3], aaddr + A_SQL*2);
                #pragma unroll
                for (int pp = 0; pp < 2; pp++) {
                    uint32_t kh4[2][4];
                    #pragma unroll
                    for (int i = 0; i < 2; i++) {
                        int p = 2*pp + i;
                        int brow = p*16 + (lane & 7) + ((lane >> 4) << 3);
                        uint32_t baddr = stb + (uint32_t)((brow*A_STR + kt*16 + ((lane >> 3) & 1)*8)*2);
                        ldsm_x4(kh4[i][0], kh4[i][1], kh4[i][2], kh4[i][3], baddr);
                    }
                    #pragma unroll
                    for (int i = 0; i < 2; i++) {
                        int p = 2*pp + i;
                        mma_f16(sc[2*p],   ah, kh4[i]);
                        mma_f16(sc[2*p+1], ah, kh4[i]+2);
                    }
                    #pragma unroll
                    for (int i = 0; i < 2; i++) {
                        int p = 2*pp + i;
                        mma_f16(sc[2*p],   al, kh4[i]);
                        mma_f16(sc[2*p+1], al, kh4[i]+2);
                    }
                }
            }

            // ---- softmax: scale/mask/max, P = ex2.f16x2, sums via ones-MMA ----
            const int qrow = q0 + wq*16 + (lane >> 2);
            const bool needmask = (k0 + 63 > q0 + wq*16);
            float mx0 = -1e30f, mx1 = -1e30f;
            #pragma unroll
            for (int nt = 0; nt < 8; nt++) {
                #pragma unroll
                for (int j = 0; j < 4; j++) sc[nt][j] *= SCALE_LOG2;
                if (needmask) {
                    int kcol = k0 + nt*8 + 2*(lane & 3);
                    if (kcol+0 > qrow)   sc[nt][0] = -1e30f;
                    if (kcol+1 > qrow)   sc[nt][1] = -1e30f;
                    if (kcol+0 > qrow+8) sc[nt][2] = -1e30f;
                    if (kcol+1 > qrow+8) sc[nt][3] = -1e30f;
                }
                mx0 = fmaxf(mx0, fmaxf(sc[nt][0], sc[nt][1]));
                mx1 = fmaxf(mx1, fmaxf(sc[nt][2], sc[nt][3]));
            }
            mx0 = fmaxf(mx0, __shfl_xor_sync(0xffffffffu, mx0, 1));
            mx0 = fmaxf(mx0, __shfl_xor_sync(0xffffffffu, mx0, 2));
            mx1 = fmaxf(mx1, __shfl_xor_sync(0xffffffffu, mx1, 1));
            mx1 = fmaxf(mx1, __shfl_xor_sync(0xffffffffu, mx1, 2));
            float mn0 = fmaxf(m0, mx0), mn1 = fmaxf(m1, mx1);
            float f0 = exp2f(m0 - mn0), f1 = exp2f(m1 - mn1);
            m0 = mn0; m1 = mn1;

            uint32_t pr[8][2];
            #pragma unroll
            for (int nt = 0; nt < 8; nt++) {
                pr[nt][0] = ex2_h2(pack_h2(sc[nt][0] - mn0, sc[nt][1] - mn0));
                pr[nt][1] = ex2_h2(pack_h2(sc[nt][2] - mn1, sc[nt][3] - mn1));
            }

            float ps[4] = {0.f, 0.f, 0.f, 0.f};
            #pragma unroll
            for (int kt = 0; kt < 4; kt++) {
                uint32_t pf[4] = {pr[2*kt][0], pr[2*kt][1], pr[2*kt+1][0], pr[2*kt+1][1]};
                mma_f16(ps, pf, ones_b);
            }
            l0 = l0*f0 + ps[0];
            l1 = l1*f1 + ps[2];
            #pragma unroll
            for (int nt = 0; nt < 8; nt++) {
                o[nt][0] *= f0; o[nt][1] *= f0;
                o[nt][2] *= f1; o[nt][3] *= f1;
            }

            // ---- O += P V (single-pass fp16) ----
            #pragma unroll
            for (int kt = 0; kt < 4; kt++) {
                uint32_t pf[4] = {pr[2*kt][0], pr[2*kt][1], pr[2*kt+1][0], pr[2*kt+1][1]};
                #pragma unroll
                for (int pp = 0; pp < 2; pp++) {
                    uint32_t vh4[2][4];
                    #pragma unroll
                    for (int i = 0; i < 2; i++) {
                        int dp = 2*pp + i;
                        uint32_t vaddr = stb + (uint32_t)((A_BUF +
                                         (kt*16 + (lane & 15))*A_STR +
                                         dp*16 + ((lane >> 4) & 1)*8)*2);
                        ldsm_x4t(vh4[i][0], vh4[i][1], vh4[i][2], vh4[i][3], vaddr);
                    }
                    #pragma unroll
                    for (int i = 0; i < 2; i++) {
                        int dp = 2*pp + i;
                        mma_f16(o[2*dp],   pf, vh4[i]);
                        mma_f16(o[2*dp+1], pf, vh4[i]+2);
                    }
                }
            }
        }
    }

    // ---- epilogue: single fp16 ----
    const int b = bh >> 4, h = bh & 15;
    const float i0 = 1.f / l0, i1 = 1.f / l1;
    const int srow = q0 + wq*16 + (lane >> 2);
    const size_t base0 = ((size_t)(b*SEQ + srow))*DMODEL + h*64;
    const size_t base1 = base0 + (size_t)8*DMODEL;
    #pragma unroll
    for (int nt = 0; nt < 8; nt++) {
        int col = nt*8 + 2*(lane & 3);
        *(uint32_t*)(Oh + base0 + col) = pack_h2(o[nt][0]*i0, o[nt][1]*i0);
        *(uint32_t*)(Oh + base1 + col) = pack_h2(o[nt][2]*i1, o[nt][3]*i1);
    }
}

// ---------------- launch ----------------
extern "C" void kernel_launch(void* const* d_in, const int* in_sizes, int n_in,
                              void* d_out, int out_size)
{
    const float* x  = (const float*)d_in[0];
    const float* wq = (const float*)d_in[1];
    const float* wk = (const float*)d_in[2];
    const float* wv = (const float*)d_in[3];
    const float* wo = (const float*)d_in[4];
    const int*  pos = (const int*)d_in[5];
    float* out = (float*)d_out;

    float *rc, *rs;
    __half *xh, *xl, *wh, *qh, *ql, *kh, *vh, *aoh;
    cudaGetSymbolAddress((void**)&rc,  g_ropec);
    cudaGetSymbolAddress((void**)&rs,  g_ropes);
    cudaGetSymbolAddress((void**)&xh,  g_xh);
    cudaGetSymbolAddress((void**)&xl,  g_xl);
    cudaGetSymbolAddress((void**)&wh,  g_wh);
    cudaGetSymbolAddress((void**)&qh,  g_qh);
    cudaGetSymbolAddress((void**)&ql,  g_ql);
    cudaGetSymbolAddress((void**)&kh,  g_kh);
    cudaGetSymbolAddress((void**)&vh,  g_vh);
    cudaGetSymbolAddress((void**)&aoh, g_aoh);

    const int SMEM3 = 3*(3*GT_BYTES);   // 92160 (split-A QKV)
    const int SMEM0 = 3*(2*GT_BYTES);   // 61440 (single-A out-proj)

    static bool attr_done = false;
    if (!attr_done) {
        cudaFuncSetAttribute(gemm_mma<0>, cudaFuncAttributeMaxDynamicSharedMemorySize, SMEM0);
        cudaFuncSetAttribute(gemm_mma<3>, cudaFuncAttributeMaxDynamicSharedMemorySize, SMEM3);
        cudaFuncSetAttribute(attn_mma, cudaFuncAttributeMaxDynamicSharedMemorySize, ATTN_SMEM_BYTES);
        attr_done = true;
    }

    rope_table_kernel<<<(SEQ*32)/256, 256>>>(pos, rc, rs);
    {
        dim3 gc(1024, 8);
        convall_kernel<<<gc, 256>>>(x, wq, wk, wv, wo, xh, xl, wh);
    }

    const size_t WN = (size_t)DMODEL*DMODEL;

    dim3 gqkv(DMODEL/128, M_TOT/128, 3);
    gemm_mma<3><<<gqkv, 256, SMEM3>>>(xh, xl, wh,
                                      nullptr, qh, ql, kh, vh, rc, rs);

    dim3 ga(SEQ/128, BATCH*NHEADS);
    attn_mma<<<ga, 256, ATTN_SMEM_BYTES>>>(qh, ql, kh, vh, aoh);

    dim3 gg(DMODEL/128, M_TOT/128);
    gemm_mma<0><<<gg, 256, SMEM0>>>(aoh, nullptr, wh + 3*WN,
                                    out, nullptr, nullptr, nullptr, nullptr, rc, rs);
}

// round 14
// speedup vs baseline: 5.0781x; 1.0679x over previous
#include <cuda_runtime.h>
#include <cuda_fp16.h>
#include <math.h>
#include <cstdint>

#define BATCH   2
#define SEQ     2048
#define DMODEL  1024
#define NHEADS  16
#define DKH     64
#define M_TOT   (BATCH*SEQ)   // 4096
#define QKV_ELEMS (BATCH*NHEADS*SEQ*DKH)

// ---------------- scratch (static device globals; no allocs) ----------------
__device__ __align__(256) __half g_xh[M_TOT*DMODEL];
__device__ __align__(256) __half g_xl[M_TOT*DMODEL];
__device__ __align__(256) __half g_wh[4*DMODEL*DMODEL];   // weights single fp16
__device__ __align__(256) __half g_qh[QKV_ELEMS];
__device__ __align__(256) __half g_ql[QKV_ELEMS];
__device__ __align__(256) __half g_kh[QKV_ELEMS];         // K single fp16
__device__ __align__(256) __half g_vh[QKV_ELEMS];         // V single fp16
__device__ __align__(256) __half g_aoh[M_TOT*DMODEL];     // attention out single fp16
__device__ float g_ropec[SEQ*32];   // [s][ip]
__device__ float g_ropes[SEQ*32];

// ---------------- PTX helpers ----------------
__device__ __forceinline__ uint32_t smem_u32(const void* p) {
    uint32_t a;
    asm("{ .reg .u64 t; cvta.to.shared.u64 t, %1; cvt.u32.u64 %0, t; }" : "=r"(a) : "l"(p));
    return a;
}
__device__ __forceinline__ void cp16(uint32_t dst, const void* src) {
    asm volatile("cp.async.cg.shared.global [%0], [%1], 16;" :: "r"(dst), "l"(src) : "memory");
}
#define CP_COMMIT() asm volatile("cp.async.commit_group;" ::: "memory")
template<int N>
__device__ __forceinline__ void cp_wait() {
    asm volatile("cp.async.wait_group %0;" :: "n"(N) : "memory");
}
__device__ __forceinline__ void ldsm_x4(uint32_t& r0, uint32_t& r1, uint32_t& r2,
                                        uint32_t& r3, uint32_t addr) {
    asm volatile("ldmatrix.sync.aligned.m8n8.x4.shared.b16 {%0,%1,%2,%3}, [%4];"
                 : "=r"(r0), "=r"(r1), "=r"(r2), "=r"(r3) : "r"(addr));
}
__device__ __forceinline__ void ldsm_x4t(uint32_t& r0, uint32_t& r1, uint32_t& r2,
                                         uint32_t& r3, uint32_t addr) {
    asm volatile("ldmatrix.sync.aligned.m8n8.x4.trans.shared.b16 {%0,%1,%2,%3}, [%4];"
                 : "=r"(r0), "=r"(r1), "=r"(r2), "=r"(r3) : "r"(addr));
}
__device__ __forceinline__ void mma_f16(float* c, const uint32_t* a, const uint32_t* b) {
    asm volatile("mma.sync.aligned.m16n8k16.row.col.f32.f16.f16.f32 "
                 "{%0,%1,%2,%3}, {%4,%5,%6,%7}, {%8,%9}, {%0,%1,%2,%3};"
                 : "+f"(c[0]), "+f"(c[1]), "+f"(c[2]), "+f"(c[3])
                 : "r"(a[0]), "r"(a[1]), "r"(a[2]), "r"(a[3]), "r"(b[0]), "r"(b[1]));
}
__device__ __forceinline__ uint32_t pack_h2(float a, float b) {
    __half2 h = __floats2half2_rn(a, b);
    return *(uint32_t*)&h;
}
__device__ __forceinline__ uint32_t ex2_h2(uint32_t x) {
    uint32_t r;
    asm("ex2.approx.f16x2 %0, %1;" : "=r"(r) : "r"(x));
    return r;
}
// split pair of floats into packed fp16x2 hi + lo residual (~22-bit effective)
__device__ __forceinline__ void split2h(float a, float b, uint32_t& hi, uint32_t& lo) {
    __half2 h = __floats2half2_rn(a, b);
    float ha = __low2float(h), hb = __high2float(h);
    __half2 l = __floats2half2_rn(a - ha, b - hb);
    hi = *(uint32_t*)&h;
    lo = *(uint32_t*)&l;
}

// ---------------- fused prep: x (4 quarters, split) + 4 weights + rope table ----------------
__global__ void convall_kernel(const float* __restrict__ x,
                               const float* __restrict__ w0, const float* __restrict__ w1,
                               const float* __restrict__ w2, const float* __restrict__ w3,
                               __half* __restrict__ xh, __half* __restrict__ xl,
                               __half* __restrict__ wh,
                               const int* __restrict__ pos,
                               float* __restrict__ cosT, float* __restrict__ sinT)
{
    const int y = blockIdx.y;
    int i = blockIdx.x * blockDim.x + threadIdx.x;
    if (y < 4) {
        const float* src = x + (size_t)y * (M_TOT*DMODEL/4);
        size_t off = (size_t)y * (M_TOT*DMODEL/4);
        float4 v = *(const float4*)(src + (size_t)i*4);
        uint32_t h0, l0, h1, l1;
        split2h(v.x, v.y, h0, l0);
        split2h(v.z, v.w, h1, l1);
        *(uint32_t*)(xh + off + (size_t)i*4)     = h0;
        *(uint32_t*)(xh + off + (size_t)i*4 + 2) = h1;
        *(uint32_t*)(xl + off + (size_t)i*4)     = l0;
        *(uint32_t*)(xl + off + (size_t)i*4 + 2) = l1;
    } else if (y < 8) {
        const float* ws[4] = {w0, w1, w2, w3};
        const float* src = ws[y-4];
        size_t off = (size_t)(y-4) * DMODEL * DMODEL;
        float4 v = *(const float4*)(src + (size_t)i*4);
        *(uint32_t*)(wh + off + (size_t)i*4)     = pack_h2(v.x, v.y);
        *(uint32_t*)(wh + off + (size_t)i*4 + 2) = pack_h2(v.z, v.w);
    } else {
        if (i >= SEQ*32) return;
        int s  = i >> 5;
        int ip = i & 31;
        double invf = exp2(-(double)ip * 0.41524101186092028);  // log2(10000)/32
        float ang = (float)pos[s] * (float)invf;
        float sn, cs;
        sincosf(ang, &sn, &cs);
        cosT[i] = cs;
        sinT[i] = sn;
    }
}

// ---------------- fp16 GEMM, KC=64, 2-stage ring, one barrier per chunk ----------------
// MODE 0: single-pass A (fp16), row-major fp32 C (output projection)
// MODE 3: split-A 2-pass, fused QKV (z=0 Q hi/lo + RoPE, z=1 K fp16 + RoPE, z=2 V fp16)
#define NKCH (DMODEL/64)          // 16
#define GROW 72                   // halves per row (144B = 9x16B, conflict-free ldsm)
#define GT_BYTES (128*GROW*2)     // 18432

template<int MODE>
__global__ __launch_bounds__(256, 2)
void gemm_mma(const __half* __restrict__ Ahi, const __half* __restrict__ Alo,
              const __half* __restrict__ B_,
              float* __restrict__ C,
              __half* __restrict__ Qhi, __half* __restrict__ Qlo,
              __half* __restrict__ Kout, __half* __restrict__ Vout,
              const float* __restrict__ ropec, const float* __restrict__ ropes)
{
    constexpr bool SPLITA = (MODE == 3);
    constexpr int OFF_B = SPLITA ? 2*GT_BYTES : GT_BYTES;
    constexpr int STG_BYTES = SPLITA ? 3*GT_BYTES : 2*GT_BYTES;

    extern __shared__ __half smh[];
    const uint32_t sbase = smem_u32(smh);
    const int tid  = threadIdx.x;
    const int wid  = tid >> 5;
    const int lane = tid & 31;
    const int bm = blockIdx.y, bn = blockIdx.x;
    const int wm = wid & 3;
    const int wn = wid >> 2;

    const __half* Bw = B_;
    bool do_rope = false;
    int zsel = 0;
    if (MODE == 3) {
        zsel = blockIdx.z;
        Bw = B_ + (size_t)zsel * DMODEL * DMODEL;
        do_rope = (zsel < 2);
    }

    float acc[2][8][4];
    #pragma unroll
    for (int mt = 0; mt < 2; mt++)
        #pragma unroll
        for (int nt = 0; nt < 8; nt++)
            #pragma unroll
            for (int j = 0; j < 4; j++) acc[mt][nt][j] = 0.f;

    const __half* Ah = Ahi + (size_t)(bm*128)*DMODEL;
    const __half* Al = SPLITA ? (Alo + (size_t)(bm*128)*DMODEL) : nullptr;
    const __half* Bh = Bw  + (size_t)(bn*128)*DMODEL;

    // loader: thread owns rows rb+32i (i=0..3), chunk lc (16B units over 128B of KC=64)
    const int lc = tid & 7;
    const int rb = tid >> 3;              // 0..31
    const __half* SA  = Ah + (size_t)rb*DMODEL + lc*8;
    const __half* SAl = SPLITA ? (Al + (size_t)rb*DMODEL + lc*8) : nullptr;
    const __half* SB  = Bh + (size_t)rb*DMODEL + lc*8;
    const uint32_t dsl = sbase + (uint32_t)(rb*GROW + lc*8)*2;
    const uint32_t rowhop = (uint32_t)(32*GROW)*2;
    const size_t   srchop = (size_t)32*DMODEL;

    auto load_stage = [&](int stg, int kc) {
        const uint32_t d = dsl + stg*STG_BYTES;
        const int ko = kc*64;
        #pragma unroll
        for (int i = 0; i < 4; i++) {
            cp16(d + i*rowhop, SA + i*srchop + ko);
            if (SPLITA) cp16(d + GT_BYTES + i*rowhop, SAl + i*srchop + ko);
            cp16(d + OFF_B + i*rowhop, SB + i*srchop + ko);
        }
        CP_COMMIT();
    };

    load_stage(0, 0);

    const int a_row   = wm*32 + (lane & 15);
    const int a_co    = (lane >> 4) * 8;
    const int b_row_p = wn*64 + (lane & 7) + ((lane >> 4) << 3);
    const int b_co    = ((lane >> 3) & 1) * 8;

    for (int kc = 0; kc < NKCH; kc++) {
        cp_wait<0>();
        __syncthreads();
        if (kc + 1 < NKCH) load_stage((kc + 1) & 1, kc + 1);
        const uint32_t sbk = sbase + (kc & 1)*STG_BYTES;

        #pragma unroll
        for (int ks = 0; ks < 4; ks++) {
            const int kof = ks*16;
            uint32_t ah[2][4], al[2][4];
            #pragma unroll
            for (int mt = 0; mt < 2; mt++) {
                uint32_t aaddr = sbk + (uint32_t)(((a_row + mt*16)*GROW + kof + a_co)*2);
                ldsm_x4(ah[mt][0], ah[mt][1], ah[mt][2], ah[mt][3], aaddr);
                if (SPLITA)
                    ldsm_x4(al[mt][0], al[mt][1], al[mt][2], al[mt][3], aaddr + GT_BYTES);
            }
            #pragma unroll
            for (int pp = 0; pp < 2; pp++) {
                uint32_t b4[2][4];
                #pragma unroll
                for (int i = 0; i < 2; i++) {
                    int p = 2*pp + i;
                    uint32_t baddr = sbk + OFF_B +
                                     (uint32_t)(((b_row_p + p*16)*GROW + kof + b_co)*2);
                    ldsm_x4(b4[i][0], b4[i][1], b4[i][2], b4[i][3], baddr);
                }
                #pragma unroll
                for (int i = 0; i < 2; i++) {
                    int p = 2*pp + i;
                    #pragma unroll
                    for (int mt = 0; mt < 2; mt++) {
                        mma_f16(acc[mt][2*p],   ah[mt], b4[i]);
                        mma_f16(acc[mt][2*p+1], ah[mt], b4[i]+2);
                    }
                }
                if (SPLITA) {
                    #pragma unroll
                    for (int i = 0; i < 2; i++) {
                        int p = 2*pp + i;
                        #pragma unroll
                        for (int mt = 0; mt < 2; mt++) {
                            mma_f16(acc[mt][2*p],   al[mt], b4[i]);
                            mma_f16(acc[mt][2*p+1], al[mt], b4[i]+2);
                        }
                    }
                }
            }
        }
    }

    // ---- epilogue ----
    const int row_base = bm*128 + wm*32;
    const int col_base = bn*128 + wn*64;
    #pragma unroll
    for (int mt = 0; mt < 2; mt++) {
        #pragma unroll
        for (int rg = 0; rg < 2; rg++) {
            int row = row_base + mt*16 + rg*8 + (lane >> 2);
            int s = row & (SEQ-1);
            int b = row >> 11;
            #pragma unroll
            for (int nt = 0; nt < 8; nt++) {
                int col = col_base + nt*8 + 2*(lane & 3);
                float e = acc[mt][nt][rg*2];
                float o = acc[mt][nt][rg*2+1];
                if (MODE == 3 && do_rope) {
                    int ip = (col & 63) >> 1;
                    float cs = ropec[s*32 + ip];
                    float sn = ropes[s*32 + ip];
                    float ne = e*cs - o*sn;
                    float no = e*sn + o*cs;
                    e = ne; o = no;
                }
                if (MODE == 0) {
                    *(float2*)(C + (size_t)row*DMODEL + col) = make_float2(e, o);
                } else {
                    int h = col >> 6, dk = col & 63;
                    size_t idx = ((size_t)(b*NHEADS + h)*SEQ + s)*DKH + dk;
                    if (zsel == 0) {
                        uint32_t hi, lo;
                        split2h(e, o, hi, lo);
                        *(uint32_t*)(Qhi + idx) = hi;
                        *(uint32_t*)(Qlo + idx) = lo;
                    } else if (zsel == 1) {
                        *(uint32_t*)(Kout + idx) = pack_h2(e, o);
                    } else {
                        *(uint32_t*)(Vout + idx) = pack_h2(e, o);
                    }
                }
            }
        }
    }
}

// ---------------- fp16 flash attention: 128-key macro tiles, 2-stage ring ----------------
// smem (half units): Qh[128][72] @0, Ql @9216; 2 KV stages @18432: {K[128][72], V[128][72]}
#define A_STR 72
#define A_SQL 9216
#define A_SST 18432
#define A_KBUF 9216                // 128*72
#define A_STG (2*A_KBUF)           // 18432 halves per stage
#define ATTN_SMEM_BYTES ((A_SST + 2*A_STG)*2)   // 110592
#define SCALE_LOG2 0.18033688011112042f         // 0.125 * log2(e)

__global__ __launch_bounds__(256, 2)
void attn_mma(const __half* __restrict__ Qh_g, const __half* __restrict__ Ql_g,
              const __half* __restrict__ Kh_g, const __half* __restrict__ Vh_g,
              __half* __restrict__ Oh)
{
    extern __shared__ __half smh[];
    const uint32_t sb = smem_u32(smh);
    const int tid  = threadIdx.x;
    const int wq   = tid >> 5;
    const int lane = tid & 31;
    const int bh   = blockIdx.y;
    const int qt   = gridDim.x - 1 - blockIdx.x;
    const int q0   = qt * 128;
    const size_t boff = (size_t)bh*SEQ*DKH;

    // ---- Q (hi+lo) ----
    #pragma unroll
    for (int l = 0; l < 4; l++) {
        int item = tid + l*256;
        int r = item >> 3;
        int c = item & 7;
        uint32_t d = sb + (uint32_t)(r*A_STR + c*8)*2;
        const __half* src = Qh_g + boff + (size_t)(q0+r)*DKH + c*8;
        cp16(d, src);
        cp16(d + A_SQL*2, Ql_g + (src - Qh_g));
    }
    CP_COMMIT();

    // KV loader: bsel 0 -> K, 1 -> V; 128 rows each, 8 cp16/thread per macro tile
    const int bsel = tid >> 7;
    const int loc  = tid & 127;
    const int vc   = loc & 7;
    const int vr   = loc >> 3;          // 0..15
    const __half* Pk = bsel ? Vh_g : Kh_g;
    const __half* Pkv = Pk + boff + (size_t)vr*DKH + vc*8;
    const uint32_t dkv = sb + (uint32_t)((A_SST + bsel*A_KBUF + vr*A_STR + vc*8)*2);

    auto load_kv = [&](int stg, int mt) {
        const __half* s = Pkv + (size_t)(mt*128)*DKH;
        const uint32_t d = dkv + stg*(A_STG*2);
        #pragma unroll
        for (int i = 0; i < 8; i++)
            cp16(d + i*(16*A_STR*2), s + (size_t)(i*16)*DKH);
        CP_COMMIT();
    };

    const int nmt = qt + 1;
    load_kv(0, 0);

    float sc[8][4];
    float o[8][4];
    #pragma unroll
    for (int nt = 0; nt < 8; nt++)
        #pragma unroll
        for (int j = 0; j < 4; j++) o[nt][j] = 0.f;
    float m0 = -INFINITY, m1 = -INFINITY, l0 = 0.f, l1 = 0.f;

    const uint32_t ONES2 = 0x3C003C00u;
    uint32_t ones_b[2] = {ONES2, ONES2};

    for (int mt = 0; mt < nmt; mt++) {
        cp_wait<0>();
        __syncthreads();
        if (mt + 1 < nmt) load_kv((mt + 1) & 1, mt + 1);
        const uint32_t stb = sb + (uint32_t)((A_SST + (mt & 1)*A_STG)*2);

        #pragma unroll
        for (int st = 0; st < 2; st++) {
            const int k0 = mt*128 + st*64;
            if (k0 > q0 + wq*16 + 15) continue;   // fully masked for this warp
            const uint32_t ktb = stb + (uint32_t)(st*64*A_STR)*2;
            const uint32_t vtb = stb + (uint32_t)((A_KBUF + st*64*A_STR))*2;

            // ---- S = Q K^T (split-Q, 2 passes) ----
            #pragma unroll
            for (int nt = 0; nt < 8; nt++)
                #pragma unroll
                for (int j = 0; j < 4; j++) sc[nt][j] = 0.f;
            #pragma unroll
            for (int kt = 0; kt < 4; kt++) {
                uint32_t ah[4], al[4];
                uint32_t aaddr = sb + (uint32_t)(((wq*16 + (lane & 15))*A_STR + kt*16 + (lane >> 4)*8)*2);
                ldsm_x4(ah[0], ah[1], ah[2], ah[3], aaddr);
                ldsm_x4(al[0], al[1], al[2], al[3], aaddr + A_SQL*2);
                #pragma unroll
                for (int pp = 0; pp < 2; pp++) {
                    uint32_t kh4[2][4];
                    #pragma unroll
                    for (int i = 0; i < 2; i++) {
                        int p = 2*pp + i;
                        int brow = p*16 + (lane & 7) + ((lane >> 4) << 3);
                        uint32_t baddr = ktb + (uint32_t)((brow*A_STR + kt*16 + ((lane >> 3) & 1)*8)*2);
                        ldsm_x4(kh4[i][0], kh4[i][1], kh4[i][2], kh4[i][3], baddr);
                    }
                    #pragma unroll
                    for (int i = 0; i < 2; i++) {
                        int p = 2*pp + i;
                        mma_f16(sc[2*p],   ah, kh4[i]);
                        mma_f16(sc[2*p+1], ah, kh4[i]+2);
                    }
                    #pragma unroll
                    for (int i = 0; i < 2; i++) {
                        int p = 2*pp + i;
                        mma_f16(sc[2*p],   al, kh4[i]);
                        mma_f16(sc[2*p+1], al, kh4[i]+2);
                    }
                }
            }

            // ---- softmax: scale/mask/max, P = ex2.f16x2, sums via ones-MMA ----
            const int qrow = q0 + wq*16 + (lane >> 2);
            const bool needmask = (k0 + 63 > q0 + wq*16);
            float mx0 = -1e30f, mx1 = -1e30f;
            #pragma unroll
            for (int nt = 0; nt < 8; nt++) {
                #pragma unroll
                for (int j = 0; j < 4; j++) sc[nt][j] *= SCALE_LOG2;
                if (needmask) {
                    int kcol = k0 + nt*8 + 2*(lane & 3);
                    if (kcol+0 > qrow)   sc[nt][0] = -1e30f;
                    if (kcol+1 > qrow)   sc[nt][1] = -1e30f;
                    if (kcol+0 > qrow+8) sc[nt][2] = -1e30f;
                    if (kcol+1 > qrow+8) sc[nt][3] = -1e30f;
                }
                mx0 = fmaxf(mx0, fmaxf(sc[nt][0], sc[nt][1]));
                mx1 = fmaxf(mx1, fmaxf(sc[nt][2], sc[nt][3]));
            }
            mx0 = fmaxf(mx0, __shfl_xor_sync(0xffffffffu, mx0, 1));
            mx0 = fmaxf(mx0, __shfl_xor_sync(0xffffffffu, mx0, 2));
            mx1 = fmaxf(mx1, __shfl_xor_sync(0xffffffffu, mx1, 1));
            mx1 = fmaxf(mx1, __shfl_xor_sync(0xffffffffu, mx1, 2));
            float mn0 = fmaxf(m0, mx0), mn1 = fmaxf(m1, mx1);
            float f0 = exp2f(m0 - mn0), f1 = exp2f(m1 - mn1);
            m0 = mn0; m1 = mn1;

            uint32_t pr[8][2];
            #pragma unroll
            for (int nt = 0; nt < 8; nt++) {
                pr[nt][0] = ex2_h2(pack_h2(sc[nt][0] - mn0, sc[nt][1] - mn0));
                pr[nt][1] = ex2_h2(pack_h2(sc[nt][2] - mn1, sc[nt][3] - mn1));
            }

            float ps[4] = {0.f, 0.f, 0.f, 0.f};
            #pragma unroll
            for (int kt = 0; kt < 4; kt++) {
                uint32_t pf[4] = {pr[2*kt][0], pr[2*kt][1], pr[2*kt+1][0], pr[2*kt+1][1]};
                mma_f16(ps, pf, ones_b);
            }
            l0 = l0*f0 + ps[0];
            l1 = l1*f1 + ps[2];
            #pragma unroll
            for (int nt = 0; nt < 8; nt++) {
                o[nt][0] *= f0; o[nt][1] *= f0;
                o[nt][2] *= f1; o[nt][3] *= f1;
            }

            // ---- O += P V (single-pass fp16) ----
            #pragma unroll
            for (int kt = 0; kt < 4; kt++) {
                uint32_t pf[4] = {pr[2*kt][0], pr[2*kt][1], pr[2*kt+1][0], pr[2*kt+1][1]};
                #pragma unroll
                for (int pp = 0; pp < 2; pp++) {
                    uint32_t vh4[2][4];
                    #pragma unroll
                    for (int i = 0; i < 2; i++) {
                        int dp = 2*pp + i;
                        uint32_t vaddr = vtb + (uint32_t)(((kt*16 + (lane & 15))*A_STR +
                                         dp*16 + ((lane >> 4) & 1)*8)*2);
                        ldsm_x4t(vh4[i][0], vh4[i][1], vh4[i][2], vh4[i][3], vaddr);
                    }
                    #pragma unroll
                    for (int i = 0; i < 2; i++) {
                        int dp = 2*pp + i;
                        mma_f16(o[2*dp],   pf, vh4[i]);
                        mma_f16(o[2*dp+1], pf, vh4[i]+2);
                    }
                }
            }
        }
    }

    // ---- epilogue: single fp16 ----
    const int b = bh >> 4, h = bh & 15;
    const float i0 = 1.f / l0, i1 = 1.f / l1;
    const int srow = q0 + wq*16 + (lane >> 2);
    const size_t base0 = ((size_t)(b*SEQ + srow))*DMODEL + h*64;
    const size_t base1 = base0 + (size_t)8*DMODEL;
    #pragma unroll
    for (int nt = 0; nt < 8; nt++) {
        int col = nt*8 + 2*(lane & 3);
        *(uint32_t*)(Oh + base0 + col) = pack_h2(o[nt][0]*i0, o[nt][1]*i0);
        *(uint32_t*)(Oh + base1 + col) = pack_h2(o[nt][2]*i1, o[nt][3]*i1);
    }
}

// ---------------- launch ----------------
extern "C" void kernel_launch(void* const* d_in, const int* in_sizes, int n_in,
                              void* d_out, int out_size)
{
    const float* x  = (const float*)d_in[0];
    const float* wq = (const float*)d_in[1];
    const float* wk = (const float*)d_in[2];
    const float* wv = (const float*)d_in[3];
    const float* wo = (const float*)d_in[4];
    const int*  pos = (const int*)d_in[5];
    float* out = (float*)d_out;

    float *rc, *rs;
    __half *xh, *xl, *wh, *qh, *ql, *kh, *vh, *aoh;
    cudaGetSymbolAddress((void**)&rc,  g_ropec);
    cudaGetSymbolAddress((void**)&rs,  g_ropes);
    cudaGetSymbolAddress((void**)&xh,  g_xh);
    cudaGetSymbolAddress((void**)&xl,  g_xl);
    cudaGetSymbolAddress((void**)&wh,  g_wh);
    cudaGetSymbolAddress((void**)&qh,  g_qh);
    cudaGetSymbolAddress((void**)&ql,  g_ql);
    cudaGetSymbolAddress((void**)&kh,  g_kh);
    cudaGetSymbolAddress((void**)&vh,  g_vh);
    cudaGetSymbolAddress((void**)&aoh, g_aoh);

    const int SMEM3 = 2*(3*GT_BYTES);   // 110592 (split-A QKV)
    const int SMEM0 = 2*(2*GT_BYTES);   // 73728  (single-A out-proj)

    static bool attr_done = false;
    if (!attr_done) {
        cudaFuncSetAttribute(gemm_mma<0>, cudaFuncAttributeMaxDynamicSharedMemorySize, SMEM0);
        cudaFuncSetAttribute(gemm_mma<3>, cudaFuncAttributeMaxDynamicSharedMemorySize, SMEM3);
        cudaFuncSetAttribute(attn_mma, cudaFuncAttributeMaxDynamicSharedMemorySize, ATTN_SMEM_BYTES);
        attr_done = true;
    }

    {
        dim3 gc(1024, 9);   // 8 conversion segments + 1 rope segment
        convall_kernel<<<gc, 256>>>(x, wq, wk, wv, wo, xh, xl, wh, pos, rc, rs);
    }

    const size_t WN = (size_t)DMODEL*DMODEL;

    dim3 gqkv(DMODEL/128, M_TOT/128, 3);
    gemm_mma<3><<<gqkv, 256, SMEM3>>>(xh, xl, wh,
                                      nullptr, qh, ql, kh, vh, rc, rs);

    dim3 ga(SEQ/128, BATCH*NHEADS);
    attn_mma<<<ga, 256, ATTN_SMEM_BYTES>>>(qh, ql, kh, vh, aoh);

    dim3 gg(DMODEL/128, M_TOT/128);
    gemm_mma<0><<<gg, 256, SMEM0>>>(aoh, nullptr, wh + 3*WN,
                                    out, nullptr, nullptr, nullptr, nullptr, rc, rs);
}

// round 15
// speedup vs baseline: 5.6000x; 1.1028x over previous
#include <cuda_runtime.h>
#include <cuda_fp16.h>
#include <math.h>
#include <cstdint>

#define BATCH   2
#define SEQ     2048
#define DMODEL  1024
#define NHEADS  16
#define DKH     64
#define M_TOT   (BATCH*SEQ)   // 4096
#define QKV_ELEMS (BATCH*NHEADS*SEQ*DKH)

// ---------------- scratch (static device globals; no allocs) ----------------
__device__ __align__(256) __half g_xh[M_TOT*DMODEL];
__device__ __align__(256) __half g_xl[M_TOT*DMODEL];
__device__ __align__(256) __half g_wh[4*DMODEL*DMODEL];   // weights single fp16
__device__ __align__(256) __half g_qh[QKV_ELEMS];
__device__ __align__(256) __half g_ql[QKV_ELEMS];
__device__ __align__(256) __half g_kh[QKV_ELEMS];         // K single fp16
__device__ __align__(256) __half g_vh[QKV_ELEMS];         // V single fp16
__device__ __align__(256) __half g_aoh[M_TOT*DMODEL];     // attention out single fp16
__device__ float g_ropec[SEQ*32];   // [s][ip]
__device__ float g_ropes[SEQ*32];

// ---------------- PTX helpers ----------------
__device__ __forceinline__ uint32_t smem_u32(const void* p) {
    uint32_t a;
    asm("{ .reg .u64 t; cvta.to.shared.u64 t, %1; cvt.u32.u64 %0, t; }" : "=r"(a) : "l"(p));
    return a;
}
__device__ __forceinline__ void cp16(uint32_t dst, const void* src) {
    asm volatile("cp.async.cg.shared.global [%0], [%1], 16;" :: "r"(dst), "l"(src) : "memory");
}
#define CP_COMMIT() asm volatile("cp.async.commit_group;" ::: "memory")
template<int N>
__device__ __forceinline__ void cp_wait() {
    asm volatile("cp.async.wait_group %0;" :: "n"(N) : "memory");
}
__device__ __forceinline__ void ldsm_x4(uint32_t& r0, uint32_t& r1, uint32_t& r2,
                                        uint32_t& r3, uint32_t addr) {
    asm volatile("ldmatrix.sync.aligned.m8n8.x4.shared.b16 {%0,%1,%2,%3}, [%4];"
                 : "=r"(r0), "=r"(r1), "=r"(r2), "=r"(r3) : "r"(addr));
}
__device__ __forceinline__ void ldsm_x4t(uint32_t& r0, uint32_t& r1, uint32_t& r2,
                                         uint32_t& r3, uint32_t addr) {
    asm volatile("ldmatrix.sync.aligned.m8n8.x4.trans.shared.b16 {%0,%1,%2,%3}, [%4];"
                 : "=r"(r0), "=r"(r1), "=r"(r2), "=r"(r3) : "r"(addr));
}
__device__ __forceinline__ void mma_f16(float* c, const uint32_t* a, const uint32_t* b) {
    asm volatile("mma.sync.aligned.m16n8k16.row.col.f32.f16.f16.f32 "
                 "{%0,%1,%2,%3}, {%4,%5,%6,%7}, {%8,%9}, {%0,%1,%2,%3};"
                 : "+f"(c[0]), "+f"(c[1]), "+f"(c[2]), "+f"(c[3])
                 : "r"(a[0]), "r"(a[1]), "r"(a[2]), "r"(a[3]), "r"(b[0]), "r"(b[1]));
}
__device__ __forceinline__ uint32_t pack_h2(float a, float b) {
    __half2 h = __floats2half2_rn(a, b);
    return *(uint32_t*)&h;
}
__device__ __forceinline__ uint32_t ex2_h2(uint32_t x) {
    uint32_t r;
    asm("ex2.approx.f16x2 %0, %1;" : "=r"(r) : "r"(x));
    return r;
}
// split pair of floats into packed fp16x2 hi + lo residual (~22-bit effective)
__device__ __forceinline__ void split2h(float a, float b, uint32_t& hi, uint32_t& lo) {
    __half2 h = __floats2half2_rn(a, b);
    float ha = __low2float(h), hb = __high2float(h);
    __half2 l = __floats2half2_rn(a - ha, b - hb);
    hi = *(uint32_t*)&h;
    lo = *(uint32_t*)&l;
}

// ---------------- fused prep: x (4 quarters, split) + 4 weights + rope table ----------------
__global__ void convall_kernel(const float* __restrict__ x,
                               const float* __restrict__ w0, const float* __restrict__ w1,
                               const float* __restrict__ w2, const float* __restrict__ w3,
                               __half* __restrict__ xh, __half* __restrict__ xl,
                               __half* __restrict__ wh,
                               const int* __restrict__ pos,
                               float* __restrict__ cosT, float* __restrict__ sinT)
{
    const int y = blockIdx.y;
    int i = blockIdx.x * blockDim.x + threadIdx.x;
    if (y < 4) {
        const float* src = x + (size_t)y * (M_TOT*DMODEL/4);
        size_t off = (size_t)y * (M_TOT*DMODEL/4);
        float4 v = *(const float4*)(src + (size_t)i*4);
        uint32_t h0, l0, h1, l1;
        split2h(v.x, v.y, h0, l0);
        split2h(v.z, v.w, h1, l1);
        *(uint32_t*)(xh + off + (size_t)i*4)     = h0;
        *(uint32_t*)(xh + off + (size_t)i*4 + 2) = h1;
        *(uint32_t*)(xl + off + (size_t)i*4)     = l0;
        *(uint32_t*)(xl + off + (size_t)i*4 + 2) = l1;
    } else if (y < 8) {
        const float* ws[4] = {w0, w1, w2, w3};
        const float* src = ws[y-4];
        size_t off = (size_t)(y-4) * DMODEL * DMODEL;
        float4 v = *(const float4*)(src + (size_t)i*4);
        *(uint32_t*)(wh + off + (size_t)i*4)     = pack_h2(v.x, v.y);
        *(uint32_t*)(wh + off + (size_t)i*4 + 2) = pack_h2(v.z, v.w);
    } else {
        if (i >= SEQ*32) return;
        int s  = i >> 5;
        int ip = i & 31;
        double invf = exp2(-(double)ip * 0.41524101186092028);  // log2(10000)/32
        float ang = (float)pos[s] * (float)invf;
        float sn, cs;
        sincosf(ang, &sn, &cs);
        cosT[i] = cs;
        sinT[i] = sn;
    }
}

// ---------------- fp16 GEMM, KC=64, 2-stage ring, one barrier per chunk ----------------
// MODE 0: single-pass A, row-major fp32 C (output projection)
// MODE 2: split-A 2-pass, Q hi/lo + RoPE
// MODE 4: single-pass A, z=0 -> K fp16 + RoPE, z=1 -> V fp16
#define NKCH (DMODEL/64)          // 16
#define GROW 72                   // halves per row (144B = 9x16B, conflict-free ldsm)
#define GT_BYTES (128*GROW*2)     // 18432

template<int MODE>
__global__ __launch_bounds__(256, 2)
void gemm_mma(const __half* __restrict__ Ahi, const __half* __restrict__ Alo,
              const __half* __restrict__ B_,
              float* __restrict__ C,
              __half* __restrict__ Qhi, __half* __restrict__ Qlo,
              __half* __restrict__ Kout, __half* __restrict__ Vout,
              const float* __restrict__ ropec, const float* __restrict__ ropes)
{
    constexpr bool SPLITA = (MODE == 2);
    constexpr int OFF_B = SPLITA ? 2*GT_BYTES : GT_BYTES;
    constexpr int STG_BYTES = SPLITA ? 3*GT_BYTES : 2*GT_BYTES;

    extern __shared__ __half smh[];
    const uint32_t sbase = smem_u32(smh);
    const int tid  = threadIdx.x;
    const int wid  = tid >> 5;
    const int lane = tid & 31;
    const int bm = blockIdx.y, bn = blockIdx.x;
    const int wm = wid & 3;
    const int wn = wid >> 2;

    const __half* Bw = B_;
    bool do_rope = (MODE == 2);
    int zsel = 0;
    if (MODE == 4) {
        zsel = blockIdx.z;                 // 0 -> K, 1 -> V
        Bw = B_ + (size_t)(zsel + 1) * DMODEL * DMODEL;
        do_rope = (zsel == 0);
    }

    float acc[2][8][4];
    #pragma unroll
    for (int mt = 0; mt < 2; mt++)
        #pragma unroll
        for (int nt = 0; nt < 8; nt++)
            #pragma unroll
            for (int j = 0; j < 4; j++) acc[mt][nt][j] = 0.f;

    const __half* Ah = Ahi + (size_t)(bm*128)*DMODEL;
    const __half* Al = SPLITA ? (Alo + (size_t)(bm*128)*DMODEL) : nullptr;
    const __half* Bh = Bw  + (size_t)(bn*128)*DMODEL;

    // loader: thread owns rows rb+32i (i=0..3), chunk lc (16B units over 128B of KC=64)
    const int lc = tid & 7;
    const int rb = tid >> 3;              // 0..31
    const __half* SA  = Ah + (size_t)rb*DMODEL + lc*8;
    const __half* SAl = SPLITA ? (Al + (size_t)rb*DMODEL + lc*8) : nullptr;
    const __half* SB  = Bh + (size_t)rb*DMODEL + lc*8;
    const uint32_t dsl = sbase + (uint32_t)(rb*GROW + lc*8)*2;
    const uint32_t rowhop = (uint32_t)(32*GROW)*2;
    const size_t   srchop = (size_t)32*DMODEL;

    auto load_stage = [&](int stg, int kc) {
        const uint32_t d = dsl + stg*STG_BYTES;
        const int ko = kc*64;
        #pragma unroll
        for (int i = 0; i < 4; i++) {
            cp16(d + i*rowhop, SA + i*srchop + ko);
            if (SPLITA) cp16(d + GT_BYTES + i*rowhop, SAl + i*srchop + ko);
            cp16(d + OFF_B + i*rowhop, SB + i*srchop + ko);
        }
        CP_COMMIT();
    };

    load_stage(0, 0);

    const int a_row   = wm*32 + (lane & 15);
    const int a_co    = (lane >> 4) * 8;
    const int b_row_p = wn*64 + (lane & 7) + ((lane >> 4) << 3);
    const int b_co    = ((lane >> 3) & 1) * 8;

    for (int kc = 0; kc < NKCH; kc++) {
        cp_wait<0>();
        __syncthreads();
        if (kc + 1 < NKCH) load_stage((kc + 1) & 1, kc + 1);
        const uint32_t sbk = sbase + (kc & 1)*STG_BYTES;

        #pragma unroll
        for (int ks = 0; ks < 4; ks++) {
            const int kof = ks*16;
            uint32_t ah[2][4], al[2][4];
            #pragma unroll
            for (int mt = 0; mt < 2; mt++) {
                uint32_t aaddr = sbk + (uint32_t)(((a_row + mt*16)*GROW + kof + a_co)*2);
                ldsm_x4(ah[mt][0], ah[mt][1], ah[mt][2], ah[mt][3], aaddr);
                if (SPLITA)
                    ldsm_x4(al[mt][0], al[mt][1], al[mt][2], al[mt][3], aaddr + GT_BYTES);
            }
            #pragma unroll
            for (int pp = 0; pp < 2; pp++) {
                uint32_t b4[2][4];
                #pragma unroll
                for (int i = 0; i < 2; i++) {
                    int p = 2*pp + i;
                    uint32_t baddr = sbk + OFF_B +
                                     (uint32_t)(((b_row_p + p*16)*GROW + kof + b_co)*2);
                    ldsm_x4(b4[i][0], b4[i][1], b4[i][2], b4[i][3], baddr);
                }
                #pragma unroll
                for (int i = 0; i < 2; i++) {
                    int p = 2*pp + i;
                    #pragma unroll
                    for (int mt = 0; mt < 2; mt++) {
                        mma_f16(acc[mt][2*p],   ah[mt], b4[i]);
                        mma_f16(acc[mt][2*p+1], ah[mt], b4[i]+2);
                    }
                }
                if (SPLITA) {
                    #pragma unroll
                    for (int i = 0; i < 2; i++) {
                        int p = 2*pp + i;
                        #pragma unroll
                        for (int mt = 0; mt < 2; mt++) {
                            mma_f16(acc[mt][2*p],   al[mt], b4[i]);
                            mma_f16(acc[mt][2*p+1], al[mt], b4[i]+2);
                        }
                    }
                }
            }
        }
    }

    // ---- epilogue ----
    const int row_base = bm*128 + wm*32;
    const int col_base = bn*128 + wn*64;
    #pragma unroll
    for (int mt = 0; mt < 2; mt++) {
        #pragma unroll
        for (int rg = 0; rg < 2; rg++) {
            int row = row_base + mt*16 + rg*8 + (lane >> 2);
            int s = row & (SEQ-1);
            int b = row >> 11;
            #pragma unroll
            for (int nt = 0; nt < 8; nt++) {
                int col = col_base + nt*8 + 2*(lane & 3);
                float e = acc[mt][nt][rg*2];
                float o = acc[mt][nt][rg*2+1];
                if (do_rope) {
                    int ip = (col & 63) >> 1;
                    float cs = ropec[s*32 + ip];
                    float sn = ropes[s*32 + ip];
                    float ne = e*cs - o*sn;
                    float no = e*sn + o*cs;
                    e = ne; o = no;
                }
                if (MODE == 0) {
                    *(float2*)(C + (size_t)row*DMODEL + col) = make_float2(e, o);
                } else {
                    int h = col >> 6, dk = col & 63;
                    size_t idx = ((size_t)(b*NHEADS + h)*SEQ + s)*DKH + dk;
                    if (MODE == 2) {
                        uint32_t hi, lo;
                        split2h(e, o, hi, lo);
                        *(uint32_t*)(Qhi + idx) = hi;
                        *(uint32_t*)(Qlo + idx) = lo;
                    } else if (zsel == 0) {
                        *(uint32_t*)(Kout + idx) = pack_h2(e, o);
                    } else {
                        *(uint32_t*)(Vout + idx) = pack_h2(e, o);
                    }
                }
            }
        }
    }
}

// ---------------- fp16 flash attention: 128-key macro tiles, 2-stage ring ----------------
#define A_STR 72
#define A_SQL 9216
#define A_SST 18432
#define A_KBUF 9216                // 128*72
#define A_STG (2*A_KBUF)           // 18432 halves per stage
#define ATTN_SMEM_BYTES ((A_SST + 2*A_STG)*2)   // 110592
#define SCALE_LOG2 0.18033688011112042f         // 0.125 * log2(e)

__global__ __launch_bounds__(256, 2)
void attn_mma(const __half* __restrict__ Qh_g, const __half* __restrict__ Ql_g,
              const __half* __restrict__ Kh_g, const __half* __restrict__ Vh_g,
              __half* __restrict__ Oh)
{
    extern __shared__ __half smh[];
    const uint32_t sb = smem_u32(smh);
    const int tid  = threadIdx.x;
    const int wq   = tid >> 5;
    const int lane = tid & 31;
    const int bh   = blockIdx.y;
    const int qt   = gridDim.x - 1 - blockIdx.x;
    const int q0   = qt * 128;
    const size_t boff = (size_t)bh*SEQ*DKH;

    // ---- Q (hi+lo) ----
    #pragma unroll
    for (int l = 0; l < 4; l++) {
        int item = tid + l*256;
        int r = item >> 3;
        int c = item & 7;
        uint32_t d = sb + (uint32_t)(r*A_STR + c*8)*2;
        const __half* src = Qh_g + boff + (size_t)(q0+r)*DKH + c*8;
        cp16(d, src);
        cp16(d + A_SQL*2, Ql_g + (src - Qh_g));
    }
    CP_COMMIT();

    const int bsel = tid >> 7;
    const int loc  = tid & 127;
    const int vc   = loc & 7;
    const int vr   = loc >> 3;
    const __half* Pk = bsel ? Vh_g : Kh_g;
    const __half* Pkv = Pk + boff + (size_t)vr*DKH + vc*8;
    const uint32_t dkv = sb + (uint32_t)((A_SST + bsel*A_KBUF + vr*A_STR + vc*8)*2);

    auto load_kv = [&](int stg, int mt) {
        const __half* s = Pkv + (size_t)(mt*128)*DKH;
        const uint32_t d = dkv + stg*(A_STG*2);
        #pragma unroll
        for (int i = 0; i < 8; i++)
            cp16(d + i*(16*A_STR*2), s + (size_t)(i*16)*DKH);
        CP_COMMIT();
    };

    const int nmt = qt + 1;
    load_kv(0, 0);

    float sc[8][4];
    float o[8][4];
    #pragma unroll
    for (int nt = 0; nt < 8; nt++)
        #pragma unroll
        for (int j = 0; j < 4; j++) o[nt][j] = 0.f;
    float m0 = -INFINITY, m1 = -INFINITY, l0 = 0.f, l1 = 0.f;

    const uint32_t ONES2 = 0x3C003C00u;
    uint32_t ones_b[2] = {ONES2, ONES2};

    for (int mt = 0; mt < nmt; mt++) {
        cp_wait<0>();
        __syncthreads();
        if (mt + 1 < nmt) load_kv((mt + 1) & 1, mt + 1);
        const uint32_t stb = sb + (uint32_t)((A_SST + (mt & 1)*A_STG)*2);

        #pragma unroll
        for (int st = 0; st < 2; st++) {
            const int k0 = mt*128 + st*64;
            if (k0 > q0 + wq*16 + 15) continue;
            const uint32_t ktb = stb + (uint32_t)(st*64*A_STR)*2;
            const uint32_t vtb = stb + (uint32_t)((A_KBUF + st*64*A_STR))*2;

            // ---- S = Q K^T (split-Q, 2 passes) ----
            #pragma unroll
            for (int nt = 0; nt < 8; nt++)
                #pragma unroll
                for (int j = 0; j < 4; j++) sc[nt][j] = 0.f;
            #pragma unroll
            for (int kt = 0; kt < 4; kt++) {
                uint32_t ah[4], al[4];
                uint32_t aaddr = sb + (uint32_t)(((wq*16 + (lane & 15))*A_STR + kt*16 + (lane >> 4)*8)*2);
                ldsm_x4(ah[0], ah[1], ah[2], ah[3], aaddr);
                ldsm_x4(al[0], al[1], al[2], al[3], aaddr + A_SQL*2);
                #pragma unroll
                for (int pp = 0; pp < 2; pp++) {
                    uint32_t kh4[2][4];
                    #pragma unroll
                    for (int i = 0; i < 2; i++) {
                        int p = 2*pp + i;
                        int brow = p*16 + (lane & 7) + ((lane >> 4) << 3);
                        uint32_t baddr = ktb + (uint32_t)((brow*A_STR + kt*16 + ((lane >> 3) & 1)*8)*2);
                        ldsm_x4(kh4[i][0], kh4[i][1], kh4[i][2], kh4[i][3], baddr);
                    }
                    #pragma unroll
                    for (int i = 0; i < 2; i++) {
                        int p = 2*pp + i;
                        mma_f16(sc[2*p],   ah, kh4[i]);
                        mma_f16(sc[2*p+1], ah, kh4[i]+2);
                    }
                    #pragma unroll
                    for (int i = 0; i < 2; i++) {
                        int p = 2*pp + i;
                        mma_f16(sc[2*p],   al, kh4[i]);
                        mma_f16(sc[2*p+1], al, kh4[i]+2);
                    }
                }
            }

            // ---- softmax: scale/mask/max, P = ex2.f16x2, sums via ones-MMA ----
            const int qrow = q0 + wq*16 + (lane >> 2);
            const bool needmask = (k0 + 63 > q0 + wq*16);
            float mx0 = -1e30f, mx1 = -1e30f;
            #pragma unroll
            for (int nt = 0; nt < 8; nt++) {
                #pragma unroll
                for (int j = 0; j < 4; j++) sc[nt][j] *= SCALE_LOG2;
                if (needmask) {
                    int kcol = k0 + nt*8 + 2*(lane & 3);
                    if (kcol+0 > qrow)   sc[nt][0] = -1e30f;
                    if (kcol+1 > qrow)   sc[nt][1] = -1e30f;
                    if (kcol+0 > qrow+8) sc[nt][2] = -1e30f;
                    if (kcol+1 > qrow+8) sc[nt][3] = -1e30f;
                }
                mx0 = fmaxf(mx0, fmaxf(sc[nt][0], sc[nt][1]));
                mx1 = fmaxf(mx1, fmaxf(sc[nt][2], sc[nt][3]));
            }
            mx0 = fmaxf(mx0, __shfl_xor_sync(0xffffffffu, mx0, 1));
            mx0 = fmaxf(mx0, __shfl_xor_sync(0xffffffffu, mx0, 2));
            mx1 = fmaxf(mx1, __shfl_xor_sync(0xffffffffu, mx1, 1));
            mx1 = fmaxf(mx1, __shfl_xor_sync(0xffffffffu, mx1, 2));
            float mn0 = fmaxf(m0, mx0), mn1 = fmaxf(m1, mx1);
            float f0 = exp2f(m0 - mn0), f1 = exp2f(m1 - mn1);
            m0 = mn0; m1 = mn1;

            uint32_t pr[8][2];
            #pragma unroll
            for (int nt = 0; nt < 8; nt++) {
                pr[nt][0] = ex2_h2(pack_h2(sc[nt][0] - mn0, sc[nt][1] - mn0));
                pr[nt][1] = ex2_h2(pack_h2(sc[nt][2] - mn1, sc[nt][3] - mn1));
            }

            float ps[4] = {0.f, 0.f, 0.f, 0.f};
            #pragma unroll
            for (int kt = 0; kt < 4; kt++) {
                uint32_t pf[4] = {pr[2*kt][0], pr[2*kt][1], pr[2*kt+1][0], pr[2*kt+1][1]};
                mma_f16(ps, pf, ones_b);
            }
            l0 = l0*f0 + ps[0];
            l1 = l1*f1 + ps[2];
            #pragma unroll
            for (int nt = 0; nt < 8; nt++) {
                o[nt][0] *= f0; o[nt][1] *= f0;
                o[nt][2] *= f1; o[nt][3] *= f1;
            }

            // ---- O += P V (single-pass fp16) ----
            #pragma unroll
            for (int kt = 0; kt < 4; kt++) {
                uint32_t pf[4] = {pr[2*kt][0], pr[2*kt][1], pr[2*kt+1][0], pr[2*kt+1][1]};
                #pragma unroll
                for (int pp = 0; pp < 2; pp++) {
                    uint32_t vh4[2][4];
                    #pragma unroll
                    for (int i = 0; i < 2; i++) {
                        int dp = 2*pp + i;
                        uint32_t vaddr = vtb + (uint32_t)(((kt*16 + (lane & 15))*A_STR +
                                         dp*16 + ((lane >> 4) & 1)*8)*2);
                        ldsm_x4t(vh4[i][0], vh4[i][1], vh4[i][2], vh4[i][3], vaddr);
                    }
                    #pragma unroll
                    for (int i = 0; i < 2; i++) {
                        int dp = 2*pp + i;
                        mma_f16(o[2*dp],   pf, vh4[i]);
                        mma_f16(o[2*dp+1], pf, vh4[i]+2);
                    }
                }
            }
        }
    }

    // ---- epilogue: single fp16 ----
    const int b = bh >> 4, h = bh & 15;
    const float i0 = 1.f / l0, i1 = 1.f / l1;
    const int srow = q0 + wq*16 + (lane >> 2);
    const size_t base0 = ((size_t)(b*SEQ + srow))*DMODEL + h*64;
    const size_t base1 = base0 + (size_t)8*DMODEL;
    #pragma unroll
    for (int nt = 0; nt < 8; nt++) {
        int col = nt*8 + 2*(lane & 3);
        *(uint32_t*)(Oh + base0 + col) = pack_h2(o[nt][0]*i0, o[nt][1]*i0);
        *(uint32_t*)(Oh + base1 + col) = pack_h2(o[nt][2]*i1, o[nt][3]*i1);
    }
}

// ---------------- launch ----------------
extern "C" void kernel_launch(void* const* d_in, const int* in_sizes, int n_in,
                              void* d_out, int out_size)
{
    const float* x  = (const float*)d_in[0];
    const float* wq = (const float*)d_in[1];
    const float* wk = (const float*)d_in[2];
    const float* wv = (const float*)d_in[3];
    const float* wo = (const float*)d_in[4];
    const int*  pos = (const int*)d_in[5];
    float* out = (float*)d_out;

    float *rc, *rs;
    __half *xh, *xl, *wh, *qh, *ql, *kh, *vh, *aoh;
    cudaGetSymbolAddress((void**)&rc,  g_ropec);
    cudaGetSymbolAddress((void**)&rs,  g_ropes);
    cudaGetSymbolAddress((void**)&xh,  g_xh);
    cudaGetSymbolAddress((void**)&xl,  g_xl);
    cudaGetSymbolAddress((void**)&wh,  g_wh);
    cudaGetSymbolAddress((void**)&qh,  g_qh);
    cudaGetSymbolAddress((void**)&ql,  g_ql);
    cudaGetSymbolAddress((void**)&kh,  g_kh);
    cudaGetSymbolAddress((void**)&vh,  g_vh);
    cudaGetSymbolAddress((void**)&aoh, g_aoh);

    const int SMEM2 = 2*(3*GT_BYTES);   // 110592 (split-A Q)
    const int SMEM1 = 2*(2*GT_BYTES);   // 73728  (single-A K/V, out-proj)

    static bool attr_done = false;
    if (!attr_done) {
        cudaFuncSetAttribute(gemm_mma<0>, cudaFuncAttributeMaxDynamicSharedMemorySize, SMEM1);
        cudaFuncSetAttribute(gemm_mma<2>, cudaFuncAttributeMaxDynamicSharedMemorySize, SMEM2);
        cudaFuncSetAttribute(gemm_mma<4>, cudaFuncAttributeMaxDynamicSharedMemorySize, SMEM1);
        cudaFuncSetAttribute(attn_mma, cudaFuncAttributeMaxDynamicSharedMemorySize, ATTN_SMEM_BYTES);
        attr_done = true;
    }

    {
        dim3 gc(1024, 9);   // 8 conversion segments + 1 rope segment
        convall_kernel<<<gc, 256>>>(x, wq, wk, wv, wo, xh, xl, wh, pos, rc, rs);
    }

    // Q projection: split-A (x hi/lo), output Q hi/lo + RoPE
    dim3 gq(DMODEL/128, M_TOT/128);
    gemm_mma<2><<<gq, 256, SMEM2>>>(xh, xl, wh,
                                    nullptr, qh, ql, nullptr, nullptr, rc, rs);

    // K,V projections: single-pass A (x hi only), K+RoPE / V
    dim3 gkv(DMODEL/128, M_TOT/128, 2);
    gemm_mma<4><<<gkv, 256, SMEM1>>>(xh, nullptr, wh,
                                     nullptr, nullptr, nullptr, kh, vh, rc, rs);

    dim3 ga(SEQ/128, BATCH*NHEADS);
    attn_mma<<<ga, 256, ATTN_SMEM_BYTES>>>(qh, ql, kh, vh, aoh);

    const size_t WN = (size_t)DMODEL*DMODEL;
    dim3 gg(DMODEL/128, M_TOT/128);
    gemm_mma<0><<<gg, 256, SMEM1>>>(aoh, nullptr, wh + 3*WN,
                                    out, nullptr, nullptr, nullptr, nullptr, rc, rs);
}

// round 16
// speedup vs baseline: 5.7134x; 1.0203x over previous
#include <cuda_runtime.h>
#include <cuda_fp16.h>
#include <math.h>
#include <cstdint>

#define BATCH   2
#define SEQ     2048
#define DMODEL  1024
#define NHEADS  16
#define DKH     64
#define M_TOT   (BATCH*SEQ)   // 4096
#define QKV_ELEMS (BATCH*NHEADS*SEQ*DKH)

// ---------------- scratch (static device globals; no allocs) ----------------
__device__ __align__(256) __half g_xh[M_TOT*DMODEL];
__device__ __align__(256) __half g_xl[M_TOT*DMODEL];
__device__ __align__(256) __half g_wh[4*DMODEL*DMODEL];   // weights single fp16
__device__ __align__(256) __half g_qh[QKV_ELEMS];
__device__ __align__(256) __half g_ql[QKV_ELEMS];
__device__ __align__(256) __half g_kh[QKV_ELEMS];         // K single fp16
__device__ __align__(256) __half g_vh[QKV_ELEMS];         // V single fp16
__device__ __align__(256) __half g_aoh[M_TOT*DMODEL];     // attention out single fp16
__device__ float g_ropec[SEQ*32];   // [s][ip]
__device__ float g_ropes[SEQ*32];

// ---------------- PTX helpers ----------------
__device__ __forceinline__ uint32_t smem_u32(const void* p) {
    uint32_t a;
    asm("{ .reg .u64 t; cvta.to.shared.u64 t, %1; cvt.u32.u64 %0, t; }" : "=r"(a) : "l"(p));
    return a;
}
__device__ __forceinline__ void cp16(uint32_t dst, const void* src) {
    asm volatile("cp.async.cg.shared.global [%0], [%1], 16;" :: "r"(dst), "l"(src) : "memory");
}
#define CP_COMMIT() asm volatile("cp.async.commit_group;" ::: "memory")
template<int N>
__device__ __forceinline__ void cp_wait() {
    asm volatile("cp.async.wait_group %0;" :: "n"(N) : "memory");
}
__device__ __forceinline__ void ldsm_x4(uint32_t& r0, uint32_t& r1, uint32_t& r2,
                                        uint32_t& r3, uint32_t addr) {
    asm volatile("ldmatrix.sync.aligned.m8n8.x4.shared.b16 {%0,%1,%2,%3}, [%4];"
                 : "=r"(r0), "=r"(r1), "=r"(r2), "=r"(r3) : "r"(addr));
}
__device__ __forceinline__ void ldsm_x4t(uint32_t& r0, uint32_t& r1, uint32_t& r2,
                                         uint32_t& r3, uint32_t addr) {
    asm volatile("ldmatrix.sync.aligned.m8n8.x4.trans.shared.b16 {%0,%1,%2,%3}, [%4];"
                 : "=r"(r0), "=r"(r1), "=r"(r2), "=r"(r3) : "r"(addr));
}
__device__ __forceinline__ void mma_f16(float* c, const uint32_t* a, const uint32_t* b) {
    asm volatile("mma.sync.aligned.m16n8k16.row.col.f32.f16.f16.f32 "
                 "{%0,%1,%2,%3}, {%4,%5,%6,%7}, {%8,%9}, {%0,%1,%2,%3};"
                 : "+f"(c[0]), "+f"(c[1]), "+f"(c[2]), "+f"(c[3])
                 : "r"(a[0]), "r"(a[1]), "r"(a[2]), "r"(a[3]), "r"(b[0]), "r"(b[1]));
}
__device__ __forceinline__ uint32_t pack_h2(float a, float b) {
    __half2 h = __floats2half2_rn(a, b);
    return *(uint32_t*)&h;
}
__device__ __forceinline__ uint32_t ex2_h2(uint32_t x) {
    uint32_t r;
    asm("ex2.approx.f16x2 %0, %1;" : "=r"(r) : "r"(x));
    return r;
}
// split pair of floats into packed fp16x2 hi + lo residual (~22-bit effective)
__device__ __forceinline__ void split2h(float a, float b, uint32_t& hi, uint32_t& lo) {
    __half2 h = __floats2half2_rn(a, b);
    float ha = __low2float(h), hb = __high2float(h);
    __half2 l = __floats2half2_rn(a - ha, b - hb);
    hi = *(uint32_t*)&h;
    lo = *(uint32_t*)&l;
}

// ---------------- fused prep: x (4 quarters, split) + 4 weights + rope table ----------------
__global__ void convall_kernel(const float* __restrict__ x,
                               const float* __restrict__ w0, const float* __restrict__ w1,
                               const float* __restrict__ w2, const float* __restrict__ w3,
                               __half* __restrict__ xh, __half* __restrict__ xl,
                               __half* __restrict__ wh,
                               const int* __restrict__ pos,
                               float* __restrict__ cosT, float* __restrict__ sinT)
{
    const int y = blockIdx.y;
    int i = blockIdx.x * blockDim.x + threadIdx.x;
    if (y < 4) {
        const float* src = x + (size_t)y * (M_TOT*DMODEL/4);
        size_t off = (size_t)y * (M_TOT*DMODEL/4);
        float4 v = *(const float4*)(src + (size_t)i*4);
        uint32_t h0, l0, h1, l1;
        split2h(v.x, v.y, h0, l0);
        split2h(v.z, v.w, h1, l1);
        *(uint32_t*)(xh + off + (size_t)i*4)     = h0;
        *(uint32_t*)(xh + off + (size_t)i*4 + 2) = h1;
        *(uint32_t*)(xl + off + (size_t)i*4)     = l0;
        *(uint32_t*)(xl + off + (size_t)i*4 + 2) = l1;
    } else if (y < 8) {
        const float* ws[4] = {w0, w1, w2, w3};
        const float* src = ws[y-4];
        size_t off = (size_t)(y-4) * DMODEL * DMODEL;
        float4 v = *(const float4*)(src + (size_t)i*4);
        *(uint32_t*)(wh + off + (size_t)i*4)     = pack_h2(v.x, v.y);
        *(uint32_t*)(wh + off + (size_t)i*4 + 2) = pack_h2(v.z, v.w);
    } else {
        if (i >= SEQ*32) return;
        int s  = i >> 5;
        int ip = i & 31;
        double invf = exp2(-(double)ip * 0.41524101186092028);  // log2(10000)/32
        float ang = (float)pos[s] * (float)invf;
        float sn, cs;
        sincosf(ang, &sn, &cs);
        cosT[i] = cs;
        sinT[i] = sn;
    }
}

// ---------------- GEMM common geometry ----------------
#define NKCH (DMODEL/64)          // 16
#define GROW 72                   // halves per row (144B = 9x16B, conflict-free ldsm)
#define GT_BYTES (128*GROW*2)     // 18432

// ---------------- fused QKV GEMM: one launch, z selects projection ----------------
// z=0: split-A (xh+xl) -> Q hi/lo + RoPE; z=1: single-A -> K + RoPE; z=2: single-A -> V
// Uniform 3-tile stage layout (Ah, Al, B); z!=0 leaves Al region unused.
#define QKV_STG (3*GT_BYTES)              // 55296
#define QKV_SMEM (2*QKV_STG)              // 110592

__global__ __launch_bounds__(256, 2)
void gemm_qkv(const __half* __restrict__ xh_g, const __half* __restrict__ xl_g,
              const __half* __restrict__ wh_g,
              __half* __restrict__ Qhi, __half* __restrict__ Qlo,
              __half* __restrict__ Kout, __half* __restrict__ Vout,
              const float* __restrict__ ropec, const float* __restrict__ ropes)
{
    extern __shared__ __half smh[];
    const uint32_t sbase = smem_u32(smh);
    const int tid  = threadIdx.x;
    const int wid  = tid >> 5;
    const int lane = tid & 31;
    const int bm = blockIdx.y, bn = blockIdx.x;
    const int z  = blockIdx.z;
    const bool splita  = (z == 0);
    const bool do_rope = (z < 2);
    const int wm = wid & 3;
    const int wn = wid >> 2;

    float acc[2][8][4];
    #pragma unroll
    for (int mt = 0; mt < 2; mt++)
        #pragma unroll
        for (int nt = 0; nt < 8; nt++)
            #pragma unroll
            for (int j = 0; j < 4; j++) acc[mt][nt][j] = 0.f;

    const __half* Ah = xh_g + (size_t)(bm*128)*DMODEL;
    const __half* Al = xl_g + (size_t)(bm*128)*DMODEL;
    const __half* Bh = wh_g + (size_t)z*DMODEL*DMODEL + (size_t)(bn*128)*DMODEL;

    const int lc = tid & 7;
    const int rb = tid >> 3;              // 0..31
    const __half* SA  = Ah + (size_t)rb*DMODEL + lc*8;
    const __half* SAl = Al + (size_t)rb*DMODEL + lc*8;
    const __half* SB  = Bh + (size_t)rb*DMODEL + lc*8;
    const uint32_t dsl = sbase + (uint32_t)(rb*GROW + lc*8)*2;
    const uint32_t rowhop = (uint32_t)(32*GROW)*2;
    const size_t   srchop = (size_t)32*DMODEL;

    auto load_stage = [&](int stg, int kc) {
        const uint32_t d = dsl + stg*QKV_STG;
        const int ko = kc*64;
        #pragma unroll
        for (int i = 0; i < 4; i++) {
            cp16(d + i*rowhop, SA + i*srchop + ko);
            if (splita) cp16(d + GT_BYTES + i*rowhop, SAl + i*srchop + ko);
            cp16(d + 2*GT_BYTES + i*rowhop, SB + i*srchop + ko);
        }
        CP_COMMIT();
    };

    load_stage(0, 0);

    const int a_row   = wm*32 + (lane & 15);
    const int a_co    = (lane >> 4) * 8;
    const int b_row_p = wn*64 + (lane & 7) + ((lane >> 4) << 3);
    const int b_co    = ((lane >> 3) & 1) * 8;

    for (int kc = 0; kc < NKCH; kc++) {
        cp_wait<0>();
        __syncthreads();
        if (kc + 1 < NKCH) load_stage((kc + 1) & 1, kc + 1);
        const uint32_t sbk = sbase + (kc & 1)*QKV_STG;

        #pragma unroll
        for (int ks = 0; ks < 4; ks++) {
            const int kof = ks*16;
            uint32_t ah[2][4], al[2][4];
            #pragma unroll
            for (int mt = 0; mt < 2; mt++) {
                uint32_t aaddr = sbk + (uint32_t)(((a_row + mt*16)*GROW + kof + a_co)*2);
                ldsm_x4(ah[mt][0], ah[mt][1], ah[mt][2], ah[mt][3], aaddr);
                if (splita)
                    ldsm_x4(al[mt][0], al[mt][1], al[mt][2], al[mt][3], aaddr + GT_BYTES);
            }
            #pragma unroll
            for (int pp = 0; pp < 2; pp++) {
                uint32_t b4[2][4];
                #pragma unroll
                for (int i = 0; i < 2; i++) {
                    int p = 2*pp + i;
                    uint32_t baddr = sbk + 2*GT_BYTES +
                                     (uint32_t)(((b_row_p + p*16)*GROW + kof + b_co)*2);
                    ldsm_x4(b4[i][0], b4[i][1], b4[i][2], b4[i][3], baddr);
                }
                #pragma unroll
                for (int i = 0; i < 2; i++) {
                    int p = 2*pp + i;
                    #pragma unroll
                    for (int mt = 0; mt < 2; mt++) {
                        mma_f16(acc[mt][2*p],   ah[mt], b4[i]);
                        mma_f16(acc[mt][2*p+1], ah[mt], b4[i]+2);
                    }
                }
                if (splita) {
                    #pragma unroll
                    for (int i = 0; i < 2; i++) {
                        int p = 2*pp + i;
                        #pragma unroll
                        for (int mt = 0; mt < 2; mt++) {
                            mma_f16(acc[mt][2*p],   al[mt], b4[i]);
                            mma_f16(acc[mt][2*p+1], al[mt], b4[i]+2);
                        }
                    }
                }
            }
        }
    }

    // ---- epilogue ----
    const int row_base = bm*128 + wm*32;
    const int col_base = bn*128 + wn*64;
    #pragma unroll
    for (int mt = 0; mt < 2; mt++) {
        #pragma unroll
        for (int rg = 0; rg < 2; rg++) {
            int row = row_base + mt*16 + rg*8 + (lane >> 2);
            int s = row & (SEQ-1);
            int b = row >> 11;
            #pragma unroll
            for (int nt = 0; nt < 8; nt++) {
                int col = col_base + nt*8 + 2*(lane & 3);
                float e = acc[mt][nt][rg*2];
                float o = acc[mt][nt][rg*2+1];
                if (do_rope) {
                    int ip = (col & 63) >> 1;
                    float cs = ropec[s*32 + ip];
                    float sn = ropes[s*32 + ip];
                    float ne = e*cs - o*sn;
                    float no = e*sn + o*cs;
                    e = ne; o = no;
                }
                int h = col >> 6, dk = col & 63;
                size_t idx = ((size_t)(b*NHEADS + h)*SEQ + s)*DKH + dk;
                if (z == 0) {
                    uint32_t hi, lo;
                    split2h(e, o, hi, lo);
                    *(uint32_t*)(Qhi + idx) = hi;
                    *(uint32_t*)(Qlo + idx) = lo;
                } else if (z == 1) {
                    *(uint32_t*)(Kout + idx) = pack_h2(e, o);
                } else {
                    *(uint32_t*)(Vout + idx) = pack_h2(e, o);
                }
            }
        }
    }
}

// ---------------- output projection GEMM: single-pass A, fp32 C ----------------
#define OP_STG (2*GT_BYTES)               // 36864
#define OP_SMEM (2*OP_STG)                // 73728

__global__ __launch_bounds__(256, 2)
void gemm_out(const __half* __restrict__ A_g, const __half* __restrict__ B_g,
              float* __restrict__ C)
{
    extern __shared__ __half smh[];
    const uint32_t sbase = smem_u32(smh);
    const int tid  = threadIdx.x;
    const int wid  = tid >> 5;
    const int lane = tid & 31;
    const int bm = blockIdx.y, bn = blockIdx.x;
    const int wm = wid & 3;
    const int wn = wid >> 2;

    float acc[2][8][4];
    #pragma unroll
    for (int mt = 0; mt < 2; mt++)
        #pragma unroll
        for (int nt = 0; nt < 8; nt++)
            #pragma unroll
            for (int j = 0; j < 4; j++) acc[mt][nt][j] = 0.f;

    const __half* Ah = A_g + (size_t)(bm*128)*DMODEL;
    const __half* Bh = B_g + (size_t)(bn*128)*DMODEL;

    const int lc = tid & 7;
    const int rb = tid >> 3;
    const __half* SA = Ah + (size_t)rb*DMODEL + lc*8;
    const __half* SB = Bh + (size_t)rb*DMODEL + lc*8;
    const uint32_t dsl = sbase + (uint32_t)(rb*GROW + lc*8)*2;
    const uint32_t rowhop = (uint32_t)(32*GROW)*2;
    const size_t   srchop = (size_t)32*DMODEL;

    auto load_stage = [&](int stg, int kc) {
        const uint32_t d = dsl + stg*OP_STG;
        const int ko = kc*64;
        #pragma unroll
        for (int i = 0; i < 4; i++) {
            cp16(d + i*rowhop, SA + i*srchop + ko);
            cp16(d + GT_BYTES + i*rowhop, SB + i*srchop + ko);
        }
        CP_COMMIT();
    };

    load_stage(0, 0);

    const int a_row   = wm*32 + (lane & 15);
    const int a_co    = (lane >> 4) * 8;
    const int b_row_p = wn*64 + (lane & 7) + ((lane >> 4) << 3);
    const int b_co    = ((lane >> 3) & 1) * 8;

    for (int kc = 0; kc < NKCH; kc++) {
        cp_wait<0>();
        __syncthreads();
        if (kc + 1 < NKCH) load_stage((kc + 1) & 1, kc + 1);
        const uint32_t sbk = sbase + (kc & 1)*OP_STG;

        #pragma unroll
        for (int ks = 0; ks < 4; ks++) {
            const int kof = ks*16;
            uint32_t ah[2][4];
            #pragma unroll
            for (int mt = 0; mt < 2; mt++) {
                uint32_t aaddr = sbk + (uint32_t)(((a_row + mt*16)*GROW + kof + a_co)*2);
                ldsm_x4(ah[mt][0], ah[mt][1], ah[mt][2], ah[mt][3], aaddr);
            }
            #pragma unroll
            for (int pp = 0; pp < 2; pp++) {
                uint32_t b4[2][4];
                #pragma unroll
                for (int i = 0; i < 2; i++) {
                    int p = 2*pp + i;
                    uint32_t baddr = sbk + GT_BYTES +
                                     (uint32_t)(((b_row_p + p*16)*GROW + kof + b_co)*2);
                    ldsm_x4(b4[i][0], b4[i][1], b4[i][2], b4[i][3], baddr);
                }
                #pragma unroll
                for (int i = 0; i < 2; i++) {
                    int p = 2*pp + i;
                    #pragma unroll
                    for (int mt = 0; mt < 2; mt++) {
                        mma_f16(acc[mt][2*p],   ah[mt], b4[i]);
                        mma_f16(acc[mt][2*p+1], ah[mt], b4[i]+2);
                    }
                }
            }
        }
    }

    const int row_base = bm*128 + wm*32;
    const int col_base = bn*128 + wn*64;
    #pragma unroll
    for (int mt = 0; mt < 2; mt++) {
        #pragma unroll
        for (int rg = 0; rg < 2; rg++) {
            int row = row_base + mt*16 + rg*8 + (lane >> 2);
            #pragma unroll
            for (int nt = 0; nt < 8; nt++) {
                int col = col_base + nt*8 + 2*(lane & 3);
                *(float2*)(C + (size_t)row*DMODEL + col) =
                    make_float2(acc[mt][nt][rg*2], acc[mt][nt][rg*2+1]);
            }
        }
    }
}

// ---------------- fp16 flash attention: 128-key macro tiles, 2-stage ring ----------------
#define A_STR 72
#define A_SQL 9216
#define A_SST 18432
#define A_KBUF 9216                // 128*72
#define A_STG (2*A_KBUF)           // 18432 halves per stage
#define ATTN_SMEM_BYTES ((A_SST + 2*A_STG)*2)   // 110592
#define SCALE_LOG2 0.18033688011112042f         // 0.125 * log2(e)

__global__ __launch_bounds__(256, 2)
void attn_mma(const __half* __restrict__ Qh_g, const __half* __restrict__ Ql_g,
              const __half* __restrict__ Kh_g, const __half* __restrict__ Vh_g,
              __half* __restrict__ Oh)
{
    extern __shared__ __half smh[];
    const uint32_t sb = smem_u32(smh);
    const int tid  = threadIdx.x;
    const int wq   = tid >> 5;
    const int lane = tid & 31;
    const int bh   = blockIdx.y;
    const int qt   = gridDim.x - 1 - blockIdx.x;
    const int q0   = qt * 128;
    const size_t boff = (size_t)bh*SEQ*DKH;

    // ---- Q (hi+lo) ----
    #pragma unroll
    for (int l = 0; l < 4; l++) {
        int item = tid + l*256;
        int r = item >> 3;
        int c = item & 7;
        uint32_t d = sb + (uint32_t)(r*A_STR + c*8)*2;
        const __half* src = Qh_g + boff + (size_t)(q0+r)*DKH + c*8;
        cp16(d, src);
        cp16(d + A_SQL*2, Ql_g + (src - Qh_g));
    }
    CP_COMMIT();

    const int bsel = tid >> 7;
    const int loc  = tid & 127;
    const int vc   = loc & 7;
    const int vr   = loc >> 3;
    const __half* Pk = bsel ? Vh_g : Kh_g;
    const __half* Pkv = Pk + boff + (size_t)vr*DKH + vc*8;
    const uint32_t dkv = sb + (uint32_t)((A_SST + bsel*A_KBUF + vr*A_STR + vc*8)*2);

    auto load_kv = [&](int stg, int mt) {
        const __half* s = Pkv + (size_t)(mt*128)*DKH;
        const uint32_t d = dkv + stg*(A_STG*2);
        #pragma unroll
        for (int i = 0; i < 8; i++)
            cp16(d + i*(16*A_STR*2), s + (size_t)(i*16)*DKH);
        CP_COMMIT();
    };

    const int nmt = qt + 1;
    load_kv(0, 0);

    float sc[8][4];
    float o[8][4];
    #pragma unroll
    for (int nt = 0; nt < 8; nt++)
        #pragma unroll
        for (int j = 0; j < 4; j++) o[nt][j] = 0.f;
    float m0 = -INFINITY, m1 = -INFINITY, l0 = 0.f, l1 = 0.f;

    const uint32_t ONES2 = 0x3C003C00u;
    uint32_t ones_b[2] = {ONES2, ONES2};

    for (int mt = 0; mt < nmt; mt++) {
        cp_wait<0>();
        __syncthreads();
        if (mt + 1 < nmt) load_kv((mt + 1) & 1, mt + 1);
        const uint32_t stb = sb + (uint32_t)((A_SST + (mt & 1)*A_STG)*2);

        #pragma unroll
        for (int st = 0; st < 2; st++) {
            const int k0 = mt*128 + st*64;
            if (k0 > q0 + wq*16 + 15) continue;
            const uint32_t ktb = stb + (uint32_t)(st*64*A_STR)*2;
            const uint32_t vtb = stb + (uint32_t)((A_KBUF + st*64*A_STR))*2;

            // ---- S = Q K^T (split-Q, 2 passes) ----
            #pragma unroll
            for (int nt = 0; nt < 8; nt++)
                #pragma unroll
                for (int j = 0; j < 4; j++) sc[nt][j] = 0.f;
            #pragma unroll
            for (int kt = 0; kt < 4; kt++) {
                uint32_t ah[4], al[4];
                uint32_t aaddr = sb + (uint32_t)(((wq*16 + (lane & 15))*A_STR + kt*16 + (lane >> 4)*8)*2);
                ldsm_x4(ah[0], ah[1], ah[2], ah[3], aaddr);
                ldsm_x4(al[0], al[1], al[2], al[3], aaddr + A_SQL*2);
                #pragma unroll
                for (int pp = 0; pp < 2; pp++) {
                    uint32_t kh4[2][4];
                    #pragma unroll
                    for (int i = 0; i < 2; i++) {
                        int p = 2*pp + i;
                        int brow = p*16 + (lane & 7) + ((lane >> 4) << 3);
                        uint32_t baddr = ktb + (uint32_t)((brow*A_STR + kt*16 + ((lane >> 3) & 1)*8)*2);
                        ldsm_x4(kh4[i][0], kh4[i][1], kh4[i][2], kh4[i][3], baddr);
                    }
                    #pragma unroll
                    for (int i = 0; i < 2; i++) {
                        int p = 2*pp + i;
                        mma_f16(sc[2*p],   ah, kh4[i]);
                        mma_f16(sc[2*p+1], ah, kh4[i]+2);
                    }
                    #pragma unroll
                    for (int i = 0; i < 2; i++) {
                        int p = 2*pp + i;
                        mma_f16(sc[2*p],   al, kh4[i]);
                        mma_f16(sc[2*p+1], al, kh4[i]+2);
                    }
                }
            }

            // ---- softmax: scale/mask/max, P = ex2.f16x2, sums via ones-MMA ----
            const int qrow = q0 + wq*16 + (lane >> 2);
            const bool needmask = (k0 + 63 > q0 + wq*16);
            float mx0 = -1e30f, mx1 = -1e30f;
            #pragma unroll
            for (int nt = 0; nt < 8; nt++) {
                #pragma unroll
                for (int j = 0; j < 4; j++) sc[nt][j] *= SCALE_LOG2;
                if (needmask) {
                    int kcol = k0 + nt*8 + 2*(lane & 3);
                    if (kcol+0 > qrow)   sc[nt][0] = -1e30f;
                    if (kcol+1 > qrow)   sc[nt][1] = -1e30f;
                    if (kcol+0 > qrow+8) sc[nt][2] = -1e30f;
                    if (kcol+1 > qrow+8) sc[nt][3] = -1e30f;
                }
                mx0 = fmaxf(mx0, fmaxf(sc[nt][0], sc[nt][1]));
                mx1 = fmaxf(mx1, fmaxf(sc[nt][2], sc[nt][3]));
            }
            mx0 = fmaxf(mx0, __shfl_xor_sync(0xffffffffu, mx0, 1));
            mx0 = fmaxf(mx0, __shfl_xor_sync(0xffffffffu, mx0, 2));
            mx1 = fmaxf(mx1, __shfl_xor_sync(0xffffffffu, mx1, 1));
            mx1 = fmaxf(mx1, __shfl_xor_sync(0xffffffffu, mx1, 2));
            float mn0 = fmaxf(m0, mx0), mn1 = fmaxf(m1, mx1);
            float f0 = exp2f(m0 - mn0), f1 = exp2f(m1 - mn1);
            m0 = mn0; m1 = mn1;

            uint32_t pr[8][2];
            #pragma unroll
            for (int nt = 0; nt < 8; nt++) {
                pr[nt][0] = ex2_h2(pack_h2(sc[nt][0] - mn0, sc[nt][1] - mn0));
                pr[nt][1] = ex2_h2(pack_h2(sc[nt][2] - mn1, sc[nt][3] - mn1));
            }

            float ps[4] = {0.f, 0.f, 0.f, 0.f};
            #pragma unroll
            for (int kt = 0; kt < 4; kt++) {
                uint32_t pf[4] = {pr[2*kt][0], pr[2*kt][1], pr[2*kt+1][0], pr[2*kt+1][1]};
                mma_f16(ps, pf, ones_b);
            }
            l0 = l0*f0 + ps[0];
            l1 = l1*f1 + ps[2];
            if (f0 != 1.0f || f1 != 1.0f) {
                #pragma unroll
                for (int nt = 0; nt < 8; nt++) {
                    o[nt][0] *= f0; o[nt][1] *= f0;
                    o[nt][2] *= f1; o[nt][3] *= f1;
                }
            }

            // ---- O += P V (single-pass fp16) ----
            #pragma unroll
            for (int kt = 0; kt < 4; kt++) {
                uint32_t pf[4] = {pr[2*kt][0], pr[2*kt][1], pr[2*kt+1][0], pr[2*kt+1][1]};
                #pragma unroll
                for (int pp = 0; pp < 2; pp++) {
                    uint32_t vh4[2][4];
                    #pragma unroll
                    for (int i = 0; i < 2; i++) {
                        int dp = 2*pp + i;
                        uint32_t vaddr = vtb + (uint32_t)(((kt*16 + (lane & 15))*A_STR +
                                         dp*16 + ((lane >> 4) & 1)*8)*2);
                        ldsm_x4t(vh4[i][0], vh4[i][1], vh4[i][2], vh4[i][3], vaddr);
                    }
                    #pragma unroll
                    for (int i = 0; i < 2; i++) {
                        int dp = 2*pp + i;
                        mma_f16(o[2*dp],   pf, vh4[i]);
                        mma_f16(o[2*dp+1], pf, vh4[i]+2);
                    }
                }
            }
        }
    }

    // ---- epilogue: single fp16 ----
    const int b = bh >> 4, h = bh & 15;
    const float i0 = 1.f / l0, i1 = 1.f / l1;
    const int srow = q0 + wq*16 + (lane >> 2);
    const size_t base0 = ((size_t)(b*SEQ + srow))*DMODEL + h*64;
    const size_t base1 = base0 + (size_t)8*DMODEL;
    #pragma unroll
    for (int nt = 0; nt < 8; nt++) {
        int col = nt*8 + 2*(lane & 3);
        *(uint32_t*)(Oh + base0 + col) = pack_h2(o[nt][0]*i0, o[nt][1]*i0);
        *(uint32_t*)(Oh + base1 + col) = pack_h2(o[nt][2]*i1, o[nt][3]*i1);
    }
}

// ---------------- launch ----------------
extern "C" void kernel_launch(void* const* d_in, const int* in_sizes, int n_in,
                              void* d_out, int out_size)
{
    const float* x  = (const float*)d_in[0];
    const float* wq = (const float*)d_in[1];
    const float* wk = (const float*)d_in[2];
    const float* wv = (const float*)d_in[3];
    const float* wo = (const float*)d_in[4];
    const int*  pos = (const int*)d_in[5];
    float* out = (float*)d_out;

    float *rc, *rs;
    __half *xh, *xl, *wh, *qh, *ql, *kh, *vh, *aoh;
    cudaGetSymbolAddress((void**)&rc,  g_ropec);
    cudaGetSymbolAddress((void**)&rs,  g_ropes);
    cudaGetSymbolAddress((void**)&xh,  g_xh);
    cudaGetSymbolAddress((void**)&xl,  g_xl);
    cudaGetSymbolAddress((void**)&wh,  g_wh);
    cudaGetSymbolAddress((void**)&qh,  g_qh);
    cudaGetSymbolAddress((void**)&ql,  g_ql);
    cudaGetSymbolAddress((void**)&kh,  g_kh);
    cudaGetSymbolAddress((void**)&vh,  g_vh);
    cudaGetSymbolAddress((void**)&aoh, g_aoh);

    static bool attr_done = false;
    if (!attr_done) {
        cudaFuncSetAttribute(gemm_qkv, cudaFuncAttributeMaxDynamicSharedMemorySize, QKV_SMEM);
        cudaFuncSetAttribute(gemm_out, cudaFuncAttributeMaxDynamicSharedMemorySize, OP_SMEM);
        cudaFuncSetAttribute(attn_mma, cudaFuncAttributeMaxDynamicSharedMemorySize, ATTN_SMEM_BYTES);
        attr_done = true;
    }

    {
        dim3 gc(1024, 9);   // 8 conversion segments + 1 rope segment
        convall_kernel<<<gc, 256>>>(x, wq, wk, wv, wo, xh, xl, wh, pos, rc, rs);
    }

    // fused Q/K/V projections (z=0 Q split-A + RoPE, z=1 K + RoPE, z=2 V)
    dim3 gqkv(DMODEL/128, M_TOT/128, 3);
    gemm_qkv<<<gqkv, 256, QKV_SMEM>>>(xh, xl, wh, qh, ql, kh, vh, rc, rs);

    dim3 ga(SEQ/128, BATCH*NHEADS);
    attn_mma<<<ga, 256, ATTN_SMEM_BYTES>>>(qh, ql, kh, vh, aoh);

    const size_t WN = (size_t)DMODEL*DMODEL;
    dim3 gg(DMODEL/128, M_TOT/128);
    gemm_out<<<gg, 256, OP_SMEM>>>(aoh, wh + 3*WN, out);
}

// round 17
// speedup vs baseline: 6.4502x; 1.1290x over previous
#include <cuda_runtime.h>
#include <cuda_fp16.h>
#include <math.h>
#include <cstdint>

#define BATCH   2
#define SEQ     2048
#define DMODEL  1024
#define NHEADS  16
#define DKH     64
#define M_TOT   (BATCH*SEQ)   // 4096
#define QKV_ELEMS (BATCH*NHEADS*SEQ*DKH)

// ---------------- scratch (static device globals; no allocs) ----------------
__device__ __align__(256) __half g_xh[M_TOT*DMODEL];
__device__ __align__(256) __half g_xl[M_TOT*DMODEL];
__device__ __align__(256) __half g_wh[4*DMODEL*DMODEL];   // weights single fp16
__device__ __align__(256) __half g_qh[QKV_ELEMS];         // Q single fp16 (split-A computed)
__device__ __align__(256) __half g_kh[QKV_ELEMS];         // K single fp16
__device__ __align__(256) __half g_vh[QKV_ELEMS];         // V single fp16
__device__ __align__(256) __half g_aoh[M_TOT*DMODEL];     // attention out single fp16
__device__ float g_ropec[SEQ*32];   // [s][ip]
__device__ float g_ropes[SEQ*32];

// ---------------- PTX helpers ----------------
__device__ __forceinline__ uint32_t smem_u32(const void* p) {
    uint32_t a;
    asm("{ .reg .u64 t; cvta.to.shared.u64 t, %1; cvt.u32.u64 %0, t; }" : "=r"(a) : "l"(p));
    return a;
}
__device__ __forceinline__ void cp16(uint32_t dst, const void* src) {
    asm volatile("cp.async.cg.shared.global [%0], [%1], 16;" :: "r"(dst), "l"(src) : "memory");
}
#define CP_COMMIT() asm volatile("cp.async.commit_group;" ::: "memory")
template<int N>
__device__ __forceinline__ void cp_wait() {
    asm volatile("cp.async.wait_group %0;" :: "n"(N) : "memory");
}
__device__ __forceinline__ void ldsm_x4(uint32_t& r0, uint32_t& r1, uint32_t& r2,
                                        uint32_t& r3, uint32_t addr) {
    asm volatile("ldmatrix.sync.aligned.m8n8.x4.shared.b16 {%0,%1,%2,%3}, [%4];"
                 : "=r"(r0), "=r"(r1), "=r"(r2), "=r"(r3) : "r"(addr));
}
__device__ __forceinline__ void ldsm_x4t(uint32_t& r0, uint32_t& r1, uint32_t& r2,
                                         uint32_t& r3, uint32_t addr) {
    asm volatile("ldmatrix.sync.aligned.m8n8.x4.trans.shared.b16 {%0,%1,%2,%3}, [%4];"
                 : "=r"(r0), "=r"(r1), "=r"(r2), "=r"(r3) : "r"(addr));
}
__device__ __forceinline__ void mma_f16(float* c, const uint32_t* a, const uint32_t* b) {
    asm volatile("mma.sync.aligned.m16n8k16.row.col.f32.f16.f16.f32 "
                 "{%0,%1,%2,%3}, {%4,%5,%6,%7}, {%8,%9}, {%0,%1,%2,%3};"
                 : "+f"(c[0]), "+f"(c[1]), "+f"(c[2]), "+f"(c[3])
                 : "r"(a[0]), "r"(a[1]), "r"(a[2]), "r"(a[3]), "r"(b[0]), "r"(b[1]));
}
__device__ __forceinline__ uint32_t pack_h2(float a, float b) {
    __half2 h = __floats2half2_rn(a, b);
    return *(uint32_t*)&h;
}
__device__ __forceinline__ uint32_t ex2_h2(uint32_t x) {
    uint32_t r;
    asm("ex2.approx.f16x2 %0, %1;" : "=r"(r) : "r"(x));
    return r;
}
// split pair of floats into packed fp16x2 hi + lo residual (~22-bit effective)
__device__ __forceinline__ void split2h(float a, float b, uint32_t& hi, uint32_t& lo) {
    __half2 h = __floats2half2_rn(a, b);
    float ha = __low2float(h), hb = __high2float(h);
    __half2 l = __floats2half2_rn(a - ha, b - hb);
    hi = *(uint32_t*)&h;
    lo = *(uint32_t*)&l;
}

// ---------------- fused prep (MLP=4): x split + 4 weights + rope table ----------------
__global__ void convall_kernel(const float* __restrict__ x,
                               const float* __restrict__ w0, const float* __restrict__ w1,
                               const float* __restrict__ w2, const float* __restrict__ w3,
                               __half* __restrict__ xh, __half* __restrict__ xl,
                               __half* __restrict__ wh,
                               const int* __restrict__ pos,
                               float* __restrict__ cosT, float* __restrict__ sinT)
{
    const int y = blockIdx.y;
    const int base = blockIdx.x * (blockDim.x * 4) + threadIdx.x;
    if (y < 4) {
        const float* src = x + (size_t)y * (M_TOT*DMODEL/4);
        size_t off = (size_t)y * (M_TOT*DMODEL/4);
        float4 v[4];
        #pragma unroll
        for (int j = 0; j < 4; j++)
            v[j] = *(const float4*)(src + (size_t)(base + j*256)*4);
        #pragma unroll
        for (int j = 0; j < 4; j++) {
            size_t i = (size_t)(base + j*256)*4;
            uint32_t h0, l0, h1, l1;
            split2h(v[j].x, v[j].y, h0, l0);
            split2h(v[j].z, v[j].w, h1, l1);
            *(uint32_t*)(xh + off + i)     = h0;
            *(uint32_t*)(xh + off + i + 2) = h1;
            *(uint32_t*)(xl + off + i)     = l0;
            *(uint32_t*)(xl + off + i + 2) = l1;
        }
    } else if (y < 8) {
        const float* ws[4] = {w0, w1, w2, w3};
        const float* src = ws[y-4];
        size_t off = (size_t)(y-4) * DMODEL * DMODEL;
        float4 v[4];
        #pragma unroll
        for (int j = 0; j < 4; j++)
            v[j] = *(const float4*)(src + (size_t)(base + j*256)*4);
        #pragma unroll
        for (int j = 0; j < 4; j++) {
            size_t i = (size_t)(base + j*256)*4;
            *(uint32_t*)(wh + off + i)     = pack_h2(v[j].x, v[j].y);
            *(uint32_t*)(wh + off + i + 2) = pack_h2(v[j].z, v[j].w);
        }
    } else {
        #pragma unroll
        for (int j = 0; j < 4; j++) {
            int i = base + j*256;
            if (i >= SEQ*32) break;
            int s  = i >> 5;
            int ip = i & 31;
            double invf = exp2(-(double)ip * 0.41524101186092028);  // log2(10000)/32
            float ang = (float)pos[s] * (float)invf;
            float sn, cs;
            sincosf(ang, &sn, &cs);
            cosT[i] = cs;
            sinT[i] = sn;
        }
    }
}

// ---------------- GEMM common geometry ----------------
#define NKCH (DMODEL/64)          // 16
#define GROW 72                   // halves per row (144B = 9x16B, conflict-free ldsm)
#define GT_BYTES (128*GROW*2)     // 18432

// ---------------- fused QKV GEMM: one launch, z selects projection ----------------
// z=0: split-A (xh+xl) -> Q fp16 + RoPE (accurate compute, fp16 store)
// z=1: single-A -> K fp16 + RoPE; z=2: single-A -> V fp16
#define QKV_STG (3*GT_BYTES)              // 55296
#define QKV_SMEM (2*QKV_STG)              // 110592

__global__ __launch_bounds__(256, 2)
void gemm_qkv(const __half* __restrict__ xh_g, const __half* __restrict__ xl_g,
              const __half* __restrict__ wh_g,
              __half* __restrict__ Qout, __half* __restrict__ Kout, __half* __restrict__ Vout,
              const float* __restrict__ ropec, const float* __restrict__ ropes)
{
    extern __shared__ __half smh[];
    const uint32_t sbase = smem_u32(smh);
    const int tid  = threadIdx.x;
    const int wid  = tid >> 5;
    const int lane = tid & 31;
    const int bm = blockIdx.y, bn = blockIdx.x;
    const int z  = blockIdx.z;
    const bool splita  = (z == 0);
    const bool do_rope = (z < 2);
    const int wm = wid & 3;
    const int wn = wid >> 2;

    float acc[2][8][4];
    #pragma unroll
    for (int mt = 0; mt < 2; mt++)
        #pragma unroll
        for (int nt = 0; nt < 8; nt++)
            #pragma unroll
            for (int j = 0; j < 4; j++) acc[mt][nt][j] = 0.f;

    const __half* Ah = xh_g + (size_t)(bm*128)*DMODEL;
    const __half* Al = xl_g + (size_t)(bm*128)*DMODEL;
    const __half* Bh = wh_g + (size_t)z*DMODEL*DMODEL + (size_t)(bn*128)*DMODEL;

    const int lc = tid & 7;
    const int rb = tid >> 3;              // 0..31
    const __half* SA  = Ah + (size_t)rb*DMODEL + lc*8;
    const __half* SAl = Al + (size_t)rb*DMODEL + lc*8;
    const __half* SB  = Bh + (size_t)rb*DMODEL + lc*8;
    const uint32_t dsl = sbase + (uint32_t)(rb*GROW + lc*8)*2;
    const uint32_t rowhop = (uint32_t)(32*GROW)*2;
    const size_t   srchop = (size_t)32*DMODEL;

    auto load_stage = [&](int stg, int kc) {
        const uint32_t d = dsl + stg*QKV_STG;
        const int ko = kc*64;
        #pragma unroll
        for (int i = 0; i < 4; i++) {
            cp16(d + i*rowhop, SA + i*srchop + ko);
            if (splita) cp16(d + GT_BYTES + i*rowhop, SAl + i*srchop + ko);
            cp16(d + 2*GT_BYTES + i*rowhop, SB + i*srchop + ko);
        }
        CP_COMMIT();
    };

    load_stage(0, 0);

    const int a_row   = wm*32 + (lane & 15);
    const int a_co    = (lane >> 4) * 8;
    const int b_row_p = wn*64 + (lane & 7) + ((lane >> 4) << 3);
    const int b_co    = ((lane >> 3) & 1) * 8;

    for (int kc = 0; kc < NKCH; kc++) {
        cp_wait<0>();
        __syncthreads();
        if (kc + 1 < NKCH) load_stage((kc + 1) & 1, kc + 1);
        const uint32_t sbk = sbase + (kc & 1)*QKV_STG;

        #pragma unroll
        for (int ks = 0; ks < 4; ks++) {
            const int kof = ks*16;
            uint32_t ah[2][4], al[2][4];
            #pragma unroll
            for (int mt = 0; mt < 2; mt++) {
                uint32_t aaddr = sbk + (uint32_t)(((a_row + mt*16)*GROW + kof + a_co)*2);
                ldsm_x4(ah[mt][0], ah[mt][1], ah[mt][2], ah[mt][3], aaddr);
                if (splita)
                    ldsm_x4(al[mt][0], al[mt][1], al[mt][2], al[mt][3], aaddr + GT_BYTES);
            }
            #pragma unroll
            for (int pp = 0; pp < 2; pp++) {
                uint32_t b4[2][4];
                #pragma unroll
                for (int i = 0; i < 2; i++) {
                    int p = 2*pp + i;
                    uint32_t baddr = sbk + 2*GT_BYTES +
                                     (uint32_t)(((b_row_p + p*16)*GROW + kof + b_co)*2);
                    ldsm_x4(b4[i][0], b4[i][1], b4[i][2], b4[i][3], baddr);
                }
                #pragma unroll
                for (int i = 0; i < 2; i++) {
                    int p = 2*pp + i;
                    #pragma unroll
                    for (int mt = 0; mt < 2; mt++) {
                        mma_f16(acc[mt][2*p],   ah[mt], b4[i]);
                        mma_f16(acc[mt][2*p+1], ah[mt], b4[i]+2);
                    }
                }
                if (splita) {
                    #pragma unroll
                    for (int i = 0; i < 2; i++) {
                        int p = 2*pp + i;
                        #pragma unroll
                        for (int mt = 0; mt < 2; mt++) {
                            mma_f16(acc[mt][2*p],   al[mt], b4[i]);
                            mma_f16(acc[mt][2*p+1], al[mt], b4[i]+2);
                        }
                    }
                }
            }
        }
    }

    // ---- epilogue ----
    const int row_base = bm*128 + wm*32;
    const int col_base = bn*128 + wn*64;
    __half* Outp = (z == 0) ? Qout : (z == 1) ? Kout : Vout;
    #pragma unroll
    for (int mt = 0; mt < 2; mt++) {
        #pragma unroll
        for (int rg = 0; rg < 2; rg++) {
            int row = row_base + mt*16 + rg*8 + (lane >> 2);
            int s = row & (SEQ-1);
            int b = row >> 11;
            #pragma unroll
            for (int nt = 0; nt < 8; nt++) {
                int col = col_base + nt*8 + 2*(lane & 3);
                float e = acc[mt][nt][rg*2];
                float o = acc[mt][nt][rg*2+1];
                if (do_rope) {
                    int ip = (col & 63) >> 1;
                    float cs = ropec[s*32 + ip];
                    float sn = ropes[s*32 + ip];
                    float ne = e*cs - o*sn;
                    float no = e*sn + o*cs;
                    e = ne; o = no;
                }
                int h = col >> 6, dk = col & 63;
                size_t idx = ((size_t)(b*NHEADS + h)*SEQ + s)*DKH + dk;
                *(uint32_t*)(Outp + idx) = pack_h2(e, o);
            }
        }
    }
}

// ---------------- output projection GEMM: single-pass A, fp32 C ----------------
#define OP_STG (2*GT_BYTES)               // 36864
#define OP_SMEM (2*OP_STG)                // 73728

__global__ __launch_bounds__(256, 2)
void gemm_out(const __half* __restrict__ A_g, const __half* __restrict__ B_g,
              float* __restrict__ C)
{
    extern __shared__ __half smh[];
    const uint32_t sbase = smem_u32(smh);
    const int tid  = threadIdx.x;
    const int wid  = tid >> 5;
    const int lane = tid & 31;
    const int bm = blockIdx.y, bn = blockIdx.x;
    const int wm = wid & 3;
    const int wn = wid >> 2;

    float acc[2][8][4];
    #pragma unroll
    for (int mt = 0; mt < 2; mt++)
        #pragma unroll
        for (int nt = 0; nt < 8; nt++)
            #pragma unroll
            for (int j = 0; j < 4; j++) acc[mt][nt][j] = 0.f;

    const __half* Ah = A_g + (size_t)(bm*128)*DMODEL;
    const __half* Bh = B_g + (size_t)(bn*128)*DMODEL;

    const int lc = tid & 7;
    const int rb = tid >> 3;
    const __half* SA = Ah + (size_t)rb*DMODEL + lc*8;
    const __half* SB = Bh + (size_t)rb*DMODEL + lc*8;
    const uint32_t dsl = sbase + (uint32_t)(rb*GROW + lc*8)*2;
    const uint32_t rowhop = (uint32_t)(32*GROW)*2;
    const size_t   srchop = (size_t)32*DMODEL;

    auto load_stage = [&](int stg, int kc) {
        const uint32_t d = dsl + stg*OP_STG;
        const int ko = kc*64;
        #pragma unroll
        for (int i = 0; i < 4; i++) {
            cp16(d + i*rowhop, SA + i*srchop + ko);
            cp16(d + GT_BYTES + i*rowhop, SB + i*srchop + ko);
        }
        CP_COMMIT();
    };

    load_stage(0, 0);

    const int a_row   = wm*32 + (lane & 15);
    const int a_co    = (lane >> 4) * 8;
    const int b_row_p = wn*64 + (lane & 7) + ((lane >> 4) << 3);
    const int b_co    = ((lane >> 3) & 1) * 8;

    for (int kc = 0; kc < NKCH; kc++) {
        cp_wait<0>();
        __syncthreads();
        if (kc + 1 < NKCH) load_stage((kc + 1) & 1, kc + 1);
        const uint32_t sbk = sbase + (kc & 1)*OP_STG;

        #pragma unroll
        for (int ks = 0; ks < 4; ks++) {
            const int kof = ks*16;
            uint32_t ah[2][4];
            #pragma unroll
            for (int mt = 0; mt < 2; mt++) {
                uint32_t aaddr = sbk + (uint32_t)(((a_row + mt*16)*GROW + kof + a_co)*2);
                ldsm_x4(ah[mt][0], ah[mt][1], ah[mt][2], ah[mt][3], aaddr);
            }
            #pragma unroll
            for (int pp = 0; pp < 2; pp++) {
                uint32_t b4[2][4];
                #pragma unroll
                for (int i = 0; i < 2; i++) {
                    int p = 2*pp + i;
                    uint32_t baddr = sbk + GT_BYTES +
                                     (uint32_t)(((b_row_p + p*16)*GROW + kof + b_co)*2);
                    ldsm_x4(b4[i][0], b4[i][1], b4[i][2], b4[i][3], baddr);
                }
                #pragma unroll
                for (int i = 0; i < 2; i++) {
                    int p = 2*pp + i;
                    #pragma unroll
                    for (int mt = 0; mt < 2; mt++) {
                        mma_f16(acc[mt][2*p],   ah[mt], b4[i]);
                        mma_f16(acc[mt][2*p+1], ah[mt], b4[i]+2);
                    }
                }
            }
        }
    }

    const int row_base = bm*128 + wm*32;
    const int col_base = bn*128 + wn*64;
    #pragma unroll
    for (int mt = 0; mt < 2; mt++) {
        #pragma unroll
        for (int rg = 0; rg < 2; rg++) {
            int row = row_base + mt*16 + rg*8 + (lane >> 2);
            #pragma unroll
            for (int nt = 0; nt < 8; nt++) {
                int col = col_base + nt*8 + 2*(lane & 3);
                *(float2*)(C + (size_t)row*DMODEL + col) =
                    make_float2(acc[mt][nt][rg*2], acc[mt][nt][rg*2+1]);
            }
        }
    }
}

// ---------------- fp16 flash attention: single-pass QK, 128-key macro tiles ----------------
// smem (half units): Q[128][72] @0; 2 KV stages @9216: {K[128][72], V[128][72]}
#define A_STR 72
#define A_SQ  9216
#define A_KBUF 9216                // 128*72
#define A_STG (2*A_KBUF)           // 18432 halves per stage
#define ATTN_SMEM_BYTES ((A_SQ + 2*A_STG)*2)    // 92160
#define SCALE_LOG2 0.18033688011112042f         // 0.125 * log2(e)

__global__ __launch_bounds__(256, 2)
void attn_mma(const __half* __restrict__ Qh_g,
              const __half* __restrict__ Kh_g, const __half* __restrict__ Vh_g,
              __half* __restrict__ Oh)
{
    extern __shared__ __half smh[];
    const uint32_t sb = smem_u32(smh);
    const int tid  = threadIdx.x;
    const int wq   = tid >> 5;
    const int lane = tid & 31;
    const int bh   = blockIdx.y;
    const int qt   = gridDim.x - 1 - blockIdx.x;
    const int q0   = qt * 128;
    const size_t boff = (size_t)bh*SEQ*DKH;

    // ---- Q (single fp16) ----
    #pragma unroll
    for (int l = 0; l < 4; l++) {
        int item = tid + l*256;
        int r = item >> 3;
        int c = item & 7;
        uint32_t d = sb + (uint32_t)(r*A_STR + c*8)*2;
        cp16(d, Qh_g + boff + (size_t)(q0+r)*DKH + c*8);
    }
    CP_COMMIT();

    const int bsel = tid >> 7;
    const int loc  = tid & 127;
    const int vc   = loc & 7;
    const int vr   = loc >> 3;
    const __half* Pk = bsel ? Vh_g : Kh_g;
    const __half* Pkv = Pk + boff + (size_t)vr*DKH + vc*8;
    const uint32_t dkv = sb + (uint32_t)((A_SQ + bsel*A_KBUF + vr*A_STR + vc*8)*2);

    auto load_kv = [&](int stg, int mt) {
        const __half* s = Pkv + (size_t)(mt*128)*DKH;
        const uint32_t d = dkv + stg*(A_STG*2);
        #pragma unroll
        for (int i = 0; i < 8; i++)
            cp16(d + i*(16*A_STR*2), s + (size_t)(i*16)*DKH);
        CP_COMMIT();
    };

    const int nmt = qt + 1;
    load_kv(0, 0);

    float sc[8][4];
    float o[8][4];
    #pragma unroll
    for (int nt = 0; nt < 8; nt++)
        #pragma unroll
        for (int j = 0; j < 4; j++) o[nt][j] = 0.f;
    float m0 = -INFINITY, m1 = -INFINITY, l0 = 0.f, l1 = 0.f;

    const uint32_t ONES2 = 0x3C003C00u;
    uint32_t ones_b[2] = {ONES2, ONES2};

    for (int mt = 0; mt < nmt; mt++) {
        cp_wait<0>();
        __syncthreads();
        if (mt + 1 < nmt) load_kv((mt + 1) & 1, mt + 1);
        const uint32_t stb = sb + (uint32_t)((A_SQ + (mt & 1)*A_STG)*2);

        #pragma unroll
        for (int st = 0; st < 2; st++) {
            const int k0 = mt*128 + st*64;
            if (k0 > q0 + wq*16 + 15) continue;
            const uint32_t ktb = stb + (uint32_t)(st*64*A_STR)*2;
            const uint32_t vtb = stb + (uint32_t)((A_KBUF + st*64*A_STR))*2;

            // ---- S = Q K^T (single-pass fp16) ----
            #pragma unroll
            for (int nt = 0; nt < 8; nt++)
                #pragma unroll
                for (int j = 0; j < 4; j++) sc[nt][j] = 0.f;
            #pragma unroll
            for (int kt = 0; kt < 4; kt++) {
                uint32_t ah[4];
                uint32_t aaddr = sb + (uint32_t)(((wq*16 + (lane & 15))*A_STR + kt*16 + (lane >> 4)*8)*2);
                ldsm_x4(ah[0], ah[1], ah[2], ah[3], aaddr);
                #pragma unroll
                for (int pp = 0; pp < 2; pp++) {
                    uint32_t kh4[2][4];
                    #pragma unroll
                    for (int i = 0; i < 2; i++) {
                        int p = 2*pp + i;
                        int brow = p*16 + (lane & 7) + ((lane >> 4) << 3);
                        uint32_t baddr = ktb + (uint32_t)((brow*A_STR + kt*16 + ((lane >> 3) & 1)*8)*2);
                        ldsm_x4(kh4[i][0], kh4[i][1], kh4[i][2], kh4[i][3], baddr);
                    }
                    #pragma unroll
                    for (int i = 0; i < 2; i++) {
                        int p = 2*pp + i;
                        mma_f16(sc[2*p],   ah, kh4[i]);
                        mma_f16(sc[2*p+1], ah, kh4[i]+2);
                    }
                }
            }

            // ---- softmax: scale/mask/max, P = ex2.f16x2, sums via ones-MMA ----
            const int qrow = q0 + wq*16 + (lane >> 2);
            const bool needmask = (k0 + 63 > q0 + wq*16);
            float mx0 = -1e30f, mx1 = -1e30f;
            #pragma unroll
            for (int nt = 0; nt < 8; nt++) {
                #pragma unroll
                for (int j = 0; j < 4; j++) sc[nt][j] *= SCALE_LOG2;
                if (needmask) {
                    int kcol = k0 + nt*8 + 2*(lane & 3);
                    if (kcol+0 > qrow)   sc[nt][0] = -1e30f;
                    if (kcol+1 > qrow)   sc[nt][1] = -1e30f;
                    if (kcol+0 > qrow+8) sc[nt][2] = -1e30f;
                    if (kcol+1 > qrow+8) sc[nt][3] = -1e30f;
                }
                mx0 = fmaxf(mx0, fmaxf(sc[nt][0], sc[nt][1]));
                mx1 = fmaxf(mx1, fmaxf(sc[nt][2], sc[nt][3]));
            }
            mx0 = fmaxf(mx0, __shfl_xor_sync(0xffffffffu, mx0, 1));
            mx0 = fmaxf(mx0, __shfl_xor_sync(0xffffffffu, mx0, 2));
            mx1 = fmaxf(mx1, __shfl_xor_sync(0xffffffffu, mx1, 1));
            mx1 = fmaxf(mx1, __shfl_xor_sync(0xffffffffu, mx1, 2));
            float mn0 = fmaxf(m0, mx0), mn1 = fmaxf(m1, mx1);
            float f0 = exp2f(m0 - mn0), f1 = exp2f(m1 - mn1);
            m0 = mn0; m1 = mn1;

            uint32_t pr[8][2];
            #pragma unroll
            for (int nt = 0; nt < 8; nt++) {
                pr[nt][0] = ex2_h2(pack_h2(sc[nt][0] - mn0, sc[nt][1] - mn0));
                pr[nt][1] = ex2_h2(pack_h2(sc[nt][2] - mn1, sc[nt][3] - mn1));
            }

            float ps[4] = {0.f, 0.f, 0.f, 0.f};
            #pragma unroll
            for (int kt = 0; kt < 4; kt++) {
                uint32_t pf[4] = {pr[2*kt][0], pr[2*kt][1], pr[2*kt+1][0], pr[2*kt+1][1]};
                mma_f16(ps, pf, ones_b);
            }
            l0 = l0*f0 + ps[0];
            l1 = l1*f1 + ps[2];
            if (f0 != 1.0f || f1 != 1.0f) {
                #pragma unroll
                for (int nt = 0; nt < 8; nt++) {
                    o[nt][0] *= f0; o[nt][1] *= f0;
                    o[nt][2] *= f1; o[nt][3] *= f1;
                }
            }

            // ---- O += P V (single-pass fp16) ----
            #pragma unroll
            for (int kt = 0; kt < 4; kt++) {
                uint32_t pf[4] = {pr[2*kt][0], pr[2*kt][1], pr[2*kt+1][0], pr[2*kt+1][1]};
                #pragma unroll
                for (int pp = 0; pp < 2; pp++) {
                    uint32_t vh4[2][4];
                    #pragma unroll
                    for (int i = 0; i < 2; i++) {
                        int dp = 2*pp + i;
                        uint32_t vaddr = vtb + (uint32_t)(((kt*16 + (lane & 15))*A_STR +
                                         dp*16 + ((lane >> 4) & 1)*8)*2);
                        ldsm_x4t(vh4[i][0], vh4[i][1], vh4[i][2], vh4[i][3], vaddr);
                    }
                    #pragma unroll
                    for (int i = 0; i < 2; i++) {
                        int dp = 2*pp + i;
                        mma_f16(o[2*dp],   pf, vh4[i]);
                        mma_f16(o[2*dp+1], pf, vh4[i]+2);
                    }
                }
            }
        }
    }

    // ---- epilogue: single fp16 ----
    const int b = bh >> 4, h = bh & 15;
    const float i0 = 1.f / l0, i1 = 1.f / l1;
    const int srow = q0 + wq*16 + (lane >> 2);
    const size_t base0 = ((size_t)(b*SEQ + srow))*DMODEL + h*64;
    const size_t base1 = base0 + (size_t)8*DMODEL;
    #pragma unroll
    for (int nt = 0; nt < 8; nt++) {
        int col = nt*8 + 2*(lane & 3);
        *(uint32_t*)(Oh + base0 + col) = pack_h2(o[nt][0]*i0, o[nt][1]*i0);
        *(uint32_t*)(Oh + base1 + col) = pack_h2(o[nt][2]*i1, o[nt][3]*i1);
    }
}

// ---------------- launch ----------------
extern "C" void kernel_launch(void* const* d_in, const int* in_sizes, int n_in,
                              void* d_out, int out_size)
{
    const float* x  = (const float*)d_in[0];
    const float* wq = (const float*)d_in[1];
    const float* wk = (const float*)d_in[2];
    const float* wv = (const float*)d_in[3];
    const float* wo = (const float*)d_in[4];
    const int*  pos = (const int*)d_in[5];
    float* out = (float*)d_out;

    float *rc, *rs;
    __half *xh, *xl, *wh, *qh, *kh, *vh, *aoh;
    cudaGetSymbolAddress((void**)&rc,  g_ropec);
    cudaGetSymbolAddress((void**)&rs,  g_ropes);
    cudaGetSymbolAddress((void**)&xh,  g_xh);
    cudaGetSymbolAddress((void**)&xl,  g_xl);
    cudaGetSymbolAddress((void**)&wh,  g_wh);
    cudaGetSymbolAddress((void**)&qh,  g_qh);
    cudaGetSymbolAddress((void**)&kh,  g_kh);
    cudaGetSymbolAddress((void**)&vh,  g_vh);
    cudaGetSymbolAddress((void**)&aoh, g_aoh);

    static bool attr_done = false;
    if (!attr_done) {
        cudaFuncSetAttribute(gemm_qkv, cudaFuncAttributeMaxDynamicSharedMemorySize, QKV_SMEM);
        cudaFuncSetAttribute(gemm_out, cudaFuncAttributeMaxDynamicSharedMemorySize, OP_SMEM);
        cudaFuncSetAttribute(attn_mma, cudaFuncAttributeMaxDynamicSharedMemorySize, ATTN_SMEM_BYTES);
        attr_done = true;
    }

    {
        dim3 gc(256, 9);   // MLP=4 per thread
        convall_kernel<<<gc, 256>>>(x, wq, wk, wv, wo, xh, xl, wh, pos, rc, rs);
    }

    // fused Q/K/V projections (z=0 Q split-A compute + RoPE, z=1 K + RoPE, z=2 V)
    dim3 gqkv(DMODEL/128, M_TOT/128, 3);
    gemm_qkv<<<gqkv, 256, QKV_SMEM>>>(xh, xl, wh, qh, kh, vh, rc, rs);

    dim3 ga(SEQ/128, BATCH*NHEADS);
    attn_mma<<<ga, 256, ATTN_SMEM_BYTES>>>(qh, kh, vh, aoh);

    const size_t WN = (size_t)DMODEL*DMODEL;
    dim3 gg(DMODEL/128, M_TOT/128);
    gemm_out<<<gg, 256, OP_SMEM>>>(aoh, wh + 3*WN, out);
}